// round 2
// baseline (speedup 1.0000x reference)
#include <cuda_runtime.h>
#include <math.h>

#define CC 48
#define NN 48
#define WW 24
#define RR 36
#define DD 1024
#define SS 256

// ---------------- scratch (device globals; no allocation allowed) ----------
__device__ __align__(16) float g_sim_mid[CC*NN*WW*SS];   // 56.6 MB
__device__ __align__(16) float g_smooth[CC*NN*WW];
__device__ __align__(16) float g_qm[(size_t)CC*NN*WW*DD]; // 226 MB
__device__ __align__(16) float g_higA[CC*NN*SS];
__device__ __align__(16) float g_higB[CC*NN*SS];

__device__ __forceinline__ float warp_sum(float v) {
#pragma unroll
    for (int o = 16; o; o >>= 1) v += __shfl_xor_sync(0xffffffffu, v, o);
    return v;
}

// ---------------------------------------------------------------------------
// alv pass: per (c,n) block computes attn -> softmax -> wctx -> sim ->
// sim_mid = l2norm(sim @ alv_w + alv_b)
// PASS 0: matrix = 1 (query = cap_emb), smooth = 9
// PASS 1: query = g_qm (cap*matrix), smooth = g_smooth
// ---------------------------------------------------------------------------
template<int PASS>
__global__ void alv_kernel(const float* __restrict__ img, const float* __restrict__ cap,
                           const int* __restrict__ lens,
                           const float* __restrict__ alvw, const float* __restrict__ alvb)
{
    extern __shared__ float sm[];
    float* sImg = sm;                    // RR*DD       (36864)
    float* sSim = sImg + RR*DD;          // WW*256      (6144)
    float* sA   = sSim + WW*256;         // RR*WW raw attn
    float* sAT  = sA + RR*WW;            // WW*RR normalized/softmaxed attn
    float* sRed = sAT + WW*RR;           // WW*8 reduction buf
    float* sFac = sRed + WW*8;           // WW factors

    const int b = blockIdx.x;
    const int c = b / NN, n = b % NN;
    const int tid = threadIdx.x, lane = tid & 31, wid = tid >> 5;
    const int len = lens[c];

    // stage image block (36x1024 f32) into SMEM
    {
        const float4* gi = (const float4*)(img + (size_t)n * RR * DD);
        float4* si = (float4*)sImg;
        for (int i = tid; i < RR*DD/4; i += 256) si[i] = gi[i];
    }
    __syncthreads();

    // ---- phase 1: raw attn[r][w] = <query_w, img_r> ----
    for (int wi = 0; wi < 3; wi++) {
        int w = wid + wi * 8;
        const float* capp = (PASS == 0) ? (cap + ((size_t)c*WW + w)*DD)
                                        : (g_qm + ((size_t)b*WW + w)*DD);
        float cr[32];
#pragma unroll
        for (int k = 0; k < 32; k++) cr[k] = capp[k*32 + lane];
        for (int r = 0; r < RR; r++) {
            const float* ip = sImg + r*DD + lane;
            float a = 0.f;
#pragma unroll
            for (int k = 0; k < 32; k++) a = fmaf(cr[k], ip[k*32], a);
            a = warp_sum(a);
            if (lane == 0) sA[r*WW + w] = a;
        }
    }
    __syncthreads();

    // ---- phase 2a: leaky relu, word mask, l2norm over words (per region) ----
    if (tid < RR) {
        int r = tid;
        float vals[WW];
        float ss = 0.f;
#pragma unroll
        for (int w = 0; w < WW; w++) {
            float v = sA[r*WW + w];
            v = (v >= 0.f) ? v : 0.1f * v;
            if (w >= len) v = 0.f;
            vals[w] = v;
            ss += v * v;
        }
        float f = 1.f / (sqrtf(ss) + 1e-8f);
#pragma unroll
        for (int w = 0; w < WW; w++) sAT[w*RR + r] = vals[w] * f;
    }
    __syncthreads();

    // ---- phase 2b: softmax over regions (per word), scaled by smooth ----
    if (tid < WW) {
        int w = tid;
        float smo = (PASS == 0) ? 9.f : g_smooth[(size_t)b*WW + w];
        float m = -1e30f;
        for (int r = 0; r < RR; r++) { float v = sAT[w*RR + r]*smo; if (v > m) m = v; }
        float s = 0.f;
        for (int r = 0; r < RR; r++) {
            float e = expf(sAT[w*RR + r]*smo - m);
            sAT[w*RR + r] = e; s += e;
        }
        float inv = 1.f / s;
        for (int r = 0; r < RR; r++) sAT[w*RR + r] *= inv;
    }
    __syncthreads();

    // ---- phase 3a: wctx sum-of-squares per word (for l2norm over D) ----
    {
        float psq[WW];
#pragma unroll
        for (int w = 0; w < WW; w++) psq[w] = 0.f;
        for (int cidx = 0; cidx < 4; cidx++) {
            int d = cidx*256 + tid;
            float acc[WW];
#pragma unroll
            for (int w = 0; w < WW; w++) acc[w] = 0.f;
            for (int r = 0; r < RR; r++) {
                float iv = sImg[r*DD + d];
#pragma unroll
                for (int w = 0; w < WW; w++) acc[w] = fmaf(sAT[w*RR + r], iv, acc[w]);
            }
#pragma unroll
            for (int w = 0; w < WW; w++) psq[w] = fmaf(acc[w], acc[w], psq[w]);
        }
#pragma unroll
        for (int w = 0; w < WW; w++) {
            float v = warp_sum(psq[w]);
            if (lane == 0) sRed[w*8 + wid] = v;
        }
    }
    __syncthreads();
    if (tid < WW) {
        float s = 0.f;
#pragma unroll
        for (int k = 0; k < 8; k++) s += sRed[tid*8 + k];
        sFac[tid] = 1.f / (sqrtf(s) + 1e-8f);
    }
    __syncthreads();

    // ---- phase 3b+5: recompute wctx chunk, sim = (cap - wctx_n)^2,
    //      fused GEMM accS[w] (s = tid) += sim @ alv_w ----
    float accS[WW];
#pragma unroll
    for (int w = 0; w < WW; w++) accS[w] = alvb[tid];
    for (int cidx = 0; cidx < 4; cidx++) {
        int d = cidx*256 + tid;
        {
            float acc[WW];
#pragma unroll
            for (int w = 0; w < WW; w++) acc[w] = 0.f;
            for (int r = 0; r < RR; r++) {
                float iv = sImg[r*DD + d];
#pragma unroll
                for (int w = 0; w < WW; w++) acc[w] = fmaf(sAT[w*RR + r], iv, acc[w]);
            }
#pragma unroll
            for (int w = 0; w < WW; w++) {
                float wc = acc[w] * sFac[w];
                float cv = cap[((size_t)c*WW + w)*DD + d];
                float df = cv - wc;
                sSim[w*256 + tid] = df * df;
            }
        }
        __syncthreads();
        const float* wp = alvw + (size_t)(cidx*256) * SS + tid;
#pragma unroll 4
        for (int j = 0; j < 256; j++) {
            float wv = wp[(size_t)j * SS];
#pragma unroll
            for (int w = 0; w < WW; w++) accS[w] = fmaf(sSim[w*256 + j], wv, accS[w]);
        }
        __syncthreads();
    }

    // ---- final: l2norm over S and store ----
    {
#pragma unroll
        for (int w = 0; w < WW; w++) {
            float v = warp_sum(accS[w] * accS[w]);
            if (lane == 0) sRed[w*8 + wid] = v;
        }
        __syncthreads();
        if (tid < WW) {
            float s = 0.f;
#pragma unroll
            for (int k = 0; k < 8; k++) s += sRed[tid*8 + k];
            sFac[tid] = 1.f / (sqrtf(s) + 1e-8f);
        }
        __syncthreads();
#pragma unroll
        for (int w = 0; w < WW; w++)
            g_sim_mid[((size_t)b*WW + w)*SS + tid] = accS[w] * sFac[w];
    }
}

// ---------------------------------------------------------------------------
// masked mean over words -> g_higA
// ---------------------------------------------------------------------------
__global__ void mean_kernel(const int* __restrict__ lens)
{
    int b = blockIdx.x;
    int c = b / NN;
    int t = threadIdx.x;
    int len = lens[c];
    float inv = 1.f / (float)len;
    const float* p = g_sim_mid + (size_t)b*WW*SS + t;
    float s = 0.f;
    for (int w = 0; w < len; w++) s += p[(size_t)w * SS];
    g_higA[(size_t)b*SS + t] = s * inv;
}

// ---------------------------------------------------------------------------
// RCR: per (c,n) block (512 threads).
//  mx = tanh(tanh(x @ W1) @ W2 + b2); qm = cap * clip(mx+1,-1,1)
//  smooth = relu(tanh(x @ sW1) @ sW2 + sb2 + 9)
// ---------------------------------------------------------------------------
__global__ void rcr_kernel(const float* __restrict__ cap,
                           const float* __restrict__ mxw1, const float* __restrict__ mxb1,
                           const float* __restrict__ mxw2, const float* __restrict__ mxb2,
                           const float* __restrict__ smw1, const float* __restrict__ smb1,
                           const float* __restrict__ smw2, const float* __restrict__ smb2)
{
    extern __shared__ float sm[];
    float* sX   = sm;              // WW*SS  (6144)
    float* sH   = sX + WW*SS;      // WW*512 (12288)
    float* sRed = sH + WW*512;     // WW*4

    const int b = blockIdx.x;
    const int c = b / NN;
    const int tid = threadIdx.x, lane = tid & 31, wid = tid >> 5;

    {
        const float4* gx = (const float4*)(g_sim_mid + (size_t)b*WW*SS);
        float4* sx4 = (float4*)sX;
        for (int i = tid; i < WW*SS/4; i += 512) sx4[i] = gx[i];
    }
    __syncthreads();

    // h1 = tanh(x @ W1 + b1): thread owns hidden col = tid (512 cols)
    {
        float acc[WW];
#pragma unroll
        for (int w = 0; w < WW; w++) acc[w] = mxb1[tid];
        const float* wp = mxw1 + tid;
        for (int d = 0; d < SS; d++) {
            float wv = wp[(size_t)d * 512];
#pragma unroll
            for (int w = 0; w < WW; w++) acc[w] = fmaf(sX[w*SS + d], wv, acc[w]);
        }
#pragma unroll
        for (int w = 0; w < WW; w++) sH[w*512 + tid] = tanhf(acc[w]);
    }

    // smooth branch (threads 0..127 own the 128 hidden cols)
    if (tid < 128) {
        float acc[WW];
#pragma unroll
        for (int w = 0; w < WW; w++) acc[w] = smb1[tid];
        const float* wp = smw1 + tid;
        for (int d = 0; d < SS; d++) {
            float wv = wp[(size_t)d * 128];
#pragma unroll
            for (int w = 0; w < WW; w++) acc[w] = fmaf(sX[w*SS + d], wv, acc[w]);
        }
        float v2 = smw2[tid];
#pragma unroll
        for (int w = 0; w < WW; w++) {
            float h = tanhf(acc[w]);
            float pv = warp_sum(h * v2);
            if (lane == 0) sRed[w*4 + wid] = pv;
        }
    }
    __syncthreads();
    if (tid < WW) {
        float s = sRed[tid*4] + sRed[tid*4+1] + sRed[tid*4+2] + sRed[tid*4+3];
        s += smb2[0] + 9.0f;
        g_smooth[(size_t)b*WW + tid] = s > 0.f ? s : 0.f;
    }

    // mx / qm: 1024 output cols, two halves of 512
    for (int half = 0; half < 2; half++) {
        int d = tid + half * 512;
        float acc[WW];
#pragma unroll
        for (int w = 0; w < WW; w++) acc[w] = mxb2[d];
        const float* wp = mxw2 + d;
        for (int h = 0; h < 512; h++) {
            float wv = wp[(size_t)h * DD];
#pragma unroll
            for (int w = 0; w < WW; w++) acc[w] = fmaf(sH[w*512 + h], wv, acc[w]);
        }
#pragma unroll
        for (int w = 0; w < WW; w++) {
            float mx = tanhf(acc[w]);
            float mat = mx + 1.f;
            mat = fminf(fmaxf(mat, -1.f), 1.f);
            g_qm[((size_t)b*WW + w)*DD + d] = cap[((size_t)c*WW + w)*DD + d] * mat;
        }
    }
}

// ---------------------------------------------------------------------------
// RAR attention pooling: mid = sim_mid[c,n] (W,S), hig (S) -> hout (S)
// dir 0: higA -> higB ; dir 1: higB -> higA
// ---------------------------------------------------------------------------
__global__ void rar_kernel(const int* __restrict__ lens,
                           const float* __restrict__ qw, const float* __restrict__ qb,
                           const float* __restrict__ kw, const float* __restrict__ kb,
                           const float* __restrict__ vw, const float* __restrict__ vb,
                           int dir)
{
    extern __shared__ float sm[];
    float* sMid = sm;             // WW*SS (6144)
    float* sHig = sMid + WW*SS;   // SS
    float* sHq  = sHig + SS;      // SS
    float* sRed = sHq + SS;       // WW*8
    float* sLog = sRed + WW*8;    // WW
    float* sWgt = sLog + WW;      // WW
    float* sMisc= sWgt + WW;      // misc

    const int b = blockIdx.x;
    const int c = b / NN;
    const int tid = threadIdx.x, lane = tid & 31, wid = tid >> 5;
    const int len = lens[c];

    const float* hin = (dir == 0) ? g_higA : g_higB;
    float*       hout= (dir == 0) ? g_higB : g_higA;

    const float* gm = g_sim_mid + (size_t)b*WW*SS;
    for (int i = tid; i < WW*SS; i += 256) sMid[i] = gm[i];
    sHig[tid] = hin[(size_t)b*SS + tid];
    __syncthreads();

    // hig_q = tanh(hig @ q_w + q_b)
    {
        float acc = qb[tid];
        const float* wp = qw + tid;
        for (int s = 0; s < SS; s++) acc = fmaf(sHig[s], wp[(size_t)s*SS], acc);
        sHq[tid] = tanhf(acc);
    }
    __syncthreads();

    // mid_k = tanh(mid @ k_w + k_b); logits[w] = sum_s mid_k*hq*vw + vb
    {
        float acck[WW];
#pragma unroll
        for (int w = 0; w < WW; w++) acck[w] = kb[tid];
        const float* wp = kw + tid;
        for (int s = 0; s < SS; s++) {
            float wv = wp[(size_t)s*SS];
#pragma unroll
            for (int w = 0; w < WW; w++) acck[w] = fmaf(sMid[w*SS + s], wv, acck[w]);
        }
        float hv = sHq[tid] * vw[tid];
#pragma unroll
        for (int w = 0; w < WW; w++) {
            float pv = warp_sum(tanhf(acck[w]) * hv);
            if (lane == 0) sRed[w*8 + wid] = pv;
        }
    }
    __syncthreads();
    if (tid < WW) {
        float s = 0.f;
#pragma unroll
        for (int k = 0; k < 8; k++) s += sRed[tid*8 + k];
        s += vb[0];
        if (tid >= len) s = -1e30f;
        sLog[tid] = s;
    }
    __syncthreads();
    if (tid == 0) {
        float m = -1e30f;
        for (int w = 0; w < WW; w++) m = fmaxf(m, sLog[w]);
        float s = 0.f;
        for (int w = 0; w < WW; w++) { float e = expf(sLog[w] - m); sWgt[w] = e; s += e; }
        float inv = 1.f / s;
        for (int w = 0; w < WW; w++) sWgt[w] *= inv;
    }
    __syncthreads();

    // out = l2norm(sum_w wgt*mid)
    float o = 0.f;
#pragma unroll
    for (int w = 0; w < WW; w++) o = fmaf(sWgt[w], sMid[w*SS + tid], o);
    float sq = warp_sum(o * o);
    if (lane == 0) sRed[wid] = sq;
    __syncthreads();
    if (tid == 0) {
        float tot = 0.f;
#pragma unroll
        for (int k = 0; k < 8; k++) tot += sRed[k];
        sMisc[0] = 1.f / (sqrtf(tot) + 1e-8f);
    }
    __syncthreads();
    hout[(size_t)b*SS + tid] = o * sMisc[0];
}

// ---------------------------------------------------------------------------
// final: sim = sigmoid(hig @ ew + eb); out[n][c] (transposed)
// ---------------------------------------------------------------------------
__global__ void final_kernel(const float* __restrict__ ew, const float* __restrict__ eb,
                             float* __restrict__ out)
{
    int gw = (blockIdx.x * blockDim.x + threadIdx.x) >> 5;
    int lane = threadIdx.x & 31;
    int nwarps = (gridDim.x * blockDim.x) >> 5;
    for (int b = gw; b < CC*NN; b += nwarps) {
        const float* h = g_higA + (size_t)b*SS;
        float a = 0.f;
#pragma unroll
        for (int k = 0; k < 8; k++) a = fmaf(h[lane + k*32], ew[lane + k*32], a);
        a = warp_sum(a);
        if (lane == 0) {
            float v = a + eb[0];
            int c = b / NN, n = b % NN;
            out[n*CC + c] = 1.f / (1.f + expf(-v));
        }
    }
}

// ---------------------------------------------------------------------------
extern "C" void kernel_launch(void* const* d_in, const int* in_sizes, int n_in,
                              void* d_out, int out_size)
{
    const float* img  = (const float*)d_in[0];
    const float* cap  = (const float*)d_in[1];
    const int*   lens = (const int*)  d_in[2];
    const float* alvw = (const float*)d_in[3];
    const float* alvb = (const float*)d_in[4];
    const float* qw   = (const float*)d_in[5];
    const float* qb   = (const float*)d_in[6];
    const float* kw   = (const float*)d_in[7];
    const float* kb   = (const float*)d_in[8];
    const float* vw   = (const float*)d_in[9];
    const float* vb   = (const float*)d_in[10];
    const float* smw1 = (const float*)d_in[11];
    const float* smb1 = (const float*)d_in[12];
    const float* smw2 = (const float*)d_in[13];
    const float* smb2 = (const float*)d_in[14];
    const float* mxw1 = (const float*)d_in[15];
    const float* mxb1 = (const float*)d_in[16];
    const float* mxw2 = (const float*)d_in[17];
    const float* mxb2 = (const float*)d_in[18];
    const float* ew   = (const float*)d_in[19];
    const float* eb   = (const float*)d_in[20];
    float* out = (float*)d_out;

    const size_t ALV_SMEM = (size_t)(RR*DD + WW*256 + RR*WW + WW*RR + WW*8 + WW) * sizeof(float);
    const size_t RCR_SMEM = (size_t)(WW*SS + WW*512 + WW*4 + 64) * sizeof(float);
    const size_t RAR_SMEM = (size_t)(WW*SS + SS + SS + WW*8 + WW + WW + 32) * sizeof(float);

    cudaFuncSetAttribute(alv_kernel<0>, cudaFuncAttributeMaxDynamicSharedMemorySize, (int)ALV_SMEM);
    cudaFuncSetAttribute(alv_kernel<1>, cudaFuncAttributeMaxDynamicSharedMemorySize, (int)ALV_SMEM);
    cudaFuncSetAttribute(rcr_kernel,    cudaFuncAttributeMaxDynamicSharedMemorySize, (int)RCR_SMEM);

    const int B = CC * NN;

    // pass 0
    alv_kernel<0><<<B, 256, ALV_SMEM>>>(img, cap, lens, alvw, alvb);
    mean_kernel<<<B, 256>>>(lens);
    rcr_kernel<<<B, 512, RCR_SMEM>>>(cap, mxw1, mxb1, mxw2, mxb2, smw1, smb1, smw2, smb2);
    rar_kernel<<<B, 256, RAR_SMEM>>>(lens, qw, qb, kw, kb, vw, vb, 0);

    // pass 1
    alv_kernel<1><<<B, 256, ALV_SMEM>>>(img, cap, lens, alvw + (size_t)DD*SS, alvb + SS);
    rar_kernel<<<B, 256, RAR_SMEM>>>(lens, qw + SS*SS, qb + SS, kw + SS*SS, kb + SS,
                                     vw + SS, vb + 1, 1);

    final_kernel<<<9, 256>>>(ew, eb, out);
}

// round 3
// speedup vs baseline: 1.6128x; 1.6128x over previous
#include <cuda_runtime.h>
#include <math.h>

#define CC 48
#define NN 48
#define WW 24
#define RR 36
#define DD 1024
#define SS 256

// ---------------- scratch (device globals; no allocation allowed) ----------
__device__ __align__(16) float g_sim_mid[CC*NN*WW*SS];   // 56.6 MB
__device__ __align__(16) float g_smooth[CC*NN*WW];
__device__ __align__(16) float g_qm[(size_t)CC*NN*WW*DD]; // 226 MB
__device__ __align__(16) float g_higA[CC*NN*SS];
__device__ __align__(16) float g_higB[CC*NN*SS];

__device__ __forceinline__ float warp_sum(float v) {
#pragma unroll
    for (int o = 16; o; o >>= 1) v += __shfl_xor_sync(0xffffffffu, v, o);
    return v;
}

// ---------------------------------------------------------------------------
// alv pass: per (c,n) block: attn -> softmax -> wctx -> sim ->
// sim_mid = l2norm(sim @ alv_w + alv_b)
// PASS 0: query = cap_emb, smooth = 9 ; PASS 1: query = g_qm, smooth = g_smooth
// ---------------------------------------------------------------------------
template<int PASS>
__global__ void __launch_bounds__(256) alv_kernel(
        const float* __restrict__ img, const float* __restrict__ cap,
        const int* __restrict__ lens,
        const float* __restrict__ alvw, const float* __restrict__ alvb)
{
    extern __shared__ float sm[];
    float* sImg = sm;                    // RR*DD (36864)
    float* sSim = sImg + RR*DD;          // WW*256 (6144)
    float* sA   = sSim + WW*256;         // RR*WW raw attn
    float* sAT  = sA + RR*WW;            // WW*RR (for softmax)
    float* sA2  = sAT + WW*RR;           // RR*WW r-major softmaxed attn (16B aligned)
    float* sRed = sA2 + RR*WW;           // WW*8
    float* sFac = sRed + WW*8;           // WW

    const int b = blockIdx.x;
    const int c = b / NN, n = b % NN;
    const int tid = threadIdx.x, lane = tid & 31, wid = tid >> 5;
    const int len = lens[c];

    // stage image block (36x1024 f32) into SMEM
    {
        const float4* gi = (const float4*)(img + (size_t)n * RR * DD);
        float4* si = (float4*)sImg;
        for (int i = tid; i < RR*DD/4; i += 256) si[i] = gi[i];
    }
    __syncthreads();

    // ---- phase 1: raw attn[r][w] = <query_w, img_r> ----
    for (int wi = 0; wi < 3; wi++) {
        int w = wid + wi * 8;
        const float* capp = (PASS == 0) ? (cap + ((size_t)c*WW + w)*DD)
                                        : (g_qm + ((size_t)b*WW + w)*DD);
        float4 cr4[8];
#pragma unroll
        for (int k = 0; k < 8; k++)
            cr4[k] = *(const float4*)(capp + k*128 + lane*4);
        for (int r = 0; r < RR; r += 2) {
            float a0 = 0.f, a1 = 0.f;
#pragma unroll
            for (int k = 0; k < 8; k++) {
                float4 i0 = *(const float4*)(sImg + r*DD + k*128 + lane*4);
                float4 i1 = *(const float4*)(sImg + (r+1)*DD + k*128 + lane*4);
                a0 = fmaf(cr4[k].x, i0.x, a0); a0 = fmaf(cr4[k].y, i0.y, a0);
                a0 = fmaf(cr4[k].z, i0.z, a0); a0 = fmaf(cr4[k].w, i0.w, a0);
                a1 = fmaf(cr4[k].x, i1.x, a1); a1 = fmaf(cr4[k].y, i1.y, a1);
                a1 = fmaf(cr4[k].z, i1.z, a1); a1 = fmaf(cr4[k].w, i1.w, a1);
            }
            a0 = warp_sum(a0); a1 = warp_sum(a1);
            if (lane == 0) { sA[r*WW + w] = a0; sA[(r+1)*WW + w] = a1; }
        }
    }
    __syncthreads();

    // ---- phase 2a: leaky relu, word mask, l2norm over words (per region) ----
    if (tid < RR) {
        int r = tid;
        float vals[WW];
        float ss = 0.f;
#pragma unroll
        for (int w = 0; w < WW; w++) {
            float v = sA[r*WW + w];
            v = (v >= 0.f) ? v : 0.1f * v;
            if (w >= len) v = 0.f;
            vals[w] = v;
            ss += v * v;
        }
        float f = 1.f / (sqrtf(ss) + 1e-8f);
#pragma unroll
        for (int w = 0; w < WW; w++) sAT[w*RR + r] = vals[w] * f;
    }
    __syncthreads();

    // ---- phase 2b: softmax over regions (per word), scaled by smooth ----
    if (tid < WW) {
        int w = tid;
        float smo = (PASS == 0) ? 9.f : g_smooth[(size_t)b*WW + w];
        float m = -1e30f;
        for (int r = 0; r < RR; r++) { float v = sAT[w*RR + r]*smo; if (v > m) m = v; }
        float s = 0.f;
        for (int r = 0; r < RR; r++) {
            float e = expf(sAT[w*RR + r]*smo - m);
            sAT[w*RR + r] = e; s += e;
        }
        float inv = 1.f / s;
        for (int r = 0; r < RR; r++) sA2[r*WW + w] = sAT[w*RR + r] * inv;
    }
    __syncthreads();

    // ---- phase 3a: wctx sum-of-squares per word (l2norm over D) ----
    {
        float psq[WW];
#pragma unroll
        for (int w = 0; w < WW; w++) psq[w] = 0.f;
        for (int cidx = 0; cidx < 4; cidx++) {
            int d = cidx*256 + tid;
            float acc[WW];
#pragma unroll
            for (int w = 0; w < WW; w++) acc[w] = 0.f;
            for (int r = 0; r < RR; r++) {
                float iv = sImg[r*DD + d];
                const float4* ap = (const float4*)(sA2 + r*WW);
#pragma unroll
                for (int q = 0; q < 6; q++) {
                    float4 a4 = ap[q];
                    acc[q*4+0] = fmaf(a4.x, iv, acc[q*4+0]);
                    acc[q*4+1] = fmaf(a4.y, iv, acc[q*4+1]);
                    acc[q*4+2] = fmaf(a4.z, iv, acc[q*4+2]);
                    acc[q*4+3] = fmaf(a4.w, iv, acc[q*4+3]);
                }
            }
#pragma unroll
            for (int w = 0; w < WW; w++) psq[w] = fmaf(acc[w], acc[w], psq[w]);
        }
#pragma unroll
        for (int w = 0; w < WW; w++) {
            float v = warp_sum(psq[w]);
            if (lane == 0) sRed[w*8 + wid] = v;
        }
    }
    __syncthreads();
    if (tid < WW) {
        float s = 0.f;
#pragma unroll
        for (int k = 0; k < 8; k++) s += sRed[tid*8 + k];
        sFac[tid] = 1.f / (sqrtf(s) + 1e-8f);
    }
    __syncthreads();

    // ---- phase 3b: recompute wctx chunk, sim = (cap - wctx_n)^2,
    //      fused GEMM accS[w] (s-col = tid) += sim @ alv_w ----
    float accS[WW];
#pragma unroll
    for (int w = 0; w < WW; w++) accS[w] = alvb[tid];
    for (int cidx = 0; cidx < 4; cidx++) {
        int d = cidx*256 + tid;
        {
            float acc[WW];
#pragma unroll
            for (int w = 0; w < WW; w++) acc[w] = 0.f;
            for (int r = 0; r < RR; r++) {
                float iv = sImg[r*DD + d];
                const float4* ap = (const float4*)(sA2 + r*WW);
#pragma unroll
                for (int q = 0; q < 6; q++) {
                    float4 a4 = ap[q];
                    acc[q*4+0] = fmaf(a4.x, iv, acc[q*4+0]);
                    acc[q*4+1] = fmaf(a4.y, iv, acc[q*4+1]);
                    acc[q*4+2] = fmaf(a4.z, iv, acc[q*4+2]);
                    acc[q*4+3] = fmaf(a4.w, iv, acc[q*4+3]);
                }
            }
#pragma unroll
            for (int w = 0; w < WW; w++) {
                float wc = acc[w] * sFac[w];
                float cv = cap[((size_t)c*WW + w)*DD + d];
                float df = cv - wc;
                sSim[w*256 + tid] = df * df;
            }
        }
        __syncthreads();
        // GEMM: accS[w] += sim[w][j] * alvw[cidx*256+j][tid], float4 over j
        const float* wp = alvw + (size_t)(cidx*256) * SS + tid;
#pragma unroll 2
        for (int j0 = 0; j0 < 64; j0++) {
            float w0 = wp[(size_t)(j0*4+0) * SS];
            float w1 = wp[(size_t)(j0*4+1) * SS];
            float w2 = wp[(size_t)(j0*4+2) * SS];
            float w3 = wp[(size_t)(j0*4+3) * SS];
#pragma unroll
            for (int w = 0; w < WW; w++) {
                float4 s4 = *(const float4*)(sSim + w*256 + j0*4);
                accS[w] = fmaf(s4.x, w0, accS[w]);
                accS[w] = fmaf(s4.y, w1, accS[w]);
                accS[w] = fmaf(s4.z, w2, accS[w]);
                accS[w] = fmaf(s4.w, w3, accS[w]);
            }
        }
        __syncthreads();
    }

    // ---- final: l2norm over S and store ----
    {
#pragma unroll
        for (int w = 0; w < WW; w++) {
            float v = warp_sum(accS[w] * accS[w]);
            if (lane == 0) sRed[w*8 + wid] = v;
        }
        __syncthreads();
        if (tid < WW) {
            float s = 0.f;
#pragma unroll
            for (int k = 0; k < 8; k++) s += sRed[tid*8 + k];
            sFac[tid] = 1.f / (sqrtf(s) + 1e-8f);
        }
        __syncthreads();
#pragma unroll
        for (int w = 0; w < WW; w++)
            g_sim_mid[((size_t)b*WW + w)*SS + tid] = accS[w] * sFac[w];
    }
}

// ---------------------------------------------------------------------------
// masked mean over words -> g_higA
// ---------------------------------------------------------------------------
__global__ void mean_kernel(const int* __restrict__ lens)
{
    int b = blockIdx.x;
    int c = b / NN;
    int t = threadIdx.x;
    int len = lens[c];
    float inv = 1.f / (float)len;
    const float* p = g_sim_mid + (size_t)b*WW*SS + t;
    float s = 0.f;
    for (int w = 0; w < len; w++) s += p[(size_t)w * SS];
    g_higA[(size_t)b*SS + t] = s * inv;
}

// ---------------------------------------------------------------------------
// RCR: per (c,n) block (512 threads).
// ---------------------------------------------------------------------------
__global__ void __launch_bounds__(512) rcr_kernel(
        const float* __restrict__ cap,
        const float* __restrict__ mxw1, const float* __restrict__ mxb1,
        const float* __restrict__ mxw2, const float* __restrict__ mxb2,
        const float* __restrict__ smw1, const float* __restrict__ smb1,
        const float* __restrict__ smw2, const float* __restrict__ smb2)
{
    extern __shared__ float sm[];
    float* sX   = sm;              // WW*SS  (6144)
    float* sH   = sX + WW*SS;      // WW*512 (12288)
    float* sRed = sH + WW*512;     // WW*4

    const int b = blockIdx.x;
    const int c = b / NN;
    const int tid = threadIdx.x, lane = tid & 31, wid = tid >> 5;

    {
        const float4* gx = (const float4*)(g_sim_mid + (size_t)b*WW*SS);
        float4* sx4 = (float4*)sX;
        for (int i = tid; i < WW*SS/4; i += 512) sx4[i] = gx[i];
    }
    __syncthreads();

    // h1 = tanh(x @ W1 + b1): thread owns hidden col = tid (512 cols)
    {
        float acc[WW];
#pragma unroll
        for (int w = 0; w < WW; w++) acc[w] = mxb1[tid];
        const float* wp = mxw1 + tid;
#pragma unroll 2
        for (int d0 = 0; d0 < SS/4; d0++) {
            float w0 = wp[(size_t)(d0*4+0) * 512];
            float w1 = wp[(size_t)(d0*4+1) * 512];
            float w2 = wp[(size_t)(d0*4+2) * 512];
            float w3 = wp[(size_t)(d0*4+3) * 512];
#pragma unroll
            for (int w = 0; w < WW; w++) {
                float4 x4 = *(const float4*)(sX + w*SS + d0*4);
                acc[w] = fmaf(x4.x, w0, acc[w]);
                acc[w] = fmaf(x4.y, w1, acc[w]);
                acc[w] = fmaf(x4.z, w2, acc[w]);
                acc[w] = fmaf(x4.w, w3, acc[w]);
            }
        }
#pragma unroll
        for (int w = 0; w < WW; w++) sH[w*512 + tid] = tanhf(acc[w]);
    }

    // smooth branch (threads 0..127 own the 128 hidden cols)
    if (tid < 128) {
        float acc[WW];
#pragma unroll
        for (int w = 0; w < WW; w++) acc[w] = smb1[tid];
        const float* wp = smw1 + tid;
#pragma unroll 2
        for (int d0 = 0; d0 < SS/4; d0++) {
            float w0 = wp[(size_t)(d0*4+0) * 128];
            float w1 = wp[(size_t)(d0*4+1) * 128];
            float w2 = wp[(size_t)(d0*4+2) * 128];
            float w3 = wp[(size_t)(d0*4+3) * 128];
#pragma unroll
            for (int w = 0; w < WW; w++) {
                float4 x4 = *(const float4*)(sX + w*SS + d0*4);
                acc[w] = fmaf(x4.x, w0, acc[w]);
                acc[w] = fmaf(x4.y, w1, acc[w]);
                acc[w] = fmaf(x4.z, w2, acc[w]);
                acc[w] = fmaf(x4.w, w3, acc[w]);
            }
        }
        float v2 = smw2[tid];
#pragma unroll
        for (int w = 0; w < WW; w++) {
            float h = tanhf(acc[w]);
            float pv = warp_sum(h * v2);
            if (lane == 0) sRed[w*4 + wid] = pv;
        }
    }
    __syncthreads();
    if (tid < WW) {
        float s = sRed[tid*4] + sRed[tid*4+1] + sRed[tid*4+2] + sRed[tid*4+3];
        s += smb2[0] + 9.0f;
        g_smooth[(size_t)b*WW + tid] = s > 0.f ? s : 0.f;
    }

    // mx / qm: 1024 output cols, two halves of 512
    for (int half = 0; half < 2; half++) {
        int d = tid + half * 512;
        float acc[WW];
#pragma unroll
        for (int w = 0; w < WW; w++) acc[w] = mxb2[d];
        const float* wp = mxw2 + d;
#pragma unroll 2
        for (int h0 = 0; h0 < 128; h0++) {
            float w0 = wp[(size_t)(h0*4+0) * DD];
            float w1 = wp[(size_t)(h0*4+1) * DD];
            float w2 = wp[(size_t)(h0*4+2) * DD];
            float w3 = wp[(size_t)(h0*4+3) * DD];
#pragma unroll
            for (int w = 0; w < WW; w++) {
                float4 h4 = *(const float4*)(sH + w*512 + h0*4);
                acc[w] = fmaf(h4.x, w0, acc[w]);
                acc[w] = fmaf(h4.y, w1, acc[w]);
                acc[w] = fmaf(h4.z, w2, acc[w]);
                acc[w] = fmaf(h4.w, w3, acc[w]);
            }
        }
#pragma unroll
        for (int w = 0; w < WW; w++) {
            float mx = tanhf(acc[w]);
            float mat = mx + 1.f;
            mat = fminf(fmaxf(mat, -1.f), 1.f);
            g_qm[((size_t)b*WW + w)*DD + d] = cap[((size_t)c*WW + w)*DD + d] * mat;
        }
    }
}

// ---------------------------------------------------------------------------
// RAR attention pooling
// ---------------------------------------------------------------------------
__global__ void __launch_bounds__(256) rar_kernel(
        const int* __restrict__ lens,
        const float* __restrict__ qw, const float* __restrict__ qb,
        const float* __restrict__ kw, const float* __restrict__ kb,
        const float* __restrict__ vw, const float* __restrict__ vb,
        int dir)
{
    extern __shared__ float sm[];
    float* sMid = sm;             // WW*SS (6144)
    float* sHig = sMid + WW*SS;   // SS
    float* sHq  = sHig + SS;      // SS
    float* sRed = sHq + SS;       // WW*8
    float* sLog = sRed + WW*8;    // WW
    float* sWgt = sLog + WW;      // WW
    float* sMisc= sWgt + WW;      // misc

    const int b = blockIdx.x;
    const int c = b / NN;
    const int tid = threadIdx.x, lane = tid & 31, wid = tid >> 5;
    const int len = lens[c];

    const float* hin = (dir == 0) ? g_higA : g_higB;
    float*       hout= (dir == 0) ? g_higB : g_higA;

    {
        const float4* gm = (const float4*)(g_sim_mid + (size_t)b*WW*SS);
        float4* s4 = (float4*)sMid;
        for (int i = tid; i < WW*SS/4; i += 256) s4[i] = gm[i];
    }
    sHig[tid] = hin[(size_t)b*SS + tid];
    __syncthreads();

    // hig_q = tanh(hig @ q_w + q_b)
    {
        float acc = qb[tid];
        const float* wp = qw + tid;
#pragma unroll 4
        for (int s0 = 0; s0 < SS/4; s0++) {
            float4 h4 = *(const float4*)(sHig + s0*4);
            acc = fmaf(h4.x, wp[(size_t)(s0*4+0)*SS], acc);
            acc = fmaf(h4.y, wp[(size_t)(s0*4+1)*SS], acc);
            acc = fmaf(h4.z, wp[(size_t)(s0*4+2)*SS], acc);
            acc = fmaf(h4.w, wp[(size_t)(s0*4+3)*SS], acc);
        }
        sHq[tid] = tanhf(acc);
    }
    __syncthreads();

    // mid_k = tanh(mid @ k_w + k_b); logits[w] = sum_s mid_k*hq*vw + vb
    {
        float acck[WW];
#pragma unroll
        for (int w = 0; w < WW; w++) acck[w] = kb[tid];
        const float* wp = kw + tid;
#pragma unroll 2
        for (int s0 = 0; s0 < SS/4; s0++) {
            float w0 = wp[(size_t)(s0*4+0) * SS];
            float w1 = wp[(size_t)(s0*4+1) * SS];
            float w2 = wp[(size_t)(s0*4+2) * SS];
            float w3 = wp[(size_t)(s0*4+3) * SS];
#pragma unroll
            for (int w = 0; w < WW; w++) {
                float4 m4 = *(const float4*)(sMid + w*SS + s0*4);
                acck[w] = fmaf(m4.x, w0, acck[w]);
                acck[w] = fmaf(m4.y, w1, acck[w]);
                acck[w] = fmaf(m4.z, w2, acck[w]);
                acck[w] = fmaf(m4.w, w3, acck[w]);
            }
        }
        float hv = sHq[tid] * vw[tid];
#pragma unroll
        for (int w = 0; w < WW; w++) {
            float pv = warp_sum(tanhf(acck[w]) * hv);
            if (lane == 0) sRed[w*8 + wid] = pv;
        }
    }
    __syncthreads();
    if (tid < WW) {
        float s = 0.f;
#pragma unroll
        for (int k = 0; k < 8; k++) s += sRed[tid*8 + k];
        s += vb[0];
        if (tid >= len) s = -1e30f;
        sLog[tid] = s;
    }
    __syncthreads();
    if (tid == 0) {
        float m = -1e30f;
        for (int w = 0; w < WW; w++) m = fmaxf(m, sLog[w]);
        float s = 0.f;
        for (int w = 0; w < WW; w++) { float e = expf(sLog[w] - m); sWgt[w] = e; s += e; }
        float inv = 1.f / s;
        for (int w = 0; w < WW; w++) sWgt[w] *= inv;
    }
    __syncthreads();

    // out = l2norm(sum_w wgt*mid)
    float o = 0.f;
#pragma unroll
    for (int w = 0; w < WW; w++) o = fmaf(sWgt[w], sMid[w*SS + tid], o);
    float sq = warp_sum(o * o);
    if (lane == 0) sRed[wid] = sq;
    __syncthreads();
    if (tid == 0) {
        float tot = 0.f;
#pragma unroll
        for (int k = 0; k < 8; k++) tot += sRed[k];
        sMisc[0] = 1.f / (sqrtf(tot) + 1e-8f);
    }
    __syncthreads();
    hout[(size_t)b*SS + tid] = o * sMisc[0];
}

// ---------------------------------------------------------------------------
// final: sim = sigmoid(hig @ ew + eb); out[n][c]
// ---------------------------------------------------------------------------
__global__ void final_kernel(const float* __restrict__ ew, const float* __restrict__ eb,
                             float* __restrict__ out)
{
    int gw = (blockIdx.x * blockDim.x + threadIdx.x) >> 5;
    int lane = threadIdx.x & 31;
    int nwarps = (gridDim.x * blockDim.x) >> 5;
    for (int b = gw; b < CC*NN; b += nwarps) {
        const float* h = g_higA + (size_t)b*SS;
        float a = 0.f;
#pragma unroll
        for (int k = 0; k < 8; k++) a = fmaf(h[lane + k*32], ew[lane + k*32], a);
        a = warp_sum(a);
        if (lane == 0) {
            float v = a + eb[0];
            int c = b / NN, n = b % NN;
            out[n*CC + c] = 1.f / (1.f + expf(-v));
        }
    }
}

// ---------------------------------------------------------------------------
extern "C" void kernel_launch(void* const* d_in, const int* in_sizes, int n_in,
                              void* d_out, int out_size)
{
    const float* img  = (const float*)d_in[0];
    const float* cap  = (const float*)d_in[1];
    const int*   lens = (const int*)  d_in[2];
    const float* alvw = (const float*)d_in[3];
    const float* alvb = (const float*)d_in[4];
    const float* qw   = (const float*)d_in[5];
    const float* qb   = (const float*)d_in[6];
    const float* kw   = (const float*)d_in[7];
    const float* kb   = (const float*)d_in[8];
    const float* vw   = (const float*)d_in[9];
    const float* vb   = (const float*)d_in[10];
    const float* smw1 = (const float*)d_in[11];
    const float* smb1 = (const float*)d_in[12];
    const float* smw2 = (const float*)d_in[13];
    const float* smb2 = (const float*)d_in[14];
    const float* mxw1 = (const float*)d_in[15];
    const float* mxb1 = (const float*)d_in[16];
    const float* mxw2 = (const float*)d_in[17];
    const float* mxb2 = (const float*)d_in[18];
    const float* ew   = (const float*)d_in[19];
    const float* eb   = (const float*)d_in[20];
    float* out = (float*)d_out;

    const size_t ALV_SMEM = (size_t)(RR*DD + WW*256 + RR*WW*3 + WW*8 + WW + 16) * sizeof(float);
    const size_t RCR_SMEM = (size_t)(WW*SS + WW*512 + WW*4 + 64) * sizeof(float);
    const size_t RAR_SMEM = (size_t)(WW*SS + SS + SS + WW*8 + WW + WW + 32) * sizeof(float);

    cudaFuncSetAttribute(alv_kernel<0>, cudaFuncAttributeMaxDynamicSharedMemorySize, (int)ALV_SMEM);
    cudaFuncSetAttribute(alv_kernel<1>, cudaFuncAttributeMaxDynamicSharedMemorySize, (int)ALV_SMEM);
    cudaFuncSetAttribute(rcr_kernel,    cudaFuncAttributeMaxDynamicSharedMemorySize, (int)RCR_SMEM);

    const int B = CC * NN;

    // pass 0
    alv_kernel<0><<<B, 256, ALV_SMEM>>>(img, cap, lens, alvw, alvb);
    mean_kernel<<<B, 256>>>(lens);
    rcr_kernel<<<B, 512, RCR_SMEM>>>(cap, mxw1, mxb1, mxw2, mxb2, smw1, smb1, smw2, smb2);
    rar_kernel<<<B, 256, RAR_SMEM>>>(lens, qw, qb, kw, kb, vw, vb, 0);

    // pass 1
    alv_kernel<1><<<B, 256, ALV_SMEM>>>(img, cap, lens, alvw + (size_t)DD*SS, alvb + SS);
    rar_kernel<<<B, 256, RAR_SMEM>>>(lens, qw + SS*SS, qb + SS, kw + SS*SS, kb + SS,
                                     vw + SS, vb + 1, 1);

    final_kernel<<<9, 256>>>(ew, eb, out);
}

// round 4
// speedup vs baseline: 1.9504x; 1.2093x over previous
#include <cuda_runtime.h>
#include <math.h>
#include <stdint.h>

#define CC 48
#define NN 48
#define WW 24
#define RR 36
#define DD 1024
#define SS 256
#define MTOT (CC*NN*WW)   // 55296

// ---------------- scratch (device globals; no allocation allowed) ----------
__device__ __align__(16) float g_sim_mid[MTOT*SS];          // 56.6 MB
__device__ __align__(16) float g_smooth[MTOT];
__device__ __align__(16) float g_qm[(size_t)MTOT*DD];       // 226 MB
__device__ __align__(16) float g_simbuf[(size_t)MTOT*DD];   // 226 MB
__device__ __align__(16) float g_h[(size_t)MTOT*512];       // 113 MB
__device__ __align__(16) float g_hsm[(size_t)MTOT*128];     // 28 MB
__device__ __align__(16) float g_higA[CC*NN*SS];
__device__ __align__(16) float g_higB[CC*NN*SS];

__device__ __forceinline__ float warp_sum(float v) {
#pragma unroll
    for (int o = 16; o; o >>= 1) v += __shfl_xor_sync(0xffffffffu, v, o);
    return v;
}

__device__ __forceinline__ uint32_t f2t(float f){
    uint32_t u; asm("cvt.rna.tf32.f32 %0, %1;" : "=r"(u) : "f"(f)); return u;
}
__device__ __forceinline__ void mma8(float* d, const uint32_t* a, const uint32_t* b){
    asm volatile("mma.sync.aligned.m16n8k8.row.col.f32.tf32.tf32.f32 "
        "{%0,%1,%2,%3}, {%4,%5,%6,%7}, {%8,%9}, {%0,%1,%2,%3};"
        : "+f"(d[0]),"+f"(d[1]),"+f"(d[2]),"+f"(d[3])
        : "r"(a[0]),"r"(a[1]),"r"(a[2]),"r"(a[3]),"r"(b[0]),"r"(b[1]));
}

// ---------------------------------------------------------------------------
// Generic tf32 GEMM: C(M_TOT x N_TOT) = A(M_TOT x K_DIM) @ B(K_DIM x N_TOT)
// M_blk=32, 8 warps each own 32(M) x N_BLK/8 (N). Double-buffered smem.
// EPI 0: +bias, l2norm over full row (requires N_BLK==N_TOT==256)
// EPI 1: +bias, tanh
// EPI 2: +bias, tanh, clip(x+1,-1,1), * cap row
// ---------------------------------------------------------------------------
template<int N_BLK, int K_DIM, int N_TOT, int EPI>
__global__ void __launch_bounds__(256) gemm_kernel(
    const float* __restrict__ A, const float* __restrict__ Bw,
    const float* __restrict__ bias, float* __restrict__ Cout,
    const float* __restrict__ cap)
{
    constexpr int SA = 36;             // 32 + 4 pad (stride % 32 == 4)
    constexpr int SB = N_BLK + 8;      // stride % 32 == 8
    constexpr int KT = K_DIM / 32;
    constexpr int NT = N_BLK / 64;     // n-tiles (of 8) per warp
    constexpr int BF4 = N_BLK / 4;     // float4 per B row
    constexpr int BROWS = 256 / BF4;   // B rows loaded per pass
    constexpr int BPASS = 32 / BROWS;

    extern __shared__ uint32_t dsm[];
    uint32_t* As = dsm;                          // 2 * 32*SA
    uint32_t* Bs = dsm + 2*32*SA;                // 2 * 32*SB
    float* sRed  = (float*)(dsm + 2*32*SA + 2*32*SB);  // 32*8
    float* sFacR = sRed + 32*8;                  // 32

    const int m0 = blockIdx.x * 32;
    const int n0 = blockIdx.y * N_BLK;
    const int tid = threadIdx.x, lane = tid & 31, wid = tid >> 5;
    const int g = lane >> 2, tig = lane & 3;
    const int wn0 = wid * (N_BLK/8);

    const int a_row = tid >> 3, a_c4 = tid & 7;
    const float* Aptr = A + (size_t)(m0 + a_row)*K_DIM + a_c4*4;
    const int b_r = tid / BF4, b_c4 = tid % BF4;
    const float* Bptr = Bw + (size_t)b_r*N_TOT + n0 + b_c4*4;

    float4 pa; float4 pb[BPASS];
    // prologue: tile 0
    pa = *(const float4*)(Aptr);
#pragma unroll
    for (int p = 0; p < BPASS; p++)
        pb[p] = *(const float4*)(Bptr + (size_t)(p*BROWS)*N_TOT);
    {
        uint4 av = make_uint4(f2t(pa.x), f2t(pa.y), f2t(pa.z), f2t(pa.w));
        *(uint4*)(As + a_row*SA + a_c4*4) = av;
#pragma unroll
        for (int p = 0; p < BPASS; p++) {
            uint4 bv = make_uint4(f2t(pb[p].x), f2t(pb[p].y), f2t(pb[p].z), f2t(pb[p].w));
            *(uint4*)(Bs + (b_r + p*BROWS)*SB + b_c4*4) = bv;
        }
    }
    __syncthreads();

    float acc[2][NT][4];
#pragma unroll
    for (int i = 0; i < 2; i++)
#pragma unroll
        for (int j = 0; j < NT; j++)
#pragma unroll
            for (int k = 0; k < 4; k++) acc[i][j][k] = 0.f;

    for (int kt = 0; kt < KT; kt++) {
        const uint32_t* Ac = As + (kt & 1) * (32*SA);
        const uint32_t* Bc = Bs + (kt & 1) * (32*SB);
        if (kt + 1 < KT) {
            pa = *(const float4*)(Aptr + (size_t)(kt+1)*32);
#pragma unroll
            for (int p = 0; p < BPASS; p++)
                pb[p] = *(const float4*)(Bptr + (size_t)((kt+1)*32 + p*BROWS)*N_TOT);
        }
#pragma unroll
        for (int ks = 0; ks < 4; ks++) {
            const int kb = ks * 8;
            uint32_t af[2][4];
#pragma unroll
            for (int i = 0; i < 2; i++) {
                af[i][0] = Ac[(i*16 + g    )*SA + kb + tig];
                af[i][1] = Ac[(i*16 + g + 8)*SA + kb + tig];
                af[i][2] = Ac[(i*16 + g    )*SA + kb + tig + 4];
                af[i][3] = Ac[(i*16 + g + 8)*SA + kb + tig + 4];
            }
            uint32_t bf[NT][2];
#pragma unroll
            for (int j = 0; j < NT; j++) {
                bf[j][0] = Bc[(kb + tig    )*SB + wn0 + j*8 + g];
                bf[j][1] = Bc[(kb + tig + 4)*SB + wn0 + j*8 + g];
            }
#pragma unroll
            for (int i = 0; i < 2; i++)
#pragma unroll
                for (int j = 0; j < NT; j++)
                    mma8(acc[i][j], af[i], bf[j]);
        }
        if (kt + 1 < KT) {
            uint4 av = make_uint4(f2t(pa.x), f2t(pa.y), f2t(pa.z), f2t(pa.w));
            *(uint4*)(As + ((kt+1)&1)*(32*SA) + a_row*SA + a_c4*4) = av;
            uint32_t* Bd0 = Bs + ((kt+1)&1)*(32*SB);
#pragma unroll
            for (int p = 0; p < BPASS; p++) {
                uint4 bv = make_uint4(f2t(pb[p].x), f2t(pb[p].y), f2t(pb[p].z), f2t(pb[p].w));
                *(uint4*)(Bd0 + (b_r + p*BROWS)*SB + b_c4*4) = bv;
            }
        }
        __syncthreads();
    }

    // add bias
#pragma unroll
    for (int j = 0; j < NT; j++) {
        int coln = n0 + wn0 + j*8 + 2*tig;
        float b0 = bias[coln], b1 = bias[coln + 1];
#pragma unroll
        for (int i = 0; i < 2; i++) {
            acc[i][j][0] += b0; acc[i][j][1] += b1;
            acc[i][j][2] += b0; acc[i][j][3] += b1;
        }
    }

    if (EPI == 0) {
        // l2norm over the full 256-wide row, then store
        float ps[2][2];
#pragma unroll
        for (int i = 0; i < 2; i++) {
            ps[i][0] = 0.f; ps[i][1] = 0.f;
#pragma unroll
            for (int j = 0; j < NT; j++) {
                ps[i][0] += acc[i][j][0]*acc[i][j][0] + acc[i][j][1]*acc[i][j][1];
                ps[i][1] += acc[i][j][2]*acc[i][j][2] + acc[i][j][3]*acc[i][j][3];
            }
        }
#pragma unroll
        for (int i = 0; i < 2; i++)
#pragma unroll
            for (int h = 0; h < 2; h++) {
                ps[i][h] += __shfl_xor_sync(0xffffffffu, ps[i][h], 1);
                ps[i][h] += __shfl_xor_sync(0xffffffffu, ps[i][h], 2);
            }
        if (tig == 0) {
#pragma unroll
            for (int i = 0; i < 2; i++) {
                sRed[(i*16 + g    )*8 + wid] = ps[i][0];
                sRed[(i*16 + g + 8)*8 + wid] = ps[i][1];
            }
        }
        __syncthreads();
        if (tid < 32) {
            float s = 0.f;
#pragma unroll
            for (int k = 0; k < 8; k++) s += sRed[tid*8 + k];
            sFacR[tid] = 1.f / (sqrtf(s) + 1e-8f);
        }
        __syncthreads();
#pragma unroll
        for (int i = 0; i < 2; i++) {
            float f0 = sFacR[i*16 + g], f1 = sFacR[i*16 + g + 8];
#pragma unroll
            for (int j = 0; j < NT; j++) {
                int coln = wn0 + j*8 + 2*tig;
                *(float2*)&Cout[(size_t)(m0 + i*16 + g    )*N_TOT + coln] =
                    make_float2(acc[i][j][0]*f0, acc[i][j][1]*f0);
                *(float2*)&Cout[(size_t)(m0 + i*16 + g + 8)*N_TOT + coln] =
                    make_float2(acc[i][j][2]*f1, acc[i][j][3]*f1);
            }
        }
    } else if (EPI == 1) {
#pragma unroll
        for (int i = 0; i < 2; i++)
#pragma unroll
            for (int j = 0; j < NT; j++) {
                int coln = n0 + wn0 + j*8 + 2*tig;
                *(float2*)&Cout[(size_t)(m0 + i*16 + g    )*N_TOT + coln] =
                    make_float2(tanhf(acc[i][j][0]), tanhf(acc[i][j][1]));
                *(float2*)&Cout[(size_t)(m0 + i*16 + g + 8)*N_TOT + coln] =
                    make_float2(tanhf(acc[i][j][2]), tanhf(acc[i][j][3]));
            }
    } else {  // EPI 2: matrix = clip(tanh(x)+1,-1,1); out = cap * matrix
#pragma unroll
        for (int i = 0; i < 2; i++) {
            int r0 = m0 + i*16 + g, r1 = r0 + 8;
            int cr0 = (r0/1152)*24 + (r0%24);
            int cr1 = (r1/1152)*24 + (r1%24);
#pragma unroll
            for (int j = 0; j < NT; j++) {
                int coln = n0 + wn0 + j*8 + 2*tig;
                float m00 = fminf(fmaxf(tanhf(acc[i][j][0]) + 1.f, -1.f), 1.f);
                float m01 = fminf(fmaxf(tanhf(acc[i][j][1]) + 1.f, -1.f), 1.f);
                float m10 = fminf(fmaxf(tanhf(acc[i][j][2]) + 1.f, -1.f), 1.f);
                float m11 = fminf(fmaxf(tanhf(acc[i][j][3]) + 1.f, -1.f), 1.f);
                float2 c0 = *(const float2*)&cap[(size_t)cr0*DD + coln];
                float2 c1 = *(const float2*)&cap[(size_t)cr1*DD + coln];
                *(float2*)&Cout[(size_t)r0*N_TOT + coln] = make_float2(c0.x*m00, c0.y*m01);
                *(float2*)&Cout[(size_t)r1*N_TOT + coln] = make_float2(c1.x*m10, c1.y*m11);
            }
        }
    }
}

// ---------------------------------------------------------------------------
// alv kernel (attn + softmax + wctx + sim) — GEMM moved out. Writes raw sim.
// ---------------------------------------------------------------------------
template<int PASS>
__global__ void __launch_bounds__(256) alv_kernel(
        const float* __restrict__ img, const float* __restrict__ cap,
        const int* __restrict__ lens)
{
    extern __shared__ float sm[];
    float* sImg = sm;                    // RR*DD (36864)
    float* sA   = sImg + RR*DD;          // RR*WW raw attn
    float* sAT  = sA + RR*WW;            // WW*RR
    float* sA2  = sAT + WW*RR;           // RR*WW r-major softmaxed
    float* sRed = sA2 + RR*WW;           // WW*8
    float* sFac = sRed + WW*8;           // WW

    const int b = blockIdx.x;
    const int c = b / NN, n = b % NN;
    const int tid = threadIdx.x, lane = tid & 31, wid = tid >> 5;
    const int len = lens[c];

    {
        const float4* gi = (const float4*)(img + (size_t)n * RR * DD);
        float4* si = (float4*)sImg;
        for (int i = tid; i < RR*DD/4; i += 256) si[i] = gi[i];
    }
    __syncthreads();

    // ---- phase 1: raw attn[r][w] = <query_w, img_r> ----
    for (int wi = 0; wi < 3; wi++) {
        int w = wid + wi * 8;
        const float* capp = (PASS == 0) ? (cap + ((size_t)c*WW + w)*DD)
                                        : (g_qm + ((size_t)b*WW + w)*DD);
        float4 cr4[8];
#pragma unroll
        for (int k = 0; k < 8; k++)
            cr4[k] = *(const float4*)(capp + k*128 + lane*4);
        for (int r = 0; r < RR; r += 2) {
            float a0 = 0.f, a1 = 0.f;
#pragma unroll
            for (int k = 0; k < 8; k++) {
                float4 i0 = *(const float4*)(sImg + r*DD + k*128 + lane*4);
                float4 i1 = *(const float4*)(sImg + (r+1)*DD + k*128 + lane*4);
                a0 = fmaf(cr4[k].x, i0.x, a0); a0 = fmaf(cr4[k].y, i0.y, a0);
                a0 = fmaf(cr4[k].z, i0.z, a0); a0 = fmaf(cr4[k].w, i0.w, a0);
                a1 = fmaf(cr4[k].x, i1.x, a1); a1 = fmaf(cr4[k].y, i1.y, a1);
                a1 = fmaf(cr4[k].z, i1.z, a1); a1 = fmaf(cr4[k].w, i1.w, a1);
            }
            a0 = warp_sum(a0); a1 = warp_sum(a1);
            if (lane == 0) { sA[r*WW + w] = a0; sA[(r+1)*WW + w] = a1; }
        }
    }
    __syncthreads();

    // ---- phase 2a: leaky relu, mask, l2norm over words ----
    if (tid < RR) {
        int r = tid;
        float vals[WW];
        float ss = 0.f;
#pragma unroll
        for (int w = 0; w < WW; w++) {
            float v = sA[r*WW + w];
            v = (v >= 0.f) ? v : 0.1f * v;
            if (w >= len) v = 0.f;
            vals[w] = v;
            ss += v * v;
        }
        float f = 1.f / (sqrtf(ss) + 1e-8f);
#pragma unroll
        for (int w = 0; w < WW; w++) sAT[w*RR + r] = vals[w] * f;
    }
    __syncthreads();

    // ---- phase 2b: softmax over regions ----
    if (tid < WW) {
        int w = tid;
        float smo = (PASS == 0) ? 9.f : g_smooth[(size_t)b*WW + w];
        float m = -1e30f;
        for (int r = 0; r < RR; r++) { float v = sAT[w*RR + r]*smo; if (v > m) m = v; }
        float s = 0.f;
        for (int r = 0; r < RR; r++) {
            float e = expf(sAT[w*RR + r]*smo - m);
            sAT[w*RR + r] = e; s += e;
        }
        float inv = 1.f / s;
        for (int r = 0; r < RR; r++) sA2[r*WW + w] = sAT[w*RR + r] * inv;
    }
    __syncthreads();

    // ---- phase 3a: wctx sum-of-squares per word ----
    {
        float psq[WW];
#pragma unroll
        for (int w = 0; w < WW; w++) psq[w] = 0.f;
        for (int cidx = 0; cidx < 4; cidx++) {
            int d = cidx*256 + tid;
            float acc[WW];
#pragma unroll
            for (int w = 0; w < WW; w++) acc[w] = 0.f;
            for (int r = 0; r < RR; r++) {
                float iv = sImg[r*DD + d];
                const float4* ap = (const float4*)(sA2 + r*WW);
#pragma unroll
                for (int q = 0; q < 6; q++) {
                    float4 a4 = ap[q];
                    acc[q*4+0] = fmaf(a4.x, iv, acc[q*4+0]);
                    acc[q*4+1] = fmaf(a4.y, iv, acc[q*4+1]);
                    acc[q*4+2] = fmaf(a4.z, iv, acc[q*4+2]);
                    acc[q*4+3] = fmaf(a4.w, iv, acc[q*4+3]);
                }
            }
#pragma unroll
            for (int w = 0; w < WW; w++) psq[w] = fmaf(acc[w], acc[w], psq[w]);
        }
#pragma unroll
        for (int w = 0; w < WW; w++) {
            float v = warp_sum(psq[w]);
            if (lane == 0) sRed[w*8 + wid] = v;
        }
    }
    __syncthreads();
    if (tid < WW) {
        float s = 0.f;
#pragma unroll
        for (int k = 0; k < 8; k++) s += sRed[tid*8 + k];
        sFac[tid] = 1.f / (sqrtf(s) + 1e-8f);
    }
    __syncthreads();

    // ---- phase 3b: recompute wctx chunk, write sim = (cap - wctx_n)^2 ----
    for (int cidx = 0; cidx < 4; cidx++) {
        int d = cidx*256 + tid;
        float acc[WW];
#pragma unroll
        for (int w = 0; w < WW; w++) acc[w] = 0.f;
        for (int r = 0; r < RR; r++) {
            float iv = sImg[r*DD + d];
            const float4* ap = (const float4*)(sA2 + r*WW);
#pragma unroll
            for (int q = 0; q < 6; q++) {
                float4 a4 = ap[q];
                acc[q*4+0] = fmaf(a4.x, iv, acc[q*4+0]);
                acc[q*4+1] = fmaf(a4.y, iv, acc[q*4+1]);
                acc[q*4+2] = fmaf(a4.z, iv, acc[q*4+2]);
                acc[q*4+3] = fmaf(a4.w, iv, acc[q*4+3]);
            }
        }
#pragma unroll
        for (int w = 0; w < WW; w++) {
            float wc = acc[w] * sFac[w];
            float cv = cap[((size_t)c*WW + w)*DD + d];
            float df = cv - wc;
            g_simbuf[((size_t)b*WW + w)*DD + d] = df * df;
        }
    }
}

// ---------------------------------------------------------------------------
// masked mean over words -> g_higA
// ---------------------------------------------------------------------------
__global__ void mean_kernel(const int* __restrict__ lens)
{
    int b = blockIdx.x;
    int c = b / NN;
    int t = threadIdx.x;
    int len = lens[c];
    float inv = 1.f / (float)len;
    const float* p = g_sim_mid + (size_t)b*WW*SS + t;
    float s = 0.f;
    for (int w = 0; w < len; w++) s += p[(size_t)w * SS];
    g_higA[(size_t)b*SS + t] = s * inv;
}

// ---------------------------------------------------------------------------
// smooth finalize: g_smooth[r] = relu(dot(g_hsm[r], w2) + b2 + 9)
// ---------------------------------------------------------------------------
__global__ void smooth_kernel(const float* __restrict__ w2, const float* __restrict__ b2)
{
    int wid = threadIdx.x >> 5, lane = threadIdx.x & 31;
    size_t r = (size_t)blockIdx.x * 8 + wid;
    const float* h = g_hsm + r * 128;
    float a = 0.f;
#pragma unroll
    for (int k = 0; k < 4; k++) a = fmaf(h[lane + 32*k], w2[lane + 32*k], a);
    a = warp_sum(a);
    if (lane == 0) {
        float v = a + b2[0] + 9.0f;
        g_smooth[r] = v > 0.f ? v : 0.f;
    }
}

// ---------------------------------------------------------------------------
// RAR attention pooling
// ---------------------------------------------------------------------------
__global__ void __launch_bounds__(256) rar_kernel(
        const int* __restrict__ lens,
        const float* __restrict__ qw, const float* __restrict__ qb,
        const float* __restrict__ kw, const float* __restrict__ kb,
        const float* __restrict__ vw, const float* __restrict__ vb,
        int dir)
{
    extern __shared__ float sm[];
    float* sMid = sm;             // WW*SS (6144)
    float* sHig = sMid + WW*SS;   // SS
    float* sHq  = sHig + SS;      // SS
    float* sRed = sHq + SS;       // WW*8
    float* sLog = sRed + WW*8;    // WW
    float* sWgt = sLog + WW;      // WW
    float* sMisc= sWgt + WW;

    const int b = blockIdx.x;
    const int c = b / NN;
    const int tid = threadIdx.x, lane = tid & 31, wid = tid >> 5;
    const int len = lens[c];

    const float* hin = (dir == 0) ? g_higA : g_higB;
    float*       hout= (dir == 0) ? g_higB : g_higA;

    {
        const float4* gm = (const float4*)(g_sim_mid + (size_t)b*WW*SS);
        float4* s4 = (float4*)sMid;
        for (int i = tid; i < WW*SS/4; i += 256) s4[i] = gm[i];
    }
    sHig[tid] = hin[(size_t)b*SS + tid];
    __syncthreads();

    {
        float acc = qb[tid];
        const float* wp = qw + tid;
#pragma unroll 4
        for (int s0 = 0; s0 < SS/4; s0++) {
            float4 h4 = *(const float4*)(sHig + s0*4);
            acc = fmaf(h4.x, wp[(size_t)(s0*4+0)*SS], acc);
            acc = fmaf(h4.y, wp[(size_t)(s0*4+1)*SS], acc);
            acc = fmaf(h4.z, wp[(size_t)(s0*4+2)*SS], acc);
            acc = fmaf(h4.w, wp[(size_t)(s0*4+3)*SS], acc);
        }
        sHq[tid] = tanhf(acc);
    }
    __syncthreads();

    {
        float acck[WW];
#pragma unroll
        for (int w = 0; w < WW; w++) acck[w] = kb[tid];
        const float* wp = kw + tid;
#pragma unroll 2
        for (int s0 = 0; s0 < SS/4; s0++) {
            float w0 = wp[(size_t)(s0*4+0) * SS];
            float w1 = wp[(size_t)(s0*4+1) * SS];
            float w2 = wp[(size_t)(s0*4+2) * SS];
            float w3 = wp[(size_t)(s0*4+3) * SS];
#pragma unroll
            for (int w = 0; w < WW; w++) {
                float4 m4 = *(const float4*)(sMid + w*SS + s0*4);
                acck[w] = fmaf(m4.x, w0, acck[w]);
                acck[w] = fmaf(m4.y, w1, acck[w]);
                acck[w] = fmaf(m4.z, w2, acck[w]);
                acck[w] = fmaf(m4.w, w3, acck[w]);
            }
        }
        float hv = sHq[tid] * vw[tid];
#pragma unroll
        for (int w = 0; w < WW; w++) {
            float pv = warp_sum(tanhf(acck[w]) * hv);
            if (lane == 0) sRed[w*8 + wid] = pv;
        }
    }
    __syncthreads();
    if (tid < WW) {
        float s = 0.f;
#pragma unroll
        for (int k = 0; k < 8; k++) s += sRed[tid*8 + k];
        s += vb[0];
        if (tid >= len) s = -1e30f;
        sLog[tid] = s;
    }
    __syncthreads();
    if (tid == 0) {
        float m = -1e30f;
        for (int w = 0; w < WW; w++) m = fmaxf(m, sLog[w]);
        float s = 0.f;
        for (int w = 0; w < WW; w++) { float e = expf(sLog[w] - m); sWgt[w] = e; s += e; }
        float inv = 1.f / s;
        for (int w = 0; w < WW; w++) sWgt[w] *= inv;
    }
    __syncthreads();

    float o = 0.f;
#pragma unroll
    for (int w = 0; w < WW; w++) o = fmaf(sWgt[w], sMid[w*SS + tid], o);
    float sq = warp_sum(o * o);
    if (lane == 0) sRed[wid] = sq;
    __syncthreads();
    if (tid == 0) {
        float tot = 0.f;
#pragma unroll
        for (int k = 0; k < 8; k++) tot += sRed[k];
        sMisc[0] = 1.f / (sqrtf(tot) + 1e-8f);
    }
    __syncthreads();
    hout[(size_t)b*SS + tid] = o * sMisc[0];
}

// ---------------------------------------------------------------------------
// final: sim = sigmoid(hig @ ew + eb); out[n][c]
// ---------------------------------------------------------------------------
__global__ void final_kernel(const float* __restrict__ ew, const float* __restrict__ eb,
                             float* __restrict__ out)
{
    int gw = (blockIdx.x * blockDim.x + threadIdx.x) >> 5;
    int lane = threadIdx.x & 31;
    int nwarps = (gridDim.x * blockDim.x) >> 5;
    for (int b = gw; b < CC*NN; b += nwarps) {
        const float* h = g_higA + (size_t)b*SS;
        float a = 0.f;
#pragma unroll
        for (int k = 0; k < 8; k++) a = fmaf(h[lane + k*32], ew[lane + k*32], a);
        a = warp_sum(a);
        if (lane == 0) {
            float v = a + eb[0];
            int c = b / NN, n = b % NN;
            out[n*CC + c] = 1.f / (1.f + expf(-v));
        }
    }
}

// ---------------------------------------------------------------------------
extern "C" void kernel_launch(void* const* d_in, const int* in_sizes, int n_in,
                              void* d_out, int out_size)
{
    const float* img  = (const float*)d_in[0];
    const float* cap  = (const float*)d_in[1];
    const int*   lens = (const int*)  d_in[2];
    const float* alvw = (const float*)d_in[3];
    const float* alvb = (const float*)d_in[4];
    const float* qw   = (const float*)d_in[5];
    const float* qb   = (const float*)d_in[6];
    const float* kw   = (const float*)d_in[7];
    const float* kb   = (const float*)d_in[8];
    const float* vw   = (const float*)d_in[9];
    const float* vb   = (const float*)d_in[10];
    const float* smw1 = (const float*)d_in[11];
    const float* smb1 = (const float*)d_in[12];
    const float* smw2 = (const float*)d_in[13];
    const float* smb2 = (const float*)d_in[14];
    const float* mxw1 = (const float*)d_in[15];
    const float* mxb1 = (const float*)d_in[16];
    const float* mxw2 = (const float*)d_in[17];
    const float* mxb2 = (const float*)d_in[18];
    const float* ew   = (const float*)d_in[19];
    const float* eb   = (const float*)d_in[20];
    float* out = (float*)d_out;

    float *pSim, *pMid, *pH, *pHsm, *pQm;
    cudaGetSymbolAddress((void**)&pSim, g_simbuf);
    cudaGetSymbolAddress((void**)&pMid, g_sim_mid);
    cudaGetSymbolAddress((void**)&pH,   g_h);
    cudaGetSymbolAddress((void**)&pHsm, g_hsm);
    cudaGetSymbolAddress((void**)&pQm,  g_qm);

    const size_t ALV_SMEM = (size_t)(RR*DD + RR*WW*3 + WW*8 + WW + 16) * sizeof(float);
    const size_t RAR_SMEM = (size_t)(WW*SS + SS + SS + WW*8 + WW + WW + 32) * sizeof(float);
    const size_t SMG256 = (size_t)(2*32*36 + 2*32*264) * 4 + (32*8 + 32) * 4;  // 77952
    const size_t SMG128 = (size_t)(2*32*36 + 2*32*136) * 4 + (32*8 + 32) * 4;  // 45184

    cudaFuncSetAttribute(alv_kernel<0>, cudaFuncAttributeMaxDynamicSharedMemorySize, (int)ALV_SMEM);
    cudaFuncSetAttribute(alv_kernel<1>, cudaFuncAttributeMaxDynamicSharedMemorySize, (int)ALV_SMEM);
    cudaFuncSetAttribute(gemm_kernel<256,1024,256,0>, cudaFuncAttributeMaxDynamicSharedMemorySize, (int)SMG256);
    cudaFuncSetAttribute(gemm_kernel<128,256,512,1>,  cudaFuncAttributeMaxDynamicSharedMemorySize, (int)SMG128);
    cudaFuncSetAttribute(gemm_kernel<128,256,128,1>,  cudaFuncAttributeMaxDynamicSharedMemorySize, (int)SMG128);
    cudaFuncSetAttribute(gemm_kernel<128,512,1024,2>, cudaFuncAttributeMaxDynamicSharedMemorySize, (int)SMG128);

    const int B = CC * NN;
    const int MB = MTOT / 32;  // 1728

    // ---- pass 0 ----
    alv_kernel<0><<<B, 256, ALV_SMEM>>>(img, cap, lens);
    gemm_kernel<256,1024,256,0><<<dim3(MB,1), 256, SMG256>>>(pSim, alvw, alvb, pMid, nullptr);
    mean_kernel<<<B, 256>>>(lens);
    gemm_kernel<128,256,512,1><<<dim3(MB,4), 256, SMG128>>>(pMid, mxw1, mxb1, pH, nullptr);
    gemm_kernel<128,256,128,1><<<dim3(MB,1), 256, SMG128>>>(pMid, smw1, smb1, pHsm, nullptr);
    smooth_kernel<<<MTOT/8, 256>>>(smw2, smb2);
    gemm_kernel<128,512,1024,2><<<dim3(MB,8), 256, SMG128>>>(pH, mxw2, mxb2, pQm, cap);
    rar_kernel<<<B, 256, RAR_SMEM>>>(lens, qw, qb, kw, kb, vw, vb, 0);

    // ---- pass 1 ----
    alv_kernel<1><<<B, 256, ALV_SMEM>>>(img, cap, lens);
    gemm_kernel<256,1024,256,0><<<dim3(MB,1), 256, SMG256>>>(pSim, alvw + (size_t)DD*SS, alvb + SS, pMid, nullptr);
    rar_kernel<<<B, 256, RAR_SMEM>>>(lens, qw + SS*SS, qb + SS, kw + SS*SS, kb + SS,
                                     vw + SS, vb + 1, 1);

    final_kernel<<<9, 256>>>(ew, eb, out);
}

// round 5
// speedup vs baseline: 4.5959x; 2.3564x over previous
#include <cuda_runtime.h>
#include <cuda_bf16.h>
#include <math.h>
#include <stdint.h>

#define CC 48
#define NN 48
#define WW 24
#define RR 36
#define DD 1024
#define SS 256
#define MTOT (CC*NN*WW)   // 55296

// ---------------- scratch (device globals; no allocation allowed) ----------
__device__ __align__(16) float g_sim_mid[MTOT*SS];          // 56.6 MB
__device__ __align__(16) float g_smooth[MTOT];
__device__ __align__(16) float g_qm[(size_t)MTOT*DD];       // 226 MB
__device__ __align__(16) float g_wc[(size_t)MTOT*DD];       // 226 MB (unnormalized wctx)
__device__ __align__(16) float g_fac[MTOT];
__device__ __align__(16) __nv_bfloat16 g_h[(size_t)MTOT*512];   // 56 MB
__device__ __align__(16) __nv_bfloat16 g_hsm[(size_t)MTOT*128]; // 14 MB
__device__ __align__(16) __nv_bfloat16 g_wbf[1212416];          // all weights bf16
__device__ __align__(16) float g_higA[CC*NN*SS];
__device__ __align__(16) float g_higB[CC*NN*SS];

// weight offsets inside g_wbf
#define OFF_ALV0 0
#define OFF_ALV1 262144
#define OFF_MX1  524288
#define OFF_SM1  655360
#define OFF_MX2  688128

__device__ __forceinline__ float warp_sum(float v) {
#pragma unroll
    for (int o = 16; o; o >>= 1) v += __shfl_xor_sync(0xffffffffu, v, o);
    return v;
}
__device__ __forceinline__ uint32_t f2bf2(float lo, float hi) {
    uint32_t r; asm("cvt.rn.bf16x2.f32 %0, %1, %2;" : "=r"(r) : "f"(hi), "f"(lo)); return r;
}
__device__ __forceinline__ void ldsm4(uint32_t* r, uint32_t a) {
    asm volatile("ldmatrix.sync.aligned.m8n8.x4.shared.b16 {%0,%1,%2,%3},[%4];"
        : "=r"(r[0]),"=r"(r[1]),"=r"(r[2]),"=r"(r[3]) : "r"(a));
}
__device__ __forceinline__ void ldsm4t(uint32_t* r, uint32_t a) {
    asm volatile("ldmatrix.sync.aligned.m8n8.x4.trans.shared.b16 {%0,%1,%2,%3},[%4];"
        : "=r"(r[0]),"=r"(r[1]),"=r"(r[2]),"=r"(r[3]) : "r"(a));
}
__device__ __forceinline__ void mmabf(float* d, const uint32_t* a, const uint32_t* b) {
    asm volatile("mma.sync.aligned.m16n8k16.row.col.f32.bf16.bf16.f32 "
        "{%0,%1,%2,%3},{%4,%5,%6,%7},{%8,%9},{%0,%1,%2,%3};"
        : "+f"(d[0]),"+f"(d[1]),"+f"(d[2]),"+f"(d[3])
        : "r"(a[0]),"r"(a[1]),"r"(a[2]),"r"(a[3]),"r"(b[0]),"r"(b[1]));
}

// ---------------------------------------------------------------------------
// weight fp32 -> bf16 convert
// ---------------------------------------------------------------------------
__global__ void cvtw_kernel(const float* __restrict__ src, __nv_bfloat16* __restrict__ dst, int n4)
{
    int i = blockIdx.x * blockDim.x + threadIdx.x;
    if (i < n4) {
        float4 v = *(const float4*)(src + (size_t)i*4);
        uint2 o; o.x = f2bf2(v.x, v.y); o.y = f2bf2(v.z, v.w);
        *(uint2*)(dst + (size_t)i*4) = o;
    }
}

// ---------------------------------------------------------------------------
// bf16 m16n8k16 GEMM. M_BLK in {32,64}. 8 warps split N (N_BLK/8 each).
// AMODE 0: A fp32 -> cvt.  AMODE 1: A = (cap - wc*fac)^2 (alv sim fusion).
// AMODE 2: A bf16 direct.
// EPI 0: +bias, l2norm over full 256 row (needs M_BLK=32, N_BLK=N_TOT=256)
// EPI 1: +bias, tanh (OUTBF: bf16 out)
// EPI 2: +bias, tanh, clip(+1), * cap row -> fp32 out
// ---------------------------------------------------------------------------
template<int M_BLK,int N_BLK,int K_DIM,int N_TOT,int AMODE,int EPI,int OUTBF>
__global__ void __launch_bounds__(256) gemm_bf16(
    const float* __restrict__ Af, const __nv_bfloat16* __restrict__ Ab,
    const __nv_bfloat16* __restrict__ Bw, const float* __restrict__ bias,
    float* __restrict__ Cf, __nv_bfloat16* __restrict__ Cb,
    const float* __restrict__ cap, const float* __restrict__ fac)
{
    constexpr int MT   = M_BLK/16;
    constexpr int NT   = N_BLK/64;
    constexpr int SAW  = 20;                // words per A smem row (32 bf16 + pad)
    constexpr int SBW  = N_BLK/2 + 4;       // words per B smem row
    constexpr int ABUF = M_BLK*SAW;
    constexpr int BBUF = 32*SBW;
    constexpr int APASS = M_BLK/32;
    constexpr int BROWP = 2048/N_BLK;       // B rows per load pass
    constexpr int BPASS = 32/BROWP;
    constexpr int KT   = K_DIM/32;

    extern __shared__ uint32_t dsm[];
    uint32_t* As = dsm;
    uint32_t* Bs = dsm + 2*ABUF;
    float* sRed  = (float*)(dsm + 2*ABUF + 2*BBUF);
    float* sFacR = sRed + 32*8;

    const int m0 = blockIdx.x * M_BLK;
    const int n0 = blockIdx.y * N_BLK;
    const int tid = threadIdx.x, lane = tid & 31, wid = tid >> 5;
    const int g = lane >> 2, tig = lane & 3;
    const int wn0 = wid * (N_BLK/8);

    const int a_row = tid >> 3, a_c = (tid & 7) * 4;
    float facr[APASS]; int caprow[APASS];
    if (AMODE == 1) {
#pragma unroll
        for (int p = 0; p < APASS; p++) {
            int r = m0 + p*32 + a_row;
            facr[p] = fac[r];
            caprow[p] = (r/1152)*24 + (r%24);
        }
    }
    const int b_row = tid / (N_BLK/8), b_c = (tid % (N_BLK/8)) * 8;
    const __nv_bfloat16* Bptr = Bw + (size_t)b_row*N_TOT + n0 + b_c;

    uint32_t areg[2*APASS]; uint4 breg[BPASS];

    auto loadA = [&](int kt) {
#pragma unroll
        for (int p = 0; p < APASS; p++) {
            int r = m0 + p*32 + a_row;
            if (AMODE == 2) {
                uint2 v = *(const uint2*)(Ab + (size_t)r*K_DIM + kt*32 + a_c);
                areg[p*2] = v.x; areg[p*2+1] = v.y;
            } else if (AMODE == 0) {
                float4 v = *(const float4*)(Af + (size_t)r*K_DIM + kt*32 + a_c);
                areg[p*2]   = f2bf2(v.x, v.y);
                areg[p*2+1] = f2bf2(v.z, v.w);
            } else {
                float4 wv = *(const float4*)(Af + (size_t)r*K_DIM + kt*32 + a_c);
                float4 cv = *(const float4*)(cap + (size_t)caprow[p]*K_DIM + kt*32 + a_c);
                float f = facr[p];
                float s0 = cv.x - wv.x*f; s0 *= s0;
                float s1 = cv.y - wv.y*f; s1 *= s1;
                float s2 = cv.z - wv.z*f; s2 *= s2;
                float s3 = cv.w - wv.w*f; s3 *= s3;
                areg[p*2]   = f2bf2(s0, s1);
                areg[p*2+1] = f2bf2(s2, s3);
            }
        }
    };
    auto stsA = [&](int buf) {
#pragma unroll
        for (int p = 0; p < APASS; p++)
            *(uint2*)(As + buf*ABUF + (p*32 + a_row)*SAW + (tid&7)*2) =
                make_uint2(areg[p*2], areg[p*2+1]);
    };
    auto loadB = [&](int kt) {
#pragma unroll
        for (int p = 0; p < BPASS; p++)
            breg[p] = *(const uint4*)(Bptr + (size_t)(kt*32 + p*BROWP)*N_TOT);
    };
    auto stsB = [&](int buf) {
#pragma unroll
        for (int p = 0; p < BPASS; p++)
            *(uint4*)(Bs + buf*BBUF + (b_row + p*BROWP)*SBW + (tid % (N_BLK/8))*4) = breg[p];
    };

    loadA(0); loadB(0);
    stsA(0);  stsB(0);
    __syncthreads();

    float acc[MT][NT][4];
#pragma unroll
    for (int i = 0; i < MT; i++)
#pragma unroll
        for (int j = 0; j < NT; j++)
#pragma unroll
            for (int k = 0; k < 4; k++) acc[i][j][k] = 0.f;

    uint32_t smA = (uint32_t)__cvta_generic_to_shared(As);
    uint32_t smB = (uint32_t)__cvta_generic_to_shared(Bs);
    const uint32_t aoff = (lane & 15)*(SAW*4) + (lane >> 4)*16;
    const uint32_t boff = ((lane & 7) + ((lane >> 3) & 1)*8)*(SBW*4)
                        + (wn0 + (lane >> 4)*8)*2;

    for (int kt = 0; kt < KT; kt++) {
        int cur = kt & 1;
        if (kt + 1 < KT) { loadA(kt+1); loadB(kt+1); }
        uint32_t Ab0 = smA + cur*(ABUF*4);
        uint32_t Bb0 = smB + cur*(BBUF*4);
#pragma unroll
        for (int ks = 0; ks < 2; ks++) {
            uint32_t af[MT][4], bf[NT][2];
#pragma unroll
            for (int i = 0; i < MT; i++)
                ldsm4(af[i], Ab0 + i*16*(SAW*4) + aoff + ks*32);
#pragma unroll
            for (int jp = 0; jp < NT/2; jp++) {
                uint32_t t[4];
                ldsm4t(t, Bb0 + ks*16*(SBW*4) + boff + jp*32);
                bf[2*jp][0] = t[0]; bf[2*jp][1] = t[1];
                bf[2*jp+1][0] = t[2]; bf[2*jp+1][1] = t[3];
            }
#pragma unroll
            for (int i = 0; i < MT; i++)
#pragma unroll
                for (int j = 0; j < NT; j++)
                    mmabf(acc[i][j], af[i], bf[j]);
        }
        if (kt + 1 < KT) { stsA((kt+1)&1); stsB((kt+1)&1); }
        __syncthreads();
    }

    // bias
#pragma unroll
    for (int j = 0; j < NT; j++) {
        int coln = n0 + wn0 + j*8 + 2*tig;
        float b0 = bias[coln], b1 = bias[coln+1];
#pragma unroll
        for (int i = 0; i < MT; i++) {
            acc[i][j][0] += b0; acc[i][j][1] += b1;
            acc[i][j][2] += b0; acc[i][j][3] += b1;
        }
    }

    if (EPI == 0) {
        // l2norm over full 256-wide row (MT==2)
        float ps[2][2];
#pragma unroll
        for (int i = 0; i < 2; i++) {
            ps[i][0] = 0.f; ps[i][1] = 0.f;
#pragma unroll
            for (int j = 0; j < NT; j++) {
                ps[i][0] += acc[i][j][0]*acc[i][j][0] + acc[i][j][1]*acc[i][j][1];
                ps[i][1] += acc[i][j][2]*acc[i][j][2] + acc[i][j][3]*acc[i][j][3];
            }
        }
#pragma unroll
        for (int i = 0; i < 2; i++)
#pragma unroll
            for (int h = 0; h < 2; h++) {
                ps[i][h] += __shfl_xor_sync(0xffffffffu, ps[i][h], 1);
                ps[i][h] += __shfl_xor_sync(0xffffffffu, ps[i][h], 2);
            }
        if (tig == 0) {
#pragma unroll
            for (int i = 0; i < 2; i++) {
                sRed[(i*16 + g    )*8 + wid] = ps[i][0];
                sRed[(i*16 + g + 8)*8 + wid] = ps[i][1];
            }
        }
        __syncthreads();
        if (tid < 32) {
            float s = 0.f;
#pragma unroll
            for (int k = 0; k < 8; k++) s += sRed[tid*8 + k];
            sFacR[tid] = 1.f / (sqrtf(s) + 1e-8f);
        }
        __syncthreads();
#pragma unroll
        for (int i = 0; i < 2; i++) {
            float f0 = sFacR[i*16 + g], f1 = sFacR[i*16 + g + 8];
#pragma unroll
            for (int j = 0; j < NT; j++) {
                int coln = wn0 + j*8 + 2*tig;
                *(float2*)&Cf[(size_t)(m0 + i*16 + g    )*N_TOT + coln] =
                    make_float2(acc[i][j][0]*f0, acc[i][j][1]*f0);
                *(float2*)&Cf[(size_t)(m0 + i*16 + g + 8)*N_TOT + coln] =
                    make_float2(acc[i][j][2]*f1, acc[i][j][3]*f1);
            }
        }
    } else if (EPI == 1) {
#pragma unroll
        for (int i = 0; i < MT; i++) {
            int r0 = m0 + i*16 + g, r1 = r0 + 8;
#pragma unroll
            for (int j = 0; j < NT; j++) {
                int coln = n0 + wn0 + j*8 + 2*tig;
                float v0 = tanhf(acc[i][j][0]), v1 = tanhf(acc[i][j][1]);
                float v2 = tanhf(acc[i][j][2]), v3 = tanhf(acc[i][j][3]);
                if (OUTBF) {
                    *(uint32_t*)&Cb[(size_t)r0*N_TOT + coln] = f2bf2(v0, v1);
                    *(uint32_t*)&Cb[(size_t)r1*N_TOT + coln] = f2bf2(v2, v3);
                } else {
                    *(float2*)&Cf[(size_t)r0*N_TOT + coln] = make_float2(v0, v1);
                    *(float2*)&Cf[(size_t)r1*N_TOT + coln] = make_float2(v2, v3);
                }
            }
        }
    } else {  // EPI 2
#pragma unroll
        for (int i = 0; i < MT; i++) {
            int r0 = m0 + i*16 + g, r1 = r0 + 8;
            int cr0 = (r0/1152)*24 + (r0%24);
            int cr1 = (r1/1152)*24 + (r1%24);
#pragma unroll
            for (int j = 0; j < NT; j++) {
                int coln = n0 + wn0 + j*8 + 2*tig;
                float m00 = fminf(fmaxf(tanhf(acc[i][j][0]) + 1.f, -1.f), 1.f);
                float m01 = fminf(fmaxf(tanhf(acc[i][j][1]) + 1.f, -1.f), 1.f);
                float m10 = fminf(fmaxf(tanhf(acc[i][j][2]) + 1.f, -1.f), 1.f);
                float m11 = fminf(fmaxf(tanhf(acc[i][j][3]) + 1.f, -1.f), 1.f);
                float2 c0 = *(const float2*)&cap[(size_t)cr0*DD + coln];
                float2 c1 = *(const float2*)&cap[(size_t)cr1*DD + coln];
                *(float2*)&Cf[(size_t)r0*N_TOT + coln] = make_float2(c0.x*m00, c0.y*m01);
                *(float2*)&Cf[(size_t)r1*N_TOT + coln] = make_float2(c1.x*m10, c1.y*m11);
            }
        }
    }
}

// ---------------------------------------------------------------------------
// alv kernel: attn + softmax + wctx. Writes unnormalized wctx + fac.
// ---------------------------------------------------------------------------
template<int PASS>
__global__ void __launch_bounds__(256) alv_kernel(
        const float* __restrict__ img, const float* __restrict__ cap,
        const int* __restrict__ lens)
{
    extern __shared__ float sm[];
    float* sImg = sm;                    // RR*DD
    float* sA   = sImg + RR*DD;          // RR*WW
    float* sAT  = sA + RR*WW;            // WW*RR
    float* sA2  = sAT + WW*RR;           // RR*WW
    float* sRed = sA2 + RR*WW;           // WW*8

    const int b = blockIdx.x;
    const int c = b / NN, n = b % NN;
    const int tid = threadIdx.x, lane = tid & 31, wid = tid >> 5;
    const int len = lens[c];

    {
        const float4* gi = (const float4*)(img + (size_t)n * RR * DD);
        float4* si = (float4*)sImg;
        for (int i = tid; i < RR*DD/4; i += 256) si[i] = gi[i];
    }
    __syncthreads();

    // phase 1: attn[r][w] = <query_w, img_r>
    for (int wi = 0; wi < 3; wi++) {
        int w = wid + wi * 8;
        const float* capp = (PASS == 0) ? (cap + ((size_t)c*WW + w)*DD)
                                        : (g_qm + ((size_t)b*WW + w)*DD);
        float4 cr4[8];
#pragma unroll
        for (int k = 0; k < 8; k++)
            cr4[k] = *(const float4*)(capp + k*128 + lane*4);
        for (int r = 0; r < RR; r += 2) {
            float a0 = 0.f, a1 = 0.f;
#pragma unroll
            for (int k = 0; k < 8; k++) {
                float4 i0 = *(const float4*)(sImg + r*DD + k*128 + lane*4);
                float4 i1 = *(const float4*)(sImg + (r+1)*DD + k*128 + lane*4);
                a0 = fmaf(cr4[k].x, i0.x, a0); a0 = fmaf(cr4[k].y, i0.y, a0);
                a0 = fmaf(cr4[k].z, i0.z, a0); a0 = fmaf(cr4[k].w, i0.w, a0);
                a1 = fmaf(cr4[k].x, i1.x, a1); a1 = fmaf(cr4[k].y, i1.y, a1);
                a1 = fmaf(cr4[k].z, i1.z, a1); a1 = fmaf(cr4[k].w, i1.w, a1);
            }
            a0 = warp_sum(a0); a1 = warp_sum(a1);
            if (lane == 0) { sA[r*WW + w] = a0; sA[(r+1)*WW + w] = a1; }
        }
    }
    __syncthreads();

    // phase 2a: leaky relu, mask, l2norm over words
    if (tid < RR) {
        int r = tid;
        float vals[WW];
        float ss = 0.f;
#pragma unroll
        for (int w = 0; w < WW; w++) {
            float v = sA[r*WW + w];
            v = (v >= 0.f) ? v : 0.1f * v;
            if (w >= len) v = 0.f;
            vals[w] = v;
            ss += v * v;
        }
        float f = 1.f / (sqrtf(ss) + 1e-8f);
#pragma unroll
        for (int w = 0; w < WW; w++) sAT[w*RR + r] = vals[w] * f;
    }
    __syncthreads();

    // phase 2b: softmax over regions
    if (tid < WW) {
        int w = tid;
        float smo = (PASS == 0) ? 9.f : g_smooth[(size_t)b*WW + w];
        float m = -1e30f;
        for (int r = 0; r < RR; r++) { float v = sAT[w*RR + r]*smo; if (v > m) m = v; }
        float s = 0.f;
        for (int r = 0; r < RR; r++) {
            float e = expf(sAT[w*RR + r]*smo - m);
            sAT[w*RR + r] = e; s += e;
        }
        float inv = 1.f / s;
        for (int r = 0; r < RR; r++) sA2[r*WW + w] = sAT[w*RR + r] * inv;
    }
    __syncthreads();

    // phase 3: wctx, write unnormalized wc + sumsq
    {
        float psq[WW];
#pragma unroll
        for (int w = 0; w < WW; w++) psq[w] = 0.f;
        for (int cidx = 0; cidx < 4; cidx++) {
            int d = cidx*256 + tid;
            float acc[WW];
#pragma unroll
            for (int w = 0; w < WW; w++) acc[w] = 0.f;
            for (int r = 0; r < RR; r++) {
                float iv = sImg[r*DD + d];
                const float4* ap = (const float4*)(sA2 + r*WW);
#pragma unroll
                for (int q = 0; q < 6; q++) {
                    float4 a4 = ap[q];
                    acc[q*4+0] = fmaf(a4.x, iv, acc[q*4+0]);
                    acc[q*4+1] = fmaf(a4.y, iv, acc[q*4+1]);
                    acc[q*4+2] = fmaf(a4.z, iv, acc[q*4+2]);
                    acc[q*4+3] = fmaf(a4.w, iv, acc[q*4+3]);
                }
            }
#pragma unroll
            for (int w = 0; w < WW; w++) {
                psq[w] = fmaf(acc[w], acc[w], psq[w]);
                g_wc[((size_t)b*WW + w)*DD + d] = acc[w];
            }
        }
#pragma unroll
        for (int w = 0; w < WW; w++) {
            float v = warp_sum(psq[w]);
            if (lane == 0) sRed[w*8 + wid] = v;
        }
    }
    __syncthreads();
    if (tid < WW) {
        float s = 0.f;
#pragma unroll
        for (int k = 0; k < 8; k++) s += sRed[tid*8 + k];
        g_fac[(size_t)b*WW + tid] = 1.f / (sqrtf(s) + 1e-8f);
    }
}

// ---------------------------------------------------------------------------
__global__ void mean_kernel(const int* __restrict__ lens)
{
    int b = blockIdx.x;
    int c = b / NN;
    int t = threadIdx.x;
    int len = lens[c];
    float inv = 1.f / (float)len;
    const float* p = g_sim_mid + (size_t)b*WW*SS + t;
    float s = 0.f;
    for (int w = 0; w < len; w++) s += p[(size_t)w * SS];
    g_higA[(size_t)b*SS + t] = s * inv;
}

__global__ void smooth_kernel(const float* __restrict__ w2, const float* __restrict__ b2)
{
    int wid = threadIdx.x >> 5, lane = threadIdx.x & 31;
    size_t r = (size_t)blockIdx.x * 8 + wid;
    const __nv_bfloat16* h = g_hsm + r * 128;
    float a = 0.f;
#pragma unroll
    for (int k = 0; k < 4; k++)
        a = fmaf(__bfloat162float(h[lane + 32*k]), w2[lane + 32*k], a);
    a = warp_sum(a);
    if (lane == 0) {
        float v = a + b2[0] + 9.0f;
        g_smooth[r] = v > 0.f ? v : 0.f;
    }
}

// ---------------------------------------------------------------------------
__global__ void __launch_bounds__(256) rar_kernel(
        const int* __restrict__ lens,
        const float* __restrict__ qw, const float* __restrict__ qb,
        const float* __restrict__ kw, const float* __restrict__ kb,
        const float* __restrict__ vw, const float* __restrict__ vb,
        int dir)
{
    extern __shared__ float sm[];
    float* sMid = sm;
    float* sHig = sMid + WW*SS;
    float* sHq  = sHig + SS;
    float* sRed = sHq + SS;
    float* sLog = sRed + WW*8;
    float* sWgt = sLog + WW;
    float* sMisc= sWgt + WW;

    const int b = blockIdx.x;
    const int c = b / NN;
    const int tid = threadIdx.x, lane = tid & 31, wid = tid >> 5;
    const int len = lens[c];

    const float* hin = (dir == 0) ? g_higA : g_higB;
    float*       hout= (dir == 0) ? g_higB : g_higA;

    {
        const float4* gm = (const float4*)(g_sim_mid + (size_t)b*WW*SS);
        float4* s4 = (float4*)sMid;
        for (int i = tid; i < WW*SS/4; i += 256) s4[i] = gm[i];
    }
    sHig[tid] = hin[(size_t)b*SS + tid];
    __syncthreads();

    {
        float acc = qb[tid];
        const float* wp = qw + tid;
#pragma unroll 4
        for (int s0 = 0; s0 < SS/4; s0++) {
            float4 h4 = *(const float4*)(sHig + s0*4);
            acc = fmaf(h4.x, wp[(size_t)(s0*4+0)*SS], acc);
            acc = fmaf(h4.y, wp[(size_t)(s0*4+1)*SS], acc);
            acc = fmaf(h4.z, wp[(size_t)(s0*4+2)*SS], acc);
            acc = fmaf(h4.w, wp[(size_t)(s0*4+3)*SS], acc);
        }
        sHq[tid] = tanhf(acc);
    }
    __syncthreads();

    {
        float acck[WW];
#pragma unroll
        for (int w = 0; w < WW; w++) acck[w] = kb[tid];
        const float* wp = kw + tid;
#pragma unroll 2
        for (int s0 = 0; s0 < SS/4; s0++) {
            float w0 = wp[(size_t)(s0*4+0) * SS];
            float w1 = wp[(size_t)(s0*4+1) * SS];
            float w2 = wp[(size_t)(s0*4+2) * SS];
            float w3 = wp[(size_t)(s0*4+3) * SS];
#pragma unroll
            for (int w = 0; w < WW; w++) {
                float4 m4 = *(const float4*)(sMid + w*SS + s0*4);
                acck[w] = fmaf(m4.x, w0, acck[w]);
                acck[w] = fmaf(m4.y, w1, acck[w]);
                acck[w] = fmaf(m4.z, w2, acck[w]);
                acck[w] = fmaf(m4.w, w3, acck[w]);
            }
        }
        float hv = sHq[tid] * vw[tid];
#pragma unroll
        for (int w = 0; w < WW; w++) {
            float pv = warp_sum(tanhf(acck[w]) * hv);
            if (lane == 0) sRed[w*8 + wid] = pv;
        }
    }
    __syncthreads();
    if (tid < WW) {
        float s = 0.f;
#pragma unroll
        for (int k = 0; k < 8; k++) s += sRed[tid*8 + k];
        s += vb[0];
        if (tid >= len) s = -1e30f;
        sLog[tid] = s;
    }
    __syncthreads();
    if (tid == 0) {
        float m = -1e30f;
        for (int w = 0; w < WW; w++) m = fmaxf(m, sLog[w]);
        float s = 0.f;
        for (int w = 0; w < WW; w++) { float e = expf(sLog[w] - m); sWgt[w] = e; s += e; }
        float inv = 1.f / s;
        for (int w = 0; w < WW; w++) sWgt[w] *= inv;
    }
    __syncthreads();

    float o = 0.f;
#pragma unroll
    for (int w = 0; w < WW; w++) o = fmaf(sWgt[w], sMid[w*SS + tid], o);
    float sq = warp_sum(o * o);
    if (lane == 0) sRed[wid] = sq;
    __syncthreads();
    if (tid == 0) {
        float tot = 0.f;
#pragma unroll
        for (int k = 0; k < 8; k++) tot += sRed[k];
        sMisc[0] = 1.f / (sqrtf(tot) + 1e-8f);
    }
    __syncthreads();
    hout[(size_t)b*SS + tid] = o * sMisc[0];
}

// ---------------------------------------------------------------------------
__global__ void final_kernel(const float* __restrict__ ew, const float* __restrict__ eb,
                             float* __restrict__ out)
{
    int gw = (blockIdx.x * blockDim.x + threadIdx.x) >> 5;
    int lane = threadIdx.x & 31;
    int nwarps = (gridDim.x * blockDim.x) >> 5;
    for (int b = gw; b < CC*NN; b += nwarps) {
        const float* h = g_higA + (size_t)b*SS;
        float a = 0.f;
#pragma unroll
        for (int k = 0; k < 8; k++) a = fmaf(h[lane + k*32], ew[lane + k*32], a);
        a = warp_sum(a);
        if (lane == 0) {
            float v = a + eb[0];
            int c = b / NN, n = b % NN;
            out[n*CC + c] = 1.f / (1.f + expf(-v));
        }
    }
}

// ---------------------------------------------------------------------------
extern "C" void kernel_launch(void* const* d_in, const int* in_sizes, int n_in,
                              void* d_out, int out_size)
{
    const float* img  = (const float*)d_in[0];
    const float* cap  = (const float*)d_in[1];
    const int*   lens = (const int*)  d_in[2];
    const float* alvw = (const float*)d_in[3];
    const float* alvb = (const float*)d_in[4];
    const float* qw   = (const float*)d_in[5];
    const float* qb   = (const float*)d_in[6];
    const float* kw   = (const float*)d_in[7];
    const float* kb   = (const float*)d_in[8];
    const float* vw   = (const float*)d_in[9];
    const float* vb   = (const float*)d_in[10];
    const float* smw1 = (const float*)d_in[11];
    const float* smb1 = (const float*)d_in[12];
    const float* smw2 = (const float*)d_in[13];
    const float* smb2 = (const float*)d_in[14];
    const float* mxw1 = (const float*)d_in[15];
    const float* mxb1 = (const float*)d_in[16];
    const float* mxw2 = (const float*)d_in[17];
    const float* mxb2 = (const float*)d_in[18];
    const float* ew   = (const float*)d_in[19];
    const float* eb   = (const float*)d_in[20];
    float* out = (float*)d_out;

    float *pMid, *pQm, *pWc, *pFac;
    __nv_bfloat16 *pH, *pHsm, *pWbf;
    cudaGetSymbolAddress((void**)&pMid, g_sim_mid);
    cudaGetSymbolAddress((void**)&pQm,  g_qm);
    cudaGetSymbolAddress((void**)&pWc,  g_wc);
    cudaGetSymbolAddress((void**)&pFac, g_fac);
    cudaGetSymbolAddress((void**)&pH,   g_h);
    cudaGetSymbolAddress((void**)&pHsm, g_hsm);
    cudaGetSymbolAddress((void**)&pWbf, g_wbf);

    const size_t ALV_SMEM = (size_t)(RR*DD + RR*WW*3 + WW*8 + 16) * sizeof(float);
    const size_t RAR_SMEM = (size_t)(WW*SS + SS + SS + WW*8 + WW + WW + 32) * sizeof(float);
    const size_t SM_ALVG = (size_t)(2*32*20 + 2*32*132)*4 + (32*8 + 32)*4;   // 40064
    const size_t SM_MLP  = (size_t)(2*64*20 + 2*32*68)*4 + (32*8 + 32)*4;    // 28800

    cudaFuncSetAttribute(alv_kernel<0>, cudaFuncAttributeMaxDynamicSharedMemorySize, (int)ALV_SMEM);
    cudaFuncSetAttribute(alv_kernel<1>, cudaFuncAttributeMaxDynamicSharedMemorySize, (int)ALV_SMEM);
    cudaFuncSetAttribute(gemm_bf16<32,256,1024,256,1,0,0>, cudaFuncAttributeMaxDynamicSharedMemorySize, (int)SM_ALVG);
    cudaFuncSetAttribute(gemm_bf16<64,128,256,512,0,1,1>,  cudaFuncAttributeMaxDynamicSharedMemorySize, (int)SM_MLP);
    cudaFuncSetAttribute(gemm_bf16<64,128,256,128,0,1,1>,  cudaFuncAttributeMaxDynamicSharedMemorySize, (int)SM_MLP);
    cudaFuncSetAttribute(gemm_bf16<64,128,512,1024,2,2,0>, cudaFuncAttributeMaxDynamicSharedMemorySize, (int)SM_MLP);

    const int B = CC * NN;

    // weight conversion (cheap; runs every launch for determinism)
    cvtw_kernel<<<(524288/4+255)/256, 256>>>(alvw, pWbf + OFF_ALV0, 524288/4);
    cvtw_kernel<<<(131072/4+255)/256, 256>>>(mxw1, pWbf + OFF_MX1, 131072/4);
    cvtw_kernel<<<(32768/4+255)/256, 256>>>(smw1, pWbf + OFF_SM1, 32768/4);
    cvtw_kernel<<<(524288/4+255)/256, 256>>>(mxw2, pWbf + OFF_MX2, 524288/4);

    // ---- pass 0 ----
    alv_kernel<0><<<B, 256, ALV_SMEM>>>(img, cap, lens);
    gemm_bf16<32,256,1024,256,1,0,0><<<dim3(MTOT/32,1), 256, SM_ALVG>>>(
        pWc, nullptr, pWbf + OFF_ALV0, alvb, pMid, nullptr, cap, pFac);
    mean_kernel<<<B, 256>>>(lens);
    gemm_bf16<64,128,256,512,0,1,1><<<dim3(MTOT/64,4), 256, SM_MLP>>>(
        pMid, nullptr, pWbf + OFF_MX1, mxb1, nullptr, pH, nullptr, nullptr);
    gemm_bf16<64,128,256,128,0,1,1><<<dim3(MTOT/64,1), 256, SM_MLP>>>(
        pMid, nullptr, pWbf + OFF_SM1, smb1, nullptr, pHsm, nullptr, nullptr);
    smooth_kernel<<<MTOT/8, 256>>>(smw2, smb2);
    gemm_bf16<64,128,512,1024,2,2,0><<<dim3(MTOT/64,8), 256, SM_MLP>>>(
        nullptr, pH, pWbf + OFF_MX2, mxb2, pQm, nullptr, cap, nullptr);
    rar_kernel<<<B, 256, RAR_SMEM>>>(lens, qw, qb, kw, kb, vw, vb, 0);

    // ---- pass 1 ----
    alv_kernel<1><<<B, 256, ALV_SMEM>>>(img, cap, lens);
    gemm_bf16<32,256,1024,256,1,0,0><<<dim3(MTOT/32,1), 256, SM_ALVG>>>(
        pWc, nullptr, pWbf + OFF_ALV1, alvb + SS, pMid, nullptr, cap, pFac);
    rar_kernel<<<B, 256, RAR_SMEM>>>(lens, qw + SS*SS, qb + SS, kw + SS*SS, kb + SS,
                                     vw + SS, vb + 1, 1);

    final_kernel<<<9, 256>>>(ew, eb, out);
}

// round 6
// speedup vs baseline: 5.5524x; 1.2081x over previous
#include <cuda_runtime.h>
#include <cuda_bf16.h>
#include <math.h>
#include <stdint.h>

#define CC 48
#define NN 48
#define WW 24
#define RR 36
#define DD 1024
#define SS 256
#define MTOT (CC*NN*WW)   // 55296

// ---------------- scratch (device globals; no allocation allowed) ----------
__device__ __align__(16) float g_sim_mid[MTOT*SS];              // 56.6 MB
__device__ __align__(16) float g_smooth[MTOT];
__device__ __align__(16) float g_qm[(size_t)MTOT*DD];           // 226 MB
__device__ __align__(16) __nv_bfloat16 g_wc[(size_t)MTOT*DD];   // 113 MB (unnorm wctx, bf16)
__device__ __align__(16) float g_fac[MTOT];
__device__ __align__(16) __nv_bfloat16 g_h[(size_t)MTOT*512];   // 56 MB
__device__ __align__(16) __nv_bfloat16 g_hsm[(size_t)MTOT*128]; // 14 MB
__device__ __align__(16) __nv_bfloat16 g_kt[(size_t)MTOT*SS];   // 28 MB
__device__ __align__(16) __nv_bfloat16 g_wbf[1343488];          // weights bf16
__device__ __align__(16) float g_higA[CC*NN*SS];
__device__ __align__(16) float g_higB[CC*NN*SS];

// weight offsets inside g_wbf
#define OFF_ALV0 0
#define OFF_ALV1 262144
#define OFF_MX1  524288
#define OFF_SM1  655360
#define OFF_MX2  688128
#define OFF_KW0  1212416
#define OFF_KW1  1277952

__device__ __forceinline__ float warp_sum(float v) {
#pragma unroll
    for (int o = 16; o; o >>= 1) v += __shfl_xor_sync(0xffffffffu, v, o);
    return v;
}
__device__ __forceinline__ uint32_t f2bf2(float lo, float hi) {
    uint32_t r; asm("cvt.rn.bf16x2.f32 %0, %1, %2;" : "=r"(r) : "f"(hi), "f"(lo)); return r;
}
__device__ __forceinline__ void ldsm4(uint32_t* r, uint32_t a) {
    asm volatile("ldmatrix.sync.aligned.m8n8.x4.shared.b16 {%0,%1,%2,%3},[%4];"
        : "=r"(r[0]),"=r"(r[1]),"=r"(r[2]),"=r"(r[3]) : "r"(a));
}
__device__ __forceinline__ void ldsm4t(uint32_t* r, uint32_t a) {
    asm volatile("ldmatrix.sync.aligned.m8n8.x4.trans.shared.b16 {%0,%1,%2,%3},[%4];"
        : "=r"(r[0]),"=r"(r[1]),"=r"(r[2]),"=r"(r[3]) : "r"(a));
}
__device__ __forceinline__ void mmabf(float* d, const uint32_t* a, const uint32_t* b) {
    asm volatile("mma.sync.aligned.m16n8k16.row.col.f32.bf16.bf16.f32 "
        "{%0,%1,%2,%3},{%4,%5,%6,%7},{%8,%9},{%0,%1,%2,%3};"
        : "+f"(d[0]),"+f"(d[1]),"+f"(d[2]),"+f"(d[3])
        : "r"(a[0]),"r"(a[1]),"r"(a[2]),"r"(a[3]),"r"(b[0]),"r"(b[1]));
}

// ---------------------------------------------------------------------------
__global__ void cvtw_kernel(const float* __restrict__ src, __nv_bfloat16* __restrict__ dst, int n4)
{
    int i = blockIdx.x * blockDim.x + threadIdx.x;
    if (i < n4) {
        float4 v = *(const float4*)(src + (size_t)i*4);
        uint2 o; o.x = f2bf2(v.x, v.y); o.y = f2bf2(v.z, v.w);
        *(uint2*)(dst + (size_t)i*4) = o;
    }
}

// ---------------------------------------------------------------------------
// bf16 m16n8k16 GEMM. 8 warps split N.
// AMODE 0: A fp32 -> cvt.  AMODE 1: A = (cap - wc_bf16*fac)^2.  AMODE 2: A bf16.
// EPI 0: +bias, l2norm over full 256 row (M_BLK=32, N_BLK=N_TOT=256)
// EPI 1: +bias, tanh (OUTBF: bf16 out)
// EPI 2: +bias, tanh, clip(+1), * cap row -> fp32 out
// ---------------------------------------------------------------------------
template<int M_BLK,int N_BLK,int K_DIM,int N_TOT,int AMODE,int EPI,int OUTBF>
__global__ void __launch_bounds__(256) gemm_bf16(
    const float* __restrict__ Af, const __nv_bfloat16* __restrict__ Ab,
    const __nv_bfloat16* __restrict__ Bw, const float* __restrict__ bias,
    float* __restrict__ Cf, __nv_bfloat16* __restrict__ Cb,
    const float* __restrict__ cap, const float* __restrict__ fac)
{
    constexpr int MT   = M_BLK/16;
    constexpr int NT   = N_BLK/64;
    constexpr int SAW  = 20;
    constexpr int SBW  = N_BLK/2 + 4;
    constexpr int ABUF = M_BLK*SAW;
    constexpr int BBUF = 32*SBW;
    constexpr int APASS = M_BLK/32;
    constexpr int BROWP = 2048/N_BLK;
    constexpr int BPASS = 32/BROWP;
    constexpr int KT   = K_DIM/32;

    extern __shared__ uint32_t dsm[];
    uint32_t* As = dsm;
    uint32_t* Bs = dsm + 2*ABUF;
    float* sRed  = (float*)(dsm + 2*ABUF + 2*BBUF);
    float* sFacR = sRed + 32*8;

    const int m0 = blockIdx.x * M_BLK;
    const int n0 = blockIdx.y * N_BLK;
    const int tid = threadIdx.x, lane = tid & 31, wid = tid >> 5;
    const int g = lane >> 2, tig = lane & 3;
    const int wn0 = wid * (N_BLK/8);

    const int a_row = tid >> 3, a_c = (tid & 7) * 4;
    float facr[APASS]; int caprow[APASS];
    if (AMODE == 1) {
#pragma unroll
        for (int p = 0; p < APASS; p++) {
            int r = m0 + p*32 + a_row;
            facr[p] = fac[r];
            caprow[p] = (r/1152)*24 + (r%24);
        }
    }
    const int b_row = tid / (N_BLK/8), b_c = (tid % (N_BLK/8)) * 8;
    const __nv_bfloat16* Bptr = Bw + (size_t)b_row*N_TOT + n0 + b_c;

    uint32_t areg[2*APASS]; uint4 breg[BPASS];

    auto loadA = [&](int kt) {
#pragma unroll
        for (int p = 0; p < APASS; p++) {
            int r = m0 + p*32 + a_row;
            if (AMODE == 2) {
                uint2 v = *(const uint2*)(Ab + (size_t)r*K_DIM + kt*32 + a_c);
                areg[p*2] = v.x; areg[p*2+1] = v.y;
            } else if (AMODE == 0) {
                float4 v = *(const float4*)(Af + (size_t)r*K_DIM + kt*32 + a_c);
                areg[p*2]   = f2bf2(v.x, v.y);
                areg[p*2+1] = f2bf2(v.z, v.w);
            } else {
                uint2 wv2 = *(const uint2*)(Ab + (size_t)r*K_DIM + kt*32 + a_c);
                float2 w01 = __bfloat1622float2(*(__nv_bfloat162*)&wv2.x);
                float2 w23 = __bfloat1622float2(*(__nv_bfloat162*)&wv2.y);
                float4 cv = *(const float4*)(cap + (size_t)caprow[p]*K_DIM + kt*32 + a_c);
                float f = facr[p];
                float s0 = cv.x - w01.x*f; s0 *= s0;
                float s1 = cv.y - w01.y*f; s1 *= s1;
                float s2 = cv.z - w23.x*f; s2 *= s2;
                float s3 = cv.w - w23.y*f; s3 *= s3;
                areg[p*2]   = f2bf2(s0, s1);
                areg[p*2+1] = f2bf2(s2, s3);
            }
        }
    };
    auto stsA = [&](int buf) {
#pragma unroll
        for (int p = 0; p < APASS; p++)
            *(uint2*)(As + buf*ABUF + (p*32 + a_row)*SAW + (tid&7)*2) =
                make_uint2(areg[p*2], areg[p*2+1]);
    };
    auto loadB = [&](int kt) {
#pragma unroll
        for (int p = 0; p < BPASS; p++)
            breg[p] = *(const uint4*)(Bptr + (size_t)(kt*32 + p*BROWP)*N_TOT);
    };
    auto stsB = [&](int buf) {
#pragma unroll
        for (int p = 0; p < BPASS; p++)
            *(uint4*)(Bs + buf*BBUF + (b_row + p*BROWP)*SBW + (tid % (N_BLK/8))*4) = breg[p];
    };

    loadA(0); loadB(0);
    stsA(0);  stsB(0);
    __syncthreads();

    float acc[MT][NT][4];
#pragma unroll
    for (int i = 0; i < MT; i++)
#pragma unroll
        for (int j = 0; j < NT; j++)
#pragma unroll
            for (int k = 0; k < 4; k++) acc[i][j][k] = 0.f;

    uint32_t smA = (uint32_t)__cvta_generic_to_shared(As);
    uint32_t smB = (uint32_t)__cvta_generic_to_shared(Bs);
    const uint32_t aoff = (lane & 15)*(SAW*4) + (lane >> 4)*16;
    const uint32_t boff = ((lane & 7) + ((lane >> 3) & 1)*8)*(SBW*4)
                        + (wn0 + (lane >> 4)*8)*2;

    for (int kt = 0; kt < KT; kt++) {
        int cur = kt & 1;
        if (kt + 1 < KT) { loadA(kt+1); loadB(kt+1); }
        uint32_t Ab0 = smA + cur*(ABUF*4);
        uint32_t Bb0 = smB + cur*(BBUF*4);
#pragma unroll
        for (int ks = 0; ks < 2; ks++) {
            uint32_t af[MT][4], bf[NT][2];
#pragma unroll
            for (int i = 0; i < MT; i++)
                ldsm4(af[i], Ab0 + i*16*(SAW*4) + aoff + ks*32);
#pragma unroll
            for (int jp = 0; jp < NT/2; jp++) {
                uint32_t t[4];
                ldsm4t(t, Bb0 + ks*16*(SBW*4) + boff + jp*32);
                bf[2*jp][0] = t[0]; bf[2*jp][1] = t[1];
                bf[2*jp+1][0] = t[2]; bf[2*jp+1][1] = t[3];
            }
#pragma unroll
            for (int i = 0; i < MT; i++)
#pragma unroll
                for (int j = 0; j < NT; j++)
                    mmabf(acc[i][j], af[i], bf[j]);
        }
        if (kt + 1 < KT) { stsA((kt+1)&1); stsB((kt+1)&1); }
        __syncthreads();
    }

#pragma unroll
    for (int j = 0; j < NT; j++) {
        int coln = n0 + wn0 + j*8 + 2*tig;
        float b0 = bias[coln], b1 = bias[coln+1];
#pragma unroll
        for (int i = 0; i < MT; i++) {
            acc[i][j][0] += b0; acc[i][j][1] += b1;
            acc[i][j][2] += b0; acc[i][j][3] += b1;
        }
    }

    if (EPI == 0) {
        float ps[2][2];
#pragma unroll
        for (int i = 0; i < 2; i++) {
            ps[i][0] = 0.f; ps[i][1] = 0.f;
#pragma unroll
            for (int j = 0; j < NT; j++) {
                ps[i][0] += acc[i][j][0]*acc[i][j][0] + acc[i][j][1]*acc[i][j][1];
                ps[i][1] += acc[i][j][2]*acc[i][j][2] + acc[i][j][3]*acc[i][j][3];
            }
        }
#pragma unroll
        for (int i = 0; i < 2; i++)
#pragma unroll
            for (int h = 0; h < 2; h++) {
                ps[i][h] += __shfl_xor_sync(0xffffffffu, ps[i][h], 1);
                ps[i][h] += __shfl_xor_sync(0xffffffffu, ps[i][h], 2);
            }
        if (tig == 0) {
#pragma unroll
            for (int i = 0; i < 2; i++) {
                sRed[(i*16 + g    )*8 + wid] = ps[i][0];
                sRed[(i*16 + g + 8)*8 + wid] = ps[i][1];
            }
        }
        __syncthreads();
        if (tid < 32) {
            float s = 0.f;
#pragma unroll
            for (int k = 0; k < 8; k++) s += sRed[tid*8 + k];
            sFacR[tid] = 1.f / (sqrtf(s) + 1e-8f);
        }
        __syncthreads();
#pragma unroll
        for (int i = 0; i < 2; i++) {
            float f0 = sFacR[i*16 + g], f1 = sFacR[i*16 + g + 8];
#pragma unroll
            for (int j = 0; j < NT; j++) {
                int coln = wn0 + j*8 + 2*tig;
                *(float2*)&Cf[(size_t)(m0 + i*16 + g    )*N_TOT + coln] =
                    make_float2(acc[i][j][0]*f0, acc[i][j][1]*f0);
                *(float2*)&Cf[(size_t)(m0 + i*16 + g + 8)*N_TOT + coln] =
                    make_float2(acc[i][j][2]*f1, acc[i][j][3]*f1);
            }
        }
    } else if (EPI == 1) {
#pragma unroll
        for (int i = 0; i < MT; i++) {
            int r0 = m0 + i*16 + g, r1 = r0 + 8;
#pragma unroll
            for (int j = 0; j < NT; j++) {
                int coln = n0 + wn0 + j*8 + 2*tig;
                float v0 = tanhf(acc[i][j][0]), v1 = tanhf(acc[i][j][1]);
                float v2 = tanhf(acc[i][j][2]), v3 = tanhf(acc[i][j][3]);
                if (OUTBF) {
                    *(uint32_t*)&Cb[(size_t)r0*N_TOT + coln] = f2bf2(v0, v1);
                    *(uint32_t*)&Cb[(size_t)r1*N_TOT + coln] = f2bf2(v2, v3);
                } else {
                    *(float2*)&Cf[(size_t)r0*N_TOT + coln] = make_float2(v0, v1);
                    *(float2*)&Cf[(size_t)r1*N_TOT + coln] = make_float2(v2, v3);
                }
            }
        }
    } else {
#pragma unroll
        for (int i = 0; i < MT; i++) {
            int r0 = m0 + i*16 + g, r1 = r0 + 8;
            int cr0 = (r0/1152)*24 + (r0%24);
            int cr1 = (r1/1152)*24 + (r1%24);
#pragma unroll
            for (int j = 0; j < NT; j++) {
                int coln = n0 + wn0 + j*8 + 2*tig;
                float m00 = fminf(fmaxf(tanhf(acc[i][j][0]) + 1.f, -1.f), 1.f);
                float m01 = fminf(fmaxf(tanhf(acc[i][j][1]) + 1.f, -1.f), 1.f);
                float m10 = fminf(fmaxf(tanhf(acc[i][j][2]) + 1.f, -1.f), 1.f);
                float m11 = fminf(fmaxf(tanhf(acc[i][j][3]) + 1.f, -1.f), 1.f);
                float2 c0 = *(const float2*)&cap[(size_t)cr0*DD + coln];
                float2 c1 = *(const float2*)&cap[(size_t)cr1*DD + coln];
                *(float2*)&Cf[(size_t)r0*N_TOT + coln] = make_float2(c0.x*m00, c0.y*m01);
                *(float2*)&Cf[(size_t)r1*N_TOT + coln] = make_float2(c1.x*m10, c1.y*m11);
            }
        }
    }
}

// ---------------------------------------------------------------------------
// alv kernel: attn + softmax + wctx. Writes unnormalized wctx (bf16) + fac.
// ---------------------------------------------------------------------------
template<int PASS>
__global__ void __launch_bounds__(256) alv_kernel(
        const float* __restrict__ img, const float* __restrict__ cap,
        const int* __restrict__ lens)
{
    extern __shared__ float sm[];
    float* sImg = sm;
    float* sA   = sImg + RR*DD;
    float* sAT  = sA + RR*WW;
    float* sA2  = sAT + WW*RR;
    float* sRed = sA2 + RR*WW;

    const int b = blockIdx.x;
    const int c = b / NN, n = b % NN;
    const int tid = threadIdx.x, lane = tid & 31, wid = tid >> 5;
    const int len = lens[c];

    {
        const float4* gi = (const float4*)(img + (size_t)n * RR * DD);
        float4* si = (float4*)sImg;
        for (int i = tid; i < RR*DD/4; i += 256) si[i] = gi[i];
    }
    __syncthreads();

    for (int wi = 0; wi < 3; wi++) {
        int w = wid + wi * 8;
        const float* capp = (PASS == 0) ? (cap + ((size_t)c*WW + w)*DD)
                                        : (g_qm + ((size_t)b*WW + w)*DD);
        float4 cr4[8];
#pragma unroll
        for (int k = 0; k < 8; k++)
            cr4[k] = *(const float4*)(capp + k*128 + lane*4);
        for (int r = 0; r < RR; r += 2) {
            float a0 = 0.f, a1 = 0.f;
#pragma unroll
            for (int k = 0; k < 8; k++) {
                float4 i0 = *(const float4*)(sImg + r*DD + k*128 + lane*4);
                float4 i1 = *(const float4*)(sImg + (r+1)*DD + k*128 + lane*4);
                a0 = fmaf(cr4[k].x, i0.x, a0); a0 = fmaf(cr4[k].y, i0.y, a0);
                a0 = fmaf(cr4[k].z, i0.z, a0); a0 = fmaf(cr4[k].w, i0.w, a0);
                a1 = fmaf(cr4[k].x, i1.x, a1); a1 = fmaf(cr4[k].y, i1.y, a1);
                a1 = fmaf(cr4[k].z, i1.z, a1); a1 = fmaf(cr4[k].w, i1.w, a1);
            }
            a0 = warp_sum(a0); a1 = warp_sum(a1);
            if (lane == 0) { sA[r*WW + w] = a0; sA[(r+1)*WW + w] = a1; }
        }
    }
    __syncthreads();

    if (tid < RR) {
        int r = tid;
        float vals[WW];
        float ss = 0.f;
#pragma unroll
        for (int w = 0; w < WW; w++) {
            float v = sA[r*WW + w];
            v = (v >= 0.f) ? v : 0.1f * v;
            if (w >= len) v = 0.f;
            vals[w] = v;
            ss += v * v;
        }
        float f = 1.f / (sqrtf(ss) + 1e-8f);
#pragma unroll
        for (int w = 0; w < WW; w++) sAT[w*RR + r] = vals[w] * f;
    }
    __syncthreads();

    if (tid < WW) {
        int w = tid;
        float smo = (PASS == 0) ? 9.f : g_smooth[(size_t)b*WW + w];
        float m = -1e30f;
        for (int r = 0; r < RR; r++) { float v = sAT[w*RR + r]*smo; if (v > m) m = v; }
        float s = 0.f;
        for (int r = 0; r < RR; r++) {
            float e = expf(sAT[w*RR + r]*smo - m);
            sAT[w*RR + r] = e; s += e;
        }
        float inv = 1.f / s;
        for (int r = 0; r < RR; r++) sA2[r*WW + w] = sAT[w*RR + r] * inv;
    }
    __syncthreads();

    {
        float psq[WW];
#pragma unroll
        for (int w = 0; w < WW; w++) psq[w] = 0.f;
        for (int cidx = 0; cidx < 4; cidx++) {
            int d = cidx*256 + tid;
            float acc[WW];
#pragma unroll
            for (int w = 0; w < WW; w++) acc[w] = 0.f;
            for (int r = 0; r < RR; r++) {
                float iv = sImg[r*DD + d];
                const float4* ap = (const float4*)(sA2 + r*WW);
#pragma unroll
                for (int q = 0; q < 6; q++) {
                    float4 a4 = ap[q];
                    acc[q*4+0] = fmaf(a4.x, iv, acc[q*4+0]);
                    acc[q*4+1] = fmaf(a4.y, iv, acc[q*4+1]);
                    acc[q*4+2] = fmaf(a4.z, iv, acc[q*4+2]);
                    acc[q*4+3] = fmaf(a4.w, iv, acc[q*4+3]);
                }
            }
#pragma unroll
            for (int w = 0; w < WW; w++) {
                psq[w] = fmaf(acc[w], acc[w], psq[w]);
                g_wc[((size_t)b*WW + w)*DD + d] = __float2bfloat16(acc[w]);
            }
        }
#pragma unroll
        for (int w = 0; w < WW; w++) {
            float v = warp_sum(psq[w]);
            if (lane == 0) sRed[w*8 + wid] = v;
        }
    }
    __syncthreads();
    if (tid < WW) {
        float s = 0.f;
#pragma unroll
        for (int k = 0; k < 8; k++) s += sRed[tid*8 + k];
        g_fac[(size_t)b*WW + tid] = 1.f / (sqrtf(s) + 1e-8f);
    }
}

// ---------------------------------------------------------------------------
__global__ void mean_kernel(const int* __restrict__ lens)
{
    int b = blockIdx.x;
    int c = b / NN;
    int t = threadIdx.x;
    int len = lens[c];
    float inv = 1.f / (float)len;
    const float* p = g_sim_mid + (size_t)b*WW*SS + t;
    float s = 0.f;
    for (int w = 0; w < len; w++) s += p[(size_t)w * SS];
    g_higA[(size_t)b*SS + t] = s * inv;
}

__global__ void smooth_kernel(const float* __restrict__ w2, const float* __restrict__ b2)
{
    int wid = threadIdx.x >> 5, lane = threadIdx.x & 31;
    size_t r = (size_t)blockIdx.x * 8 + wid;
    const __nv_bfloat16* h = g_hsm + r * 128;
    float a = 0.f;
#pragma unroll
    for (int k = 0; k < 4; k++)
        a = fmaf(__bfloat162float(h[lane + 32*k]), w2[lane + 32*k], a);
    a = warp_sum(a);
    if (lane == 0) {
        float v = a + b2[0] + 9.0f;
        g_smooth[r] = v > 0.f ? v : 0.f;
    }
}

// ---------------------------------------------------------------------------
// rar v2: kt (tanh(mid@kw+kb)) precomputed in g_kt. Light per-block work.
// ---------------------------------------------------------------------------
__global__ void __launch_bounds__(256) rar_kernel(
        const int* __restrict__ lens,
        const float* __restrict__ qw, const float* __restrict__ qb,
        const float* __restrict__ vw, const float* __restrict__ vb,
        const __nv_bfloat16* __restrict__ kt, int dir)
{
    extern __shared__ float sm[];
    float* sMid = sm;             // WW*SS
    float* sHig = sMid + WW*SS;   // SS
    float* sRed = sHig + SS;      // WW*8
    float* sLog = sRed + WW*8;    // WW
    float* sWgt = sLog + WW;      // WW
    float* sMisc= sWgt + WW;

    const int b = blockIdx.x;
    const int c = b / NN;
    const int tid = threadIdx.x, lane = tid & 31, wid = tid >> 5;
    const int len = lens[c];

    const float* hin = (dir == 0) ? g_higA : g_higB;
    float*       hout= (dir == 0) ? g_higB : g_higA;

    {
        const float4* gm = (const float4*)(g_sim_mid + (size_t)b*WW*SS);
        float4* s4 = (float4*)sMid;
        for (int i = tid; i < WW*SS/4; i += 256) s4[i] = gm[i];
    }
    sHig[tid] = hin[(size_t)b*SS + tid];
    __syncthreads();

    // hig_q col = tid
    float hv;
    {
        float acc = qb[tid];
        const float* wp = qw + tid;
#pragma unroll 4
        for (int s0 = 0; s0 < SS/4; s0++) {
            float4 h4 = *(const float4*)(sHig + s0*4);
            acc = fmaf(h4.x, wp[(size_t)(s0*4+0)*SS], acc);
            acc = fmaf(h4.y, wp[(size_t)(s0*4+1)*SS], acc);
            acc = fmaf(h4.z, wp[(size_t)(s0*4+2)*SS], acc);
            acc = fmaf(h4.w, wp[(size_t)(s0*4+3)*SS], acc);
        }
        hv = tanhf(acc) * vw[tid];
    }

    // logits[w] = sum_s kt[w][s]*hv
    {
        const __nv_bfloat16* ktp = kt + (size_t)b*WW*SS + tid;
        float pv[WW];
#pragma unroll
        for (int w = 0; w < WW; w++)
            pv[w] = __bfloat162float(ktp[(size_t)w*SS]) * hv;
#pragma unroll
        for (int w = 0; w < WW; w++) {
            float v = warp_sum(pv[w]);
            if (lane == 0) sRed[w*8 + wid] = v;
        }
    }
    __syncthreads();
    if (tid < WW) {
        float s = 0.f;
#pragma unroll
        for (int k = 0; k < 8; k++) s += sRed[tid*8 + k];
        s += vb[0];
        if (tid >= len) s = -1e30f;
        sLog[tid] = s;
    }
    __syncthreads();
    if (tid == 0) {
        float m = -1e30f;
        for (int w = 0; w < WW; w++) m = fmaxf(m, sLog[w]);
        float s = 0.f;
        for (int w = 0; w < WW; w++) { float e = expf(sLog[w] - m); sWgt[w] = e; s += e; }
        float inv = 1.f / s;
        for (int w = 0; w < WW; w++) sWgt[w] *= inv;
    }
    __syncthreads();

    float o = 0.f;
#pragma unroll
    for (int w = 0; w < WW; w++) o = fmaf(sWgt[w], sMid[w*SS + tid], o);
    float sq = warp_sum(o * o);
    if (lane == 0) sRed[wid] = sq;
    __syncthreads();
    if (tid == 0) {
        float tot = 0.f;
#pragma unroll
        for (int k = 0; k < 8; k++) tot += sRed[k];
        sMisc[0] = 1.f / (sqrtf(tot) + 1e-8f);
    }
    __syncthreads();
    hout[(size_t)b*SS + tid] = o * sMisc[0];
}

// ---------------------------------------------------------------------------
__global__ void final_kernel(const float* __restrict__ ew, const float* __restrict__ eb,
                             float* __restrict__ out)
{
    int gw = (blockIdx.x * blockDim.x + threadIdx.x) >> 5;
    int lane = threadIdx.x & 31;
    int nwarps = (gridDim.x * blockDim.x) >> 5;
    for (int b = gw; b < CC*NN; b += nwarps) {
        const float* h = g_higA + (size_t)b*SS;
        float a = 0.f;
#pragma unroll
        for (int k = 0; k < 8; k++) a = fmaf(h[lane + k*32], ew[lane + k*32], a);
        a = warp_sum(a);
        if (lane == 0) {
            float v = a + eb[0];
            int c = b / NN, n = b % NN;
            out[n*CC + c] = 1.f / (1.f + expf(-v));
        }
    }
}

// ---------------------------------------------------------------------------
extern "C" void kernel_launch(void* const* d_in, const int* in_sizes, int n_in,
                              void* d_out, int out_size)
{
    const float* img  = (const float*)d_in[0];
    const float* cap  = (const float*)d_in[1];
    const int*   lens = (const int*)  d_in[2];
    const float* alvw = (const float*)d_in[3];
    const float* alvb = (const float*)d_in[4];
    const float* qw   = (const float*)d_in[5];
    const float* qb   = (const float*)d_in[6];
    const float* kw   = (const float*)d_in[7];
    const float* kb   = (const float*)d_in[8];
    const float* vw   = (const float*)d_in[9];
    const float* vb   = (const float*)d_in[10];
    const float* smw1 = (const float*)d_in[11];
    const float* smb1 = (const float*)d_in[12];
    const float* smw2 = (const float*)d_in[13];
    const float* smb2 = (const float*)d_in[14];
    const float* mxw1 = (const float*)d_in[15];
    const float* mxb1 = (const float*)d_in[16];
    const float* mxw2 = (const float*)d_in[17];
    const float* mxb2 = (const float*)d_in[18];
    const float* ew   = (const float*)d_in[19];
    const float* eb   = (const float*)d_in[20];
    float* out = (float*)d_out;

    float *pMid, *pQm, *pFac;
    __nv_bfloat16 *pH, *pHsm, *pWbf, *pWc, *pKt;
    cudaGetSymbolAddress((void**)&pMid, g_sim_mid);
    cudaGetSymbolAddress((void**)&pQm,  g_qm);
    cudaGetSymbolAddress((void**)&pWc,  g_wc);
    cudaGetSymbolAddress((void**)&pFac, g_fac);
    cudaGetSymbolAddress((void**)&pH,   g_h);
    cudaGetSymbolAddress((void**)&pHsm, g_hsm);
    cudaGetSymbolAddress((void**)&pWbf, g_wbf);
    cudaGetSymbolAddress((void**)&pKt,  g_kt);

    const size_t ALV_SMEM = (size_t)(RR*DD + RR*WW*3 + WW*8 + 16) * sizeof(float);
    const size_t RAR_SMEM = (size_t)(WW*SS + SS + WW*8 + WW + WW + 32) * sizeof(float);
    const size_t SM_ALVG = (size_t)(2*32*20 + 2*32*132)*4 + (32*8 + 32)*4;
    const size_t SM_MLP  = (size_t)(2*64*20 + 2*32*68)*4 + (32*8 + 32)*4;

    cudaFuncSetAttribute(alv_kernel<0>, cudaFuncAttributeMaxDynamicSharedMemorySize, (int)ALV_SMEM);
    cudaFuncSetAttribute(alv_kernel<1>, cudaFuncAttributeMaxDynamicSharedMemorySize, (int)ALV_SMEM);
    cudaFuncSetAttribute(gemm_bf16<32,256,1024,256,1,0,0>, cudaFuncAttributeMaxDynamicSharedMemorySize, (int)SM_ALVG);
    cudaFuncSetAttribute(gemm_bf16<64,128,256,512,0,1,1>,  cudaFuncAttributeMaxDynamicSharedMemorySize, (int)SM_MLP);
    cudaFuncSetAttribute(gemm_bf16<64,128,256,128,0,1,1>,  cudaFuncAttributeMaxDynamicSharedMemorySize, (int)SM_MLP);
    cudaFuncSetAttribute(gemm_bf16<64,128,256,256,0,1,1>,  cudaFuncAttributeMaxDynamicSharedMemorySize, (int)SM_MLP);
    cudaFuncSetAttribute(gemm_bf16<64,128,512,1024,2,2,0>, cudaFuncAttributeMaxDynamicSharedMemorySize, (int)SM_MLP);

    const int B = CC * NN;

    // weight conversion
    cvtw_kernel<<<(524288/4+255)/256, 256>>>(alvw, pWbf + OFF_ALV0, 524288/4);
    cvtw_kernel<<<(131072/4+255)/256, 256>>>(mxw1, pWbf + OFF_MX1, 131072/4);
    cvtw_kernel<<<(32768/4+255)/256, 256>>>(smw1, pWbf + OFF_SM1, 32768/4);
    cvtw_kernel<<<(524288/4+255)/256, 256>>>(mxw2, pWbf + OFF_MX2, 524288/4);
    cvtw_kernel<<<(131072/4+255)/256, 256>>>(kw, pWbf + OFF_KW0, 131072/4);

    // ---- pass 0 ----
    alv_kernel<0><<<B, 256, ALV_SMEM>>>(img, cap, lens);
    gemm_bf16<32,256,1024,256,1,0,0><<<dim3(MTOT/32,1), 256, SM_ALVG>>>(
        nullptr, pWc, pWbf + OFF_ALV0, alvb, pMid, nullptr, cap, pFac);
    mean_kernel<<<B, 256>>>(lens);
    gemm_bf16<64,128,256,512,0,1,1><<<dim3(MTOT/64,4), 256, SM_MLP>>>(
        pMid, nullptr, pWbf + OFF_MX1, mxb1, nullptr, pH, nullptr, nullptr);
    gemm_bf16<64,128,256,128,0,1,1><<<dim3(MTOT/64,1), 256, SM_MLP>>>(
        pMid, nullptr, pWbf + OFF_SM1, smb1, nullptr, pHsm, nullptr, nullptr);
    smooth_kernel<<<MTOT/8, 256>>>(smw2, smb2);
    gemm_bf16<64,128,512,1024,2,2,0><<<dim3(MTOT/64,8), 256, SM_MLP>>>(
        nullptr, pH, pWbf + OFF_MX2, mxb2, pQm, nullptr, cap, nullptr);
    gemm_bf16<64,128,256,256,0,1,1><<<dim3(MTOT/64,2), 256, SM_MLP>>>(
        pMid, nullptr, pWbf + OFF_KW0, kb, nullptr, pKt, nullptr, nullptr);
    rar_kernel<<<B, 256, RAR_SMEM>>>(lens, qw, qb, vw, vb, pKt, 0);

    // ---- pass 1 ----
    cvtw_kernel<<<(131072/4+255)/256, 256>>>(kw + SS*SS, pWbf + OFF_KW1, 131072/4);
    alv_kernel<1><<<B, 256, ALV_SMEM>>>(img, cap, lens);
    gemm_bf16<32,256,1024,256,1,0,0><<<dim3(MTOT/32,1), 256, SM_ALVG>>>(
        nullptr, pWc, pWbf + OFF_ALV1, alvb + SS, pMid, nullptr, cap, pFac);
    gemm_bf16<64,128,256,256,0,1,1><<<dim3(MTOT/64,2), 256, SM_MLP>>>(
        pMid, nullptr, pWbf + OFF_KW1, kb + SS, nullptr, pKt, nullptr, nullptr);
    rar_kernel<<<B, 256, RAR_SMEM>>>(lens, qw + SS*SS, qb + SS, vw + SS, vb + 1, pKt, 1);

    final_kernel<<<9, 256>>>(ew, eb, out);
}

// round 7
// speedup vs baseline: 5.6652x; 1.0203x over previous
#include <cuda_runtime.h>
#include <cuda_bf16.h>
#include <math.h>
#include <stdint.h>

#define CC 48
#define NN 48
#define WW 24
#define RR 36
#define DD 1024
#define SS 256
#define MTOT (CC*NN*WW)   // 55296

// ---------------- scratch (device globals; no allocation allowed) ----------
__device__ __align__(16) float g_sim_mid[MTOT*SS];              // 56.6 MB
__device__ __align__(16) float g_smooth[MTOT];
__device__ __align__(16) __nv_bfloat16 g_qmb[(size_t)MTOT*DD];  // 113 MB (bf16 qm)
__device__ __align__(16) __nv_bfloat16 g_wc[(size_t)MTOT*DD];   // 113 MB
__device__ __align__(16) float g_fac[MTOT];
__device__ __align__(16) __nv_bfloat16 g_h[(size_t)MTOT*512];   // 56 MB
__device__ __align__(16) __nv_bfloat16 g_hsm[(size_t)MTOT*128]; // 14 MB
__device__ __align__(16) __nv_bfloat16 g_kt[(size_t)MTOT*SS];   // 28 MB
__device__ __align__(16) __nv_bfloat16 g_wbf[1507328];          // weights bf16
__device__ __align__(16) float g_higA[CC*NN*SS];
__device__ __align__(16) float g_higB[CC*NN*SS];

// weight offsets inside g_wbf
#define OFF_ALV0 0
#define OFF_ALV1 262144
#define OFF_MX2  524288          // 512*1024 -> ends 1048576
#define OFF_KW1  1048576         // 256*256  -> ends 1114112
#define OFF_WMLP 1114112         // 256*896  -> ends 1343488

__device__ __forceinline__ float warp_sum(float v) {
#pragma unroll
    for (int o = 16; o; o >>= 1) v += __shfl_xor_sync(0xffffffffu, v, o);
    return v;
}
__device__ __forceinline__ uint32_t f2bf2(float lo, float hi) {
    uint32_t r; asm("cvt.rn.bf16x2.f32 %0, %1, %2;" : "=r"(r) : "f"(hi), "f"(lo)); return r;
}
__device__ __forceinline__ void ldsm4(uint32_t* r, uint32_t a) {
    asm volatile("ldmatrix.sync.aligned.m8n8.x4.shared.b16 {%0,%1,%2,%3},[%4];"
        : "=r"(r[0]),"=r"(r[1]),"=r"(r[2]),"=r"(r[3]) : "r"(a));
}
__device__ __forceinline__ void ldsm4t(uint32_t* r, uint32_t a) {
    asm volatile("ldmatrix.sync.aligned.m8n8.x4.trans.shared.b16 {%0,%1,%2,%3},[%4];"
        : "=r"(r[0]),"=r"(r[1]),"=r"(r[2]),"=r"(r[3]) : "r"(a));
}
__device__ __forceinline__ void mmabf(float* d, const uint32_t* a, const uint32_t* b) {
    asm volatile("mma.sync.aligned.m16n8k16.row.col.f32.bf16.bf16.f32 "
        "{%0,%1,%2,%3},{%4,%5,%6,%7},{%8,%9},{%0,%1,%2,%3};"
        : "+f"(d[0]),"+f"(d[1]),"+f"(d[2]),"+f"(d[3])
        : "r"(a[0]),"r"(a[1]),"r"(a[2]),"r"(a[3]),"r"(b[0]),"r"(b[1]));
}

// ---------------------------------------------------------------------------
__global__ void cvtw_kernel(const float* __restrict__ src, __nv_bfloat16* __restrict__ dst, int n4)
{
    int i = blockIdx.x * blockDim.x + threadIdx.x;
    if (i < n4) {
        float4 v = *(const float4*)(src + (size_t)i*4);
        uint2 o; o.x = f2bf2(v.x, v.y); o.y = f2bf2(v.z, v.w);
        *(uint2*)(dst + (size_t)i*4) = o;
    }
}
// strided convert: src (nrows x ncols) -> dst at col offset dcol0, row stride dstride
__global__ void cvtw_str(const float* __restrict__ src, __nv_bfloat16* __restrict__ dst,
                         int ncols, int dstride, int dcol0, int n4)
{
    int i = blockIdx.x * blockDim.x + threadIdx.x;
    if (i < n4) {
        float4 v = *(const float4*)(src + (size_t)i*4);
        int row = (i*4) / ncols, col = (i*4) % ncols;
        uint2 o; o.x = f2bf2(v.x, v.y); o.y = f2bf2(v.z, v.w);
        *(uint2*)(dst + (size_t)row*dstride + dcol0 + col) = o;
    }
}

// ---------------------------------------------------------------------------
// bf16 m16n8k16 GEMM. grid: x = N tiles, y = M tiles (A-reuse in L2).
// AMODE 0: A fp32->cvt. 1: A=(cap-wc*fac)^2. 2: A bf16.
// EPI 0: +bias, l2norm full 256 row (N_BLK=N_TOT=256).
// EPI 1: +bias, tanh -> Cb/Cf.
// EPI 2: +bias, tanh, clip(+1), *cap -> OUTBF? Cb : Cf.
// EPI 3: fused MLP routing: [0,512)->Cb, [512,640)->Cb2, [640,896)->Cb3, all tanh bf16.
// ---------------------------------------------------------------------------
template<int M_BLK,int N_BLK,int K_DIM,int N_TOT,int AMODE,int EPI,int OUTBF>
__global__ void __launch_bounds__(256) gemm_bf16(
    const float* __restrict__ Af, const __nv_bfloat16* __restrict__ Ab,
    const __nv_bfloat16* __restrict__ Bw,
    const float* __restrict__ bias, const float* __restrict__ bias2, const float* __restrict__ bias3,
    float* __restrict__ Cf, __nv_bfloat16* __restrict__ Cb,
    __nv_bfloat16* __restrict__ Cb2, __nv_bfloat16* __restrict__ Cb3,
    const float* __restrict__ cap, const float* __restrict__ fac)
{
    constexpr int MT   = M_BLK/16;
    constexpr int NT   = N_BLK/64;
    constexpr int SAW  = 20;
    constexpr int SBW  = N_BLK/2 + 4;
    constexpr int ABUF = M_BLK*SAW;
    constexpr int BBUF = 32*SBW;
    constexpr int APASS = M_BLK/32;
    constexpr int BROWP = 2048/N_BLK;
    constexpr int BPASS = 32/BROWP;
    constexpr int KT   = K_DIM/32;

    extern __shared__ uint32_t dsm[];
    uint32_t* As = dsm;
    uint32_t* Bs = dsm + 2*ABUF;
    float* sRed  = (float*)(dsm + 2*ABUF + 2*BBUF);   // M_BLK*8
    float* sFacR = sRed + M_BLK*8;                    // M_BLK

    const int m0 = blockIdx.y * M_BLK;
    const int n0 = blockIdx.x * N_BLK;
    const int tid = threadIdx.x, lane = tid & 31, wid = tid >> 5;
    const int g = lane >> 2, tig = lane & 3;
    const int wn0 = wid * (N_BLK/8);

    const int a_row = tid >> 3, a_c = (tid & 7) * 4;
    float facr[APASS]; int caprow[APASS];
    if (AMODE == 1) {
#pragma unroll
        for (int p = 0; p < APASS; p++) {
            int r = m0 + p*32 + a_row;
            facr[p] = fac[r];
            caprow[p] = (r/1152)*24 + (r%24);
        }
    }
    const int b_row = tid / (N_BLK/8), b_c = (tid % (N_BLK/8)) * 8;
    const __nv_bfloat16* Bptr = Bw + (size_t)b_row*N_TOT + n0 + b_c;

    uint32_t areg[2*APASS]; uint4 breg[BPASS];

    auto loadA = [&](int kt) {
#pragma unroll
        for (int p = 0; p < APASS; p++) {
            int r = m0 + p*32 + a_row;
            if (AMODE == 2) {
                uint2 v = *(const uint2*)(Ab + (size_t)r*K_DIM + kt*32 + a_c);
                areg[p*2] = v.x; areg[p*2+1] = v.y;
            } else if (AMODE == 0) {
                float4 v = *(const float4*)(Af + (size_t)r*K_DIM + kt*32 + a_c);
                areg[p*2]   = f2bf2(v.x, v.y);
                areg[p*2+1] = f2bf2(v.z, v.w);
            } else {
                uint2 wv2 = *(const uint2*)(Ab + (size_t)r*K_DIM + kt*32 + a_c);
                float2 w01 = __bfloat1622float2(*(__nv_bfloat162*)&wv2.x);
                float2 w23 = __bfloat1622float2(*(__nv_bfloat162*)&wv2.y);
                float4 cv = *(const float4*)(cap + (size_t)caprow[p]*K_DIM + kt*32 + a_c);
                float f = facr[p];
                float s0 = cv.x - w01.x*f; s0 *= s0;
                float s1 = cv.y - w01.y*f; s1 *= s1;
                float s2 = cv.z - w23.x*f; s2 *= s2;
                float s3 = cv.w - w23.y*f; s3 *= s3;
                areg[p*2]   = f2bf2(s0, s1);
                areg[p*2+1] = f2bf2(s2, s3);
            }
        }
    };
    auto stsA = [&](int buf) {
#pragma unroll
        for (int p = 0; p < APASS; p++)
            *(uint2*)(As + buf*ABUF + (p*32 + a_row)*SAW + (tid&7)*2) =
                make_uint2(areg[p*2], areg[p*2+1]);
    };
    auto loadB = [&](int kt) {
#pragma unroll
        for (int p = 0; p < BPASS; p++)
            breg[p] = *(const uint4*)(Bptr + (size_t)(kt*32 + p*BROWP)*N_TOT);
    };
    auto stsB = [&](int buf) {
#pragma unroll
        for (int p = 0; p < BPASS; p++)
            *(uint4*)(Bs + buf*BBUF + (b_row + p*BROWP)*SBW + (tid % (N_BLK/8))*4) = breg[p];
    };

    loadA(0); loadB(0);
    stsA(0);  stsB(0);
    __syncthreads();

    float acc[MT][NT][4];
#pragma unroll
    for (int i = 0; i < MT; i++)
#pragma unroll
        for (int j = 0; j < NT; j++)
#pragma unroll
            for (int k = 0; k < 4; k++) acc[i][j][k] = 0.f;

    uint32_t smA = (uint32_t)__cvta_generic_to_shared(As);
    uint32_t smB = (uint32_t)__cvta_generic_to_shared(Bs);
    const uint32_t aoff = (lane & 15)*(SAW*4) + (lane >> 4)*16;
    const uint32_t boff = ((lane & 7) + ((lane >> 3) & 1)*8)*(SBW*4)
                        + (wn0 + (lane >> 4)*8)*2;

    for (int kt = 0; kt < KT; kt++) {
        int cur = kt & 1;
        if (kt + 1 < KT) { loadA(kt+1); loadB(kt+1); }
        uint32_t Ab0 = smA + cur*(ABUF*4);
        uint32_t Bb0 = smB + cur*(BBUF*4);
#pragma unroll
        for (int ks = 0; ks < 2; ks++) {
            uint32_t af[MT][4], bf[NT][2];
#pragma unroll
            for (int i = 0; i < MT; i++)
                ldsm4(af[i], Ab0 + i*16*(SAW*4) + aoff + ks*32);
#pragma unroll
            for (int jp = 0; jp < NT/2; jp++) {
                uint32_t t[4];
                ldsm4t(t, Bb0 + ks*16*(SBW*4) + boff + jp*32);
                bf[2*jp][0] = t[0]; bf[2*jp][1] = t[1];
                bf[2*jp+1][0] = t[2]; bf[2*jp+1][1] = t[3];
            }
#pragma unroll
            for (int i = 0; i < MT; i++)
#pragma unroll
                for (int j = 0; j < NT; j++)
                    mmabf(acc[i][j], af[i], bf[j]);
        }
        if (kt + 1 < KT) { stsA((kt+1)&1); stsB((kt+1)&1); }
        __syncthreads();
    }

    if (EPI != 3) {
#pragma unroll
        for (int j = 0; j < NT; j++) {
            int coln = n0 + wn0 + j*8 + 2*tig;
            float b0 = bias[coln], b1 = bias[coln+1];
#pragma unroll
            for (int i = 0; i < MT; i++) {
                acc[i][j][0] += b0; acc[i][j][1] += b1;
                acc[i][j][2] += b0; acc[i][j][3] += b1;
            }
        }
    }

    if (EPI == 0) {
        float ps[MT][2];
#pragma unroll
        for (int i = 0; i < MT; i++) {
            ps[i][0] = 0.f; ps[i][1] = 0.f;
#pragma unroll
            for (int j = 0; j < NT; j++) {
                ps[i][0] += acc[i][j][0]*acc[i][j][0] + acc[i][j][1]*acc[i][j][1];
                ps[i][1] += acc[i][j][2]*acc[i][j][2] + acc[i][j][3]*acc[i][j][3];
            }
        }
#pragma unroll
        for (int i = 0; i < MT; i++)
#pragma unroll
            for (int h = 0; h < 2; h++) {
                ps[i][h] += __shfl_xor_sync(0xffffffffu, ps[i][h], 1);
                ps[i][h] += __shfl_xor_sync(0xffffffffu, ps[i][h], 2);
            }
        if (tig == 0) {
#pragma unroll
            for (int i = 0; i < MT; i++) {
                sRed[(i*16 + g    )*8 + wid] = ps[i][0];
                sRed[(i*16 + g + 8)*8 + wid] = ps[i][1];
            }
        }
        __syncthreads();
        if (tid < M_BLK) {
            float s = 0.f;
#pragma unroll
            for (int k = 0; k < 8; k++) s += sRed[tid*8 + k];
            sFacR[tid] = 1.f / (sqrtf(s) + 1e-8f);
        }
        __syncthreads();
#pragma unroll
        for (int i = 0; i < MT; i++) {
            float f0 = sFacR[i*16 + g], f1 = sFacR[i*16 + g + 8];
#pragma unroll
            for (int j = 0; j < NT; j++) {
                int coln = wn0 + j*8 + 2*tig;
                *(float2*)&Cf[(size_t)(m0 + i*16 + g    )*N_TOT + coln] =
                    make_float2(acc[i][j][0]*f0, acc[i][j][1]*f0);
                *(float2*)&Cf[(size_t)(m0 + i*16 + g + 8)*N_TOT + coln] =
                    make_float2(acc[i][j][2]*f1, acc[i][j][3]*f1);
            }
        }
    } else if (EPI == 1) {
#pragma unroll
        for (int i = 0; i < MT; i++) {
            int r0 = m0 + i*16 + g, r1 = r0 + 8;
#pragma unroll
            for (int j = 0; j < NT; j++) {
                int coln = n0 + wn0 + j*8 + 2*tig;
                float v0 = tanhf(acc[i][j][0]), v1 = tanhf(acc[i][j][1]);
                float v2 = tanhf(acc[i][j][2]), v3 = tanhf(acc[i][j][3]);
                if (OUTBF) {
                    *(uint32_t*)&Cb[(size_t)r0*N_TOT + coln] = f2bf2(v0, v1);
                    *(uint32_t*)&Cb[(size_t)r1*N_TOT + coln] = f2bf2(v2, v3);
                } else {
                    *(float2*)&Cf[(size_t)r0*N_TOT + coln] = make_float2(v0, v1);
                    *(float2*)&Cf[(size_t)r1*N_TOT + coln] = make_float2(v2, v3);
                }
            }
        }
    } else if (EPI == 2) {
#pragma unroll
        for (int i = 0; i < MT; i++) {
            int r0 = m0 + i*16 + g, r1 = r0 + 8;
            int cr0 = (r0/1152)*24 + (r0%24);
            int cr1 = (r1/1152)*24 + (r1%24);
#pragma unroll
            for (int j = 0; j < NT; j++) {
                int coln = n0 + wn0 + j*8 + 2*tig;
                float m00 = fminf(fmaxf(tanhf(acc[i][j][0]) + 1.f, -1.f), 1.f);
                float m01 = fminf(fmaxf(tanhf(acc[i][j][1]) + 1.f, -1.f), 1.f);
                float m10 = fminf(fmaxf(tanhf(acc[i][j][2]) + 1.f, -1.f), 1.f);
                float m11 = fminf(fmaxf(tanhf(acc[i][j][3]) + 1.f, -1.f), 1.f);
                float2 c0 = *(const float2*)&cap[(size_t)cr0*DD + coln];
                float2 c1 = *(const float2*)&cap[(size_t)cr1*DD + coln];
                if (OUTBF) {
                    *(uint32_t*)&Cb[(size_t)r0*N_TOT + coln] = f2bf2(c0.x*m00, c0.y*m01);
                    *(uint32_t*)&Cb[(size_t)r1*N_TOT + coln] = f2bf2(c1.x*m10, c1.y*m11);
                } else {
                    *(float2*)&Cf[(size_t)r0*N_TOT + coln] = make_float2(c0.x*m00, c0.y*m01);
                    *(float2*)&Cf[(size_t)r1*N_TOT + coln] = make_float2(c1.x*m10, c1.y*m11);
                }
            }
        }
    } else {  // EPI 3: fused MLP routing
        __nv_bfloat16* outp; const float* bp; int ostride, oc0;
        if (n0 < 512)      { outp = Cb;  bp = bias;  ostride = 512; oc0 = n0; }
        else if (n0 < 640) { outp = Cb2; bp = bias2; ostride = 128; oc0 = n0 - 512; }
        else               { outp = Cb3; bp = bias3; ostride = 256; oc0 = n0 - 640; }
#pragma unroll
        for (int j = 0; j < NT; j++) {
            int cl = oc0 + wn0 + j*8 + 2*tig;
            float b0 = bp[cl], b1 = bp[cl+1];
#pragma unroll
            for (int i = 0; i < MT; i++) {
                acc[i][j][0] += b0; acc[i][j][1] += b1;
                acc[i][j][2] += b0; acc[i][j][3] += b1;
            }
        }
#pragma unroll
        for (int i = 0; i < MT; i++) {
            int r0 = m0 + i*16 + g, r1 = r0 + 8;
#pragma unroll
            for (int j = 0; j < NT; j++) {
                int cl = oc0 + wn0 + j*8 + 2*tig;
                *(uint32_t*)&outp[(size_t)r0*ostride + cl] =
                    f2bf2(tanhf(acc[i][j][0]), tanhf(acc[i][j][1]));
                *(uint32_t*)&outp[(size_t)r1*ostride + cl] =
                    f2bf2(tanhf(acc[i][j][2]), tanhf(acc[i][j][3]));
            }
        }
    }
}

// ---------------------------------------------------------------------------
// alv kernel: attn + softmax + wctx. PASS1 reads bf16 qm.
// ---------------------------------------------------------------------------
template<int PASS>
__global__ void __launch_bounds__(256) alv_kernel(
        const float* __restrict__ img, const float* __restrict__ cap,
        const int* __restrict__ lens)
{
    extern __shared__ float sm[];
    float* sImg = sm;
    float* sA   = sImg + RR*DD;
    float* sAT  = sA + RR*WW;
    float* sA2  = sAT + WW*RR;
    float* sRed = sA2 + RR*WW;

    const int b = blockIdx.x;
    const int c = b / NN, n = b % NN;
    const int tid = threadIdx.x, lane = tid & 31, wid = tid >> 5;
    const int len = lens[c];

    {
        const float4* gi = (const float4*)(img + (size_t)n * RR * DD);
        float4* si = (float4*)sImg;
        for (int i = tid; i < RR*DD/4; i += 256) si[i] = gi[i];
    }
    __syncthreads();

    for (int wi = 0; wi < 3; wi++) {
        int w = wid + wi * 8;
        float4 cr4[8];
        if (PASS == 0) {
            const float* capp = cap + ((size_t)c*WW + w)*DD;
#pragma unroll
            for (int k = 0; k < 8; k++)
                cr4[k] = *(const float4*)(capp + k*128 + lane*4);
        } else {
            const __nv_bfloat16* qp = g_qmb + ((size_t)b*WW + w)*DD;
#pragma unroll
            for (int k = 0; k < 8; k++) {
                uint2 v = *(const uint2*)(qp + k*128 + lane*4);
                float2 ab = __bfloat1622float2(*(__nv_bfloat162*)&v.x);
                float2 cd = __bfloat1622float2(*(__nv_bfloat162*)&v.y);
                cr4[k] = make_float4(ab.x, ab.y, cd.x, cd.y);
            }
        }
        for (int r = 0; r < RR; r += 2) {
            float a0 = 0.f, a1 = 0.f;
#pragma unroll
            for (int k = 0; k < 8; k++) {
                float4 i0 = *(const float4*)(sImg + r*DD + k*128 + lane*4);
                float4 i1 = *(const float4*)(sImg + (r+1)*DD + k*128 + lane*4);
                a0 = fmaf(cr4[k].x, i0.x, a0); a0 = fmaf(cr4[k].y, i0.y, a0);
                a0 = fmaf(cr4[k].z, i0.z, a0); a0 = fmaf(cr4[k].w, i0.w, a0);
                a1 = fmaf(cr4[k].x, i1.x, a1); a1 = fmaf(cr4[k].y, i1.y, a1);
                a1 = fmaf(cr4[k].z, i1.z, a1); a1 = fmaf(cr4[k].w, i1.w, a1);
            }
            a0 = warp_sum(a0); a1 = warp_sum(a1);
            if (lane == 0) { sA[r*WW + w] = a0; sA[(r+1)*WW + w] = a1; }
        }
    }
    __syncthreads();

    if (tid < RR) {
        int r = tid;
        float vals[WW];
        float ss = 0.f;
#pragma unroll
        for (int w = 0; w < WW; w++) {
            float v = sA[r*WW + w];
            v = (v >= 0.f) ? v : 0.1f * v;
            if (w >= len) v = 0.f;
            vals[w] = v;
            ss += v * v;
        }
        float f = 1.f / (sqrtf(ss) + 1e-8f);
#pragma unroll
        for (int w = 0; w < WW; w++) sAT[w*RR + r] = vals[w] * f;
    }
    __syncthreads();

    if (tid < WW) {
        int w = tid;
        float smo = (PASS == 0) ? 9.f : g_smooth[(size_t)b*WW + w];
        float m = -1e30f;
        for (int r = 0; r < RR; r++) { float v = sAT[w*RR + r]*smo; if (v > m) m = v; }
        float s = 0.f;
        for (int r = 0; r < RR; r++) {
            float e = expf(sAT[w*RR + r]*smo - m);
            sAT[w*RR + r] = e; s += e;
        }
        float inv = 1.f / s;
        for (int r = 0; r < RR; r++) sA2[r*WW + w] = sAT[w*RR + r] * inv;
    }
    __syncthreads();

    {
        float psq[WW];
#pragma unroll
        for (int w = 0; w < WW; w++) psq[w] = 0.f;
        for (int cidx = 0; cidx < 4; cidx++) {
            int d = cidx*256 + tid;
            float acc[WW];
#pragma unroll
            for (int w = 0; w < WW; w++) acc[w] = 0.f;
            for (int r = 0; r < RR; r++) {
                float iv = sImg[r*DD + d];
                const float4* ap = (const float4*)(sA2 + r*WW);
#pragma unroll
                for (int q = 0; q < 6; q++) {
                    float4 a4 = ap[q];
                    acc[q*4+0] = fmaf(a4.x, iv, acc[q*4+0]);
                    acc[q*4+1] = fmaf(a4.y, iv, acc[q*4+1]);
                    acc[q*4+2] = fmaf(a4.z, iv, acc[q*4+2]);
                    acc[q*4+3] = fmaf(a4.w, iv, acc[q*4+3]);
                }
            }
#pragma unroll
            for (int w = 0; w < WW; w++) {
                psq[w] = fmaf(acc[w], acc[w], psq[w]);
                g_wc[((size_t)b*WW + w)*DD + d] = __float2bfloat16(acc[w]);
            }
        }
#pragma unroll
        for (int w = 0; w < WW; w++) {
            float v = warp_sum(psq[w]);
            if (lane == 0) sRed[w*8 + wid] = v;
        }
    }
    __syncthreads();
    if (tid < WW) {
        float s = 0.f;
#pragma unroll
        for (int k = 0; k < 8; k++) s += sRed[tid*8 + k];
        g_fac[(size_t)b*WW + tid] = 1.f / (sqrtf(s) + 1e-8f);
    }
}

// ---------------------------------------------------------------------------
__global__ void mean_kernel(const int* __restrict__ lens)
{
    int b = blockIdx.x;
    int c = b / NN;
    int t = threadIdx.x;
    int len = lens[c];
    float inv = 1.f / (float)len;
    const float* p = g_sim_mid + (size_t)b*WW*SS + t;
    float s = 0.f;
    for (int w = 0; w < len; w++) s += p[(size_t)w * SS];
    g_higA[(size_t)b*SS + t] = s * inv;
}

__global__ void smooth_kernel(const float* __restrict__ w2, const float* __restrict__ b2)
{
    int wid = threadIdx.x >> 5, lane = threadIdx.x & 31;
    size_t r = (size_t)blockIdx.x * 8 + wid;
    const __nv_bfloat16* h = g_hsm + r * 128;
    float a = 0.f;
#pragma unroll
    for (int k = 0; k < 4; k++)
        a = fmaf(__bfloat162float(h[lane + 32*k]), w2[lane + 32*k], a);
    a = warp_sum(a);
    if (lane == 0) {
        float v = a + b2[0] + 9.0f;
        g_smooth[r] = v > 0.f ? v : 0.f;
    }
}

// ---------------------------------------------------------------------------
__global__ void __launch_bounds__(256) rar_kernel(
        const int* __restrict__ lens,
        const float* __restrict__ qw, const float* __restrict__ qb,
        const float* __restrict__ vw, const float* __restrict__ vb,
        const __nv_bfloat16* __restrict__ kt, int dir)
{
    extern __shared__ float sm[];
    float* sMid = sm;
    float* sHig = sMid + WW*SS;
    float* sRed = sHig + SS;
    float* sLog = sRed + WW*8;
    float* sWgt = sLog + WW;
    float* sMisc= sWgt + WW;

    const int b = blockIdx.x;
    const int c = b / NN;
    const int tid = threadIdx.x, lane = tid & 31, wid = tid >> 5;
    const int len = lens[c];

    const float* hin = (dir == 0) ? g_higA : g_higB;
    float*       hout= (dir == 0) ? g_higB : g_higA;

    {
        const float4* gm = (const float4*)(g_sim_mid + (size_t)b*WW*SS);
        float4* s4 = (float4*)sMid;
        for (int i = tid; i < WW*SS/4; i += 256) s4[i] = gm[i];
    }
    sHig[tid] = hin[(size_t)b*SS + tid];
    __syncthreads();

    float hv;
    {
        float acc = qb[tid];
        const float* wp = qw + tid;
#pragma unroll 4
        for (int s0 = 0; s0 < SS/4; s0++) {
            float4 h4 = *(const float4*)(sHig + s0*4);
            acc = fmaf(h4.x, wp[(size_t)(s0*4+0)*SS], acc);
            acc = fmaf(h4.y, wp[(size_t)(s0*4+1)*SS], acc);
            acc = fmaf(h4.z, wp[(size_t)(s0*4+2)*SS], acc);
            acc = fmaf(h4.w, wp[(size_t)(s0*4+3)*SS], acc);
        }
        hv = tanhf(acc) * vw[tid];
    }

    {
        const __nv_bfloat16* ktp = kt + (size_t)b*WW*SS + tid;
        float pv[WW];
#pragma unroll
        for (int w = 0; w < WW; w++)
            pv[w] = __bfloat162float(ktp[(size_t)w*SS]) * hv;
#pragma unroll
        for (int w = 0; w < WW; w++) {
            float v = warp_sum(pv[w]);
            if (lane == 0) sRed[w*8 + wid] = v;
        }
    }
    __syncthreads();
    if (tid < WW) {
        float s = 0.f;
#pragma unroll
        for (int k = 0; k < 8; k++) s += sRed[tid*8 + k];
        s += vb[0];
        if (tid >= len) s = -1e30f;
        sLog[tid] = s;
    }
    __syncthreads();
    if (tid == 0) {
        float m = -1e30f;
        for (int w = 0; w < WW; w++) m = fmaxf(m, sLog[w]);
        float s = 0.f;
        for (int w = 0; w < WW; w++) { float e = expf(sLog[w] - m); sWgt[w] = e; s += e; }
        float inv = 1.f / s;
        for (int w = 0; w < WW; w++) sWgt[w] *= inv;
    }
    __syncthreads();

    float o = 0.f;
#pragma unroll
    for (int w = 0; w < WW; w++) o = fmaf(sWgt[w], sMid[w*SS + tid], o);
    float sq = warp_sum(o * o);
    if (lane == 0) sRed[wid] = sq;
    __syncthreads();
    if (tid == 0) {
        float tot = 0.f;
#pragma unroll
        for (int k = 0; k < 8; k++) tot += sRed[k];
        sMisc[0] = 1.f / (sqrtf(tot) + 1e-8f);
    }
    __syncthreads();
    hout[(size_t)b*SS + tid] = o * sMisc[0];
}

// ---------------------------------------------------------------------------
__global__ void final_kernel(const float* __restrict__ ew, const float* __restrict__ eb,
                             float* __restrict__ out)
{
    int gw = (blockIdx.x * blockDim.x + threadIdx.x) >> 5;
    int lane = threadIdx.x & 31;
    int nwarps = (gridDim.x * blockDim.x) >> 5;
    for (int b = gw; b < CC*NN; b += nwarps) {
        const float* h = g_higA + (size_t)b*SS;
        float a = 0.f;
#pragma unroll
        for (int k = 0; k < 8; k++) a = fmaf(h[lane + k*32], ew[lane + k*32], a);
        a = warp_sum(a);
        if (lane == 0) {
            float v = a + eb[0];
            int c = b / NN, n = b % NN;
            out[n*CC + c] = 1.f / (1.f + expf(-v));
        }
    }
}

// ---------------------------------------------------------------------------
extern "C" void kernel_launch(void* const* d_in, const int* in_sizes, int n_in,
                              void* d_out, int out_size)
{
    const float* img  = (const float*)d_in[0];
    const float* cap  = (const float*)d_in[1];
    const int*   lens = (const int*)  d_in[2];
    const float* alvw = (const float*)d_in[3];
    const float* alvb = (const float*)d_in[4];
    const float* qw   = (const float*)d_in[5];
    const float* qb   = (const float*)d_in[6];
    const float* kw   = (const float*)d_in[7];
    const float* kb   = (const float*)d_in[8];
    const float* vw   = (const float*)d_in[9];
    const float* vb   = (const float*)d_in[10];
    const float* smw1 = (const float*)d_in[11];
    const float* smb1 = (const float*)d_in[12];
    const float* smw2 = (const float*)d_in[13];
    const float* smb2 = (const float*)d_in[14];
    const float* mxw1 = (const float*)d_in[15];
    const float* mxb1 = (const float*)d_in[16];
    const float* mxw2 = (const float*)d_in[17];
    const float* mxb2 = (const float*)d_in[18];
    const float* ew   = (const float*)d_in[19];
    const float* eb   = (const float*)d_in[20];
    float* out = (float*)d_out;

    float *pMid, *pFac;
    __nv_bfloat16 *pH, *pHsm, *pWbf, *pWc, *pKt, *pQm;
    cudaGetSymbolAddress((void**)&pMid, g_sim_mid);
    cudaGetSymbolAddress((void**)&pQm,  g_qmb);
    cudaGetSymbolAddress((void**)&pWc,  g_wc);
    cudaGetSymbolAddress((void**)&pFac, g_fac);
    cudaGetSymbolAddress((void**)&pH,   g_h);
    cudaGetSymbolAddress((void**)&pHsm, g_hsm);
    cudaGetSymbolAddress((void**)&pWbf, g_wbf);
    cudaGetSymbolAddress((void**)&pKt,  g_kt);

    const size_t ALV_SMEM = (size_t)(RR*DD + RR*WW*3 + WW*8 + 16) * sizeof(float);
    const size_t RAR_SMEM = (size_t)(WW*SS + SS + WW*8 + WW + WW + 32) * sizeof(float);
    const size_t SM_ALVG = (size_t)(2*64*20 + 2*32*132)*4 + (64*8 + 64)*4;   // 46336
    const size_t SM_MLP  = (size_t)(2*64*20 + 2*32*68)*4 + (64*8 + 64)*4;    // 29952

    cudaFuncSetAttribute(alv_kernel<0>, cudaFuncAttributeMaxDynamicSharedMemorySize, (int)ALV_SMEM);
    cudaFuncSetAttribute(alv_kernel<1>, cudaFuncAttributeMaxDynamicSharedMemorySize, (int)ALV_SMEM);
    cudaFuncSetAttribute(gemm_bf16<64,256,1024,256,1,0,0>, cudaFuncAttributeMaxDynamicSharedMemorySize, (int)SM_ALVG);
    cudaFuncSetAttribute(gemm_bf16<64,128,256,896,0,3,1>,  cudaFuncAttributeMaxDynamicSharedMemorySize, (int)SM_MLP);
    cudaFuncSetAttribute(gemm_bf16<64,128,512,1024,2,2,1>, cudaFuncAttributeMaxDynamicSharedMemorySize, (int)SM_MLP);
    cudaFuncSetAttribute(gemm_bf16<64,128,256,256,0,1,1>,  cudaFuncAttributeMaxDynamicSharedMemorySize, (int)SM_MLP);

    const int B = CC * NN;
    const int MB64 = MTOT / 64;  // 864

    // weight conversion
    cvtw_kernel<<<(524288/4+255)/256, 256>>>(alvw, pWbf + OFF_ALV0, 524288/4);
    cvtw_kernel<<<(524288/4+255)/256, 256>>>(mxw2, pWbf + OFF_MX2, 524288/4);
    cvtw_kernel<<<(65536/4+255)/256, 256>>>(kw + SS*SS, pWbf + OFF_KW1, 65536/4);
    cvtw_str<<<(131072/4+255)/256, 256>>>(mxw1, pWbf + OFF_WMLP, 512, 896, 0,   131072/4);
    cvtw_str<<<(32768/4+255)/256, 256>>>(smw1, pWbf + OFF_WMLP, 128, 896, 512, 32768/4);
    cvtw_str<<<(65536/4+255)/256, 256>>>(kw,   pWbf + OFF_WMLP, 256, 896, 640, 65536/4);

    // ---- pass 0 ----
    alv_kernel<0><<<B, 256, ALV_SMEM>>>(img, cap, lens);
    gemm_bf16<64,256,1024,256,1,0,0><<<dim3(1,MB64), 256, SM_ALVG>>>(
        nullptr, pWc, pWbf + OFF_ALV0, alvb, nullptr, nullptr,
        pMid, nullptr, nullptr, nullptr, cap, pFac);
    mean_kernel<<<B, 256>>>(lens);
    gemm_bf16<64,128,256,896,0,3,1><<<dim3(7,MB64), 256, SM_MLP>>>(
        pMid, nullptr, pWbf + OFF_WMLP, mxb1, smb1, kb,
        nullptr, pH, pHsm, pKt, nullptr, nullptr);
    smooth_kernel<<<MTOT/8, 256>>>(smw2, smb2);
    gemm_bf16<64,128,512,1024,2,2,1><<<dim3(8,MB64), 256, SM_MLP>>>(
        nullptr, pH, pWbf + OFF_MX2, mxb2, nullptr, nullptr,
        nullptr, pQm, nullptr, nullptr, cap, nullptr);
    rar_kernel<<<B, 256, RAR_SMEM>>>(lens, qw, qb, vw, vb, pKt, 0);

    // ---- pass 1 ----
    alv_kernel<1><<<B, 256, ALV_SMEM>>>(img, cap, lens);
    gemm_bf16<64,256,1024,256,1,0,0><<<dim3(1,MB64), 256, SM_ALVG>>>(
        nullptr, pWc, pWbf + OFF_ALV1, alvb + SS, nullptr, nullptr,
        pMid, nullptr, nullptr, nullptr, cap, pFac);
    gemm_bf16<64,128,256,256,0,1,1><<<dim3(2,MB64), 256, SM_MLP>>>(
        pMid, nullptr, pWbf + OFF_KW1, kb + SS, nullptr, nullptr,
        nullptr, pKt, nullptr, nullptr, nullptr, nullptr);
    rar_kernel<<<B, 256, RAR_SMEM>>>(lens, qw + SS*SS, qb + SS, vw + SS, vb + 1, pKt, 1);

    final_kernel<<<9, 256>>>(ew, eb, out);
}

// round 9
// speedup vs baseline: 6.1751x; 1.0900x over previous
#include <cuda_runtime.h>
#include <cuda_bf16.h>
#include <math.h>
#include <stdint.h>

#define CC 48
#define NN 48
#define WW 24
#define RR 36
#define DD 1024
#define SS 256
#define MTOT (CC*NN*WW)   // 55296

// ---------------- scratch (device globals; no allocation allowed) ----------
__device__ __align__(16) __nv_bfloat16 g_smid[MTOT*SS];         // 28 MB (bf16 sim_mid)
__device__ __align__(16) float g_smooth[MTOT];
__device__ __align__(16) __nv_bfloat16 g_qmb[(size_t)MTOT*DD];  // 113 MB
__device__ __align__(16) __nv_bfloat16 g_wc[(size_t)MTOT*DD];   // 113 MB
__device__ __align__(16) float g_fac[MTOT];
__device__ __align__(16) __nv_bfloat16 g_h[(size_t)MTOT*512];   // 56 MB
__device__ __align__(16) __nv_bfloat16 g_hsm[(size_t)MTOT*128]; // 14 MB
__device__ __align__(16) __nv_bfloat16 g_kt[(size_t)MTOT*SS];   // 28 MB
__device__ __align__(16) __nv_bfloat16 g_wbf[1507328];          // weights bf16
__device__ __align__(16) float g_higA[CC*NN*SS];
__device__ __align__(16) float g_higB[CC*NN*SS];

#define OFF_ALV0 0
#define OFF_ALV1 262144
#define OFF_MX2  524288
#define OFF_KW1  1048576
#define OFF_WMLP 1114112

__device__ __forceinline__ float warp_sum(float v) {
#pragma unroll
    for (int o = 16; o; o >>= 1) v += __shfl_xor_sync(0xffffffffu, v, o);
    return v;
}
__device__ __forceinline__ uint32_t f2bf2(float lo, float hi) {
    uint32_t r; asm("cvt.rn.bf16x2.f32 %0, %1, %2;" : "=r"(r) : "f"(hi), "f"(lo)); return r;
}
__device__ __forceinline__ void ldsm4(uint32_t* r, uint32_t a) {
    asm volatile("ldmatrix.sync.aligned.m8n8.x4.shared.b16 {%0,%1,%2,%3},[%4];"
        : "=r"(r[0]),"=r"(r[1]),"=r"(r[2]),"=r"(r[3]) : "r"(a));
}
__device__ __forceinline__ void ldsm4t(uint32_t* r, uint32_t a) {
    asm volatile("ldmatrix.sync.aligned.m8n8.x4.trans.shared.b16 {%0,%1,%2,%3},[%4];"
        : "=r"(r[0]),"=r"(r[1]),"=r"(r[2]),"=r"(r[3]) : "r"(a));
}
__device__ __forceinline__ void mmabf(float* d, const uint32_t* a, const uint32_t* b) {
    asm volatile("mma.sync.aligned.m16n8k16.row.col.f32.bf16.bf16.f32 "
        "{%0,%1,%2,%3},{%4,%5,%6,%7},{%8,%9},{%0,%1,%2,%3};"
        : "+f"(d[0]),"+f"(d[1]),"+f"(d[2]),"+f"(d[3])
        : "r"(a[0]),"r"(a[1]),"r"(a[2]),"r"(a[3]),"r"(b[0]),"r"(b[1]));
}

// ---------------------------------------------------------------------------
__global__ void cvtw_kernel(const float* __restrict__ src, __nv_bfloat16* __restrict__ dst, int n4)
{
    int i = blockIdx.x * blockDim.x + threadIdx.x;
    if (i < n4) {
        float4 v = *(const float4*)(src + (size_t)i*4);
        uint2 o; o.x = f2bf2(v.x, v.y); o.y = f2bf2(v.z, v.w);
        *(uint2*)(dst + (size_t)i*4) = o;
    }
}
__global__ void cvtw_str(const float* __restrict__ src, __nv_bfloat16* __restrict__ dst,
                         int ncols, int dstride, int dcol0, int n4)
{
    int i = blockIdx.x * blockDim.x + threadIdx.x;
    if (i < n4) {
        float4 v = *(const float4*)(src + (size_t)i*4);
        int row = (i*4) / ncols, col = (i*4) % ncols;
        uint2 o; o.x = f2bf2(v.x, v.y); o.y = f2bf2(v.z, v.w);
        *(uint2*)(dst + (size_t)row*dstride + dcol0 + col) = o;
    }
}

// ---------------------------------------------------------------------------
// bf16 m16n8k16 GEMM. grid: x = N tiles, y = M tiles.
// AMODE 0: A fp32->cvt. 1: A=(cap-wc*fac)^2. 2: A bf16.
// EPI 0: +bias, l2norm full 256 row -> OUTBF? bf16 : fp32.
// EPI 1: +bias, tanh. EPI 2: +bias, tanh, clip(+1), *cap.
// EPI 3: fused MLP routing (tanh bf16 x3 outputs).
// ---------------------------------------------------------------------------
template<int M_BLK,int N_BLK,int K_DIM,int N_TOT,int AMODE,int EPI,int OUTBF>
__global__ void __launch_bounds__(256) gemm_bf16(
    const float* __restrict__ Af, const __nv_bfloat16* __restrict__ Ab,
    const __nv_bfloat16* __restrict__ Bw,
    const float* __restrict__ bias, const float* __restrict__ bias2, const float* __restrict__ bias3,
    float* __restrict__ Cf, __nv_bfloat16* __restrict__ Cb,
    __nv_bfloat16* __restrict__ Cb2, __nv_bfloat16* __restrict__ Cb3,
    const float* __restrict__ cap, const float* __restrict__ fac)
{
    constexpr int MT   = M_BLK/16;
    constexpr int NT   = N_BLK/64;
    constexpr int SAW  = 20;
    constexpr int SBW  = N_BLK/2 + 4;
    constexpr int ABUF = M_BLK*SAW;
    constexpr int BBUF = 32*SBW;
    constexpr int APASS = M_BLK/32;
    constexpr int BROWP = 2048/N_BLK;
    constexpr int BPASS = 32/BROWP;
    constexpr int KT   = K_DIM/32;

    extern __shared__ uint32_t dsm[];
    uint32_t* As = dsm;
    uint32_t* Bs = dsm + 2*ABUF;
    float* sRed  = (float*)(dsm + 2*ABUF + 2*BBUF);
    float* sFacR = sRed + M_BLK*8;

    const int m0 = blockIdx.y * M_BLK;
    const int n0 = blockIdx.x * N_BLK;
    const int tid = threadIdx.x, lane = tid & 31, wid = tid >> 5;
    const int g = lane >> 2, tig = lane & 3;
    const int wn0 = wid * (N_BLK/8);

    const int a_row = tid >> 3, a_c = (tid & 7) * 4;
    float facr[APASS]; int caprow[APASS];
    if (AMODE == 1) {
#pragma unroll
        for (int p = 0; p < APASS; p++) {
            int r = m0 + p*32 + a_row;
            facr[p] = fac[r];
            caprow[p] = (r/1152)*24 + (r%24);
        }
    }
    const int b_row = tid / (N_BLK/8), b_c = (tid % (N_BLK/8)) * 8;
    const __nv_bfloat16* Bptr = Bw + (size_t)b_row*N_TOT + n0 + b_c;

    uint32_t areg[2*APASS]; uint4 breg[BPASS];

    auto loadA = [&](int kt) {
#pragma unroll
        for (int p = 0; p < APASS; p++) {
            int r = m0 + p*32 + a_row;
            if (AMODE == 2) {
                uint2 v = *(const uint2*)(Ab + (size_t)r*K_DIM + kt*32 + a_c);
                areg[p*2] = v.x; areg[p*2+1] = v.y;
            } else if (AMODE == 0) {
                float4 v = *(const float4*)(Af + (size_t)r*K_DIM + kt*32 + a_c);
                areg[p*2]   = f2bf2(v.x, v.y);
                areg[p*2+1] = f2bf2(v.z, v.w);
            } else {
                uint2 wv2 = *(const uint2*)(Ab + (size_t)r*K_DIM + kt*32 + a_c);
                float2 w01 = __bfloat1622float2(*(__nv_bfloat162*)&wv2.x);
                float2 w23 = __bfloat1622float2(*(__nv_bfloat162*)&wv2.y);
                float4 cv = *(const float4*)(cap + (size_t)caprow[p]*K_DIM + kt*32 + a_c);
                float f = facr[p];
                float s0 = cv.x - w01.x*f; s0 *= s0;
                float s1 = cv.y - w01.y*f; s1 *= s1;
                float s2 = cv.z - w23.x*f; s2 *= s2;
                float s3 = cv.w - w23.y*f; s3 *= s3;
                areg[p*2]   = f2bf2(s0, s1);
                areg[p*2+1] = f2bf2(s2, s3);
            }
        }
    };
    auto stsA = [&](int buf) {
#pragma unroll
        for (int p = 0; p < APASS; p++)
            *(uint2*)(As + buf*ABUF + (p*32 + a_row)*SAW + (tid&7)*2) =
                make_uint2(areg[p*2], areg[p*2+1]);
    };
    auto loadB = [&](int kt) {
#pragma unroll
        for (int p = 0; p < BPASS; p++)
            breg[p] = *(const uint4*)(Bptr + (size_t)(kt*32 + p*BROWP)*N_TOT);
    };
    auto stsB = [&](int buf) {
#pragma unroll
        for (int p = 0; p < BPASS; p++)
            *(uint4*)(Bs + buf*BBUF + (b_row + p*BROWP)*SBW + (tid % (N_BLK/8))*4) = breg[p];
    };

    loadA(0); loadB(0);
    stsA(0);  stsB(0);
    __syncthreads();

    float acc[MT][NT][4];
#pragma unroll
    for (int i = 0; i < MT; i++)
#pragma unroll
        for (int j = 0; j < NT; j++)
#pragma unroll
            for (int k = 0; k < 4; k++) acc[i][j][k] = 0.f;

    uint32_t smA = (uint32_t)__cvta_generic_to_shared(As);
    uint32_t smB = (uint32_t)__cvta_generic_to_shared(Bs);
    const uint32_t aoff = (lane & 15)*(SAW*4) + (lane >> 4)*16;
    const uint32_t boff = ((lane & 7) + ((lane >> 3) & 1)*8)*(SBW*4)
                        + (wn0 + (lane >> 4)*8)*2;

    for (int kt = 0; kt < KT; kt++) {
        int cur = kt & 1;
        if (kt + 1 < KT) { loadA(kt+1); loadB(kt+1); }
        uint32_t Ab0 = smA + cur*(ABUF*4);
        uint32_t Bb0 = smB + cur*(BBUF*4);
#pragma unroll
        for (int ks = 0; ks < 2; ks++) {
            uint32_t af[MT][4], bf[NT][2];
#pragma unroll
            for (int i = 0; i < MT; i++)
                ldsm4(af[i], Ab0 + i*16*(SAW*4) + aoff + ks*32);
#pragma unroll
            for (int jp = 0; jp < NT/2; jp++) {
                uint32_t t[4];
                ldsm4t(t, Bb0 + ks*16*(SBW*4) + boff + jp*32);
                bf[2*jp][0] = t[0]; bf[2*jp][1] = t[1];
                bf[2*jp+1][0] = t[2]; bf[2*jp+1][1] = t[3];
            }
#pragma unroll
            for (int i = 0; i < MT; i++)
#pragma unroll
                for (int j = 0; j < NT; j++)
                    mmabf(acc[i][j], af[i], bf[j]);
        }
        if (kt + 1 < KT) { stsA((kt+1)&1); stsB((kt+1)&1); }
        __syncthreads();
    }

    if (EPI != 3) {
#pragma unroll
        for (int j = 0; j < NT; j++) {
            int coln = n0 + wn0 + j*8 + 2*tig;
            float b0 = bias[coln], b1 = bias[coln+1];
#pragma unroll
            for (int i = 0; i < MT; i++) {
                acc[i][j][0] += b0; acc[i][j][1] += b1;
                acc[i][j][2] += b0; acc[i][j][3] += b1;
            }
        }
    }

    if (EPI == 0) {
        float ps[MT][2];
#pragma unroll
        for (int i = 0; i < MT; i++) {
            ps[i][0] = 0.f; ps[i][1] = 0.f;
#pragma unroll
            for (int j = 0; j < NT; j++) {
                ps[i][0] += acc[i][j][0]*acc[i][j][0] + acc[i][j][1]*acc[i][j][1];
                ps[i][1] += acc[i][j][2]*acc[i][j][2] + acc[i][j][3]*acc[i][j][3];
            }
        }
#pragma unroll
        for (int i = 0; i < MT; i++)
#pragma unroll
            for (int h = 0; h < 2; h++) {
                ps[i][h] += __shfl_xor_sync(0xffffffffu, ps[i][h], 1);
                ps[i][h] += __shfl_xor_sync(0xffffffffu, ps[i][h], 2);
            }
        if (tig == 0) {
#pragma unroll
            for (int i = 0; i < MT; i++) {
                sRed[(i*16 + g    )*8 + wid] = ps[i][0];
                sRed[(i*16 + g + 8)*8 + wid] = ps[i][1];
            }
        }
        __syncthreads();
        if (tid < M_BLK) {
            float s = 0.f;
#pragma unroll
            for (int k = 0; k < 8; k++) s += sRed[tid*8 + k];
            sFacR[tid] = 1.f / (sqrtf(s) + 1e-8f);
        }
        __syncthreads();
#pragma unroll
        for (int i = 0; i < MT; i++) {
            float f0 = sFacR[i*16 + g], f1 = sFacR[i*16 + g + 8];
#pragma unroll
            for (int j = 0; j < NT; j++) {
                int coln = wn0 + j*8 + 2*tig;
                if (OUTBF) {
                    *(uint32_t*)&Cb[(size_t)(m0 + i*16 + g    )*N_TOT + coln] =
                        f2bf2(acc[i][j][0]*f0, acc[i][j][1]*f0);
                    *(uint32_t*)&Cb[(size_t)(m0 + i*16 + g + 8)*N_TOT + coln] =
                        f2bf2(acc[i][j][2]*f1, acc[i][j][3]*f1);
                } else {
                    *(float2*)&Cf[(size_t)(m0 + i*16 + g    )*N_TOT + coln] =
                        make_float2(acc[i][j][0]*f0, acc[i][j][1]*f0);
                    *(float2*)&Cf[(size_t)(m0 + i*16 + g + 8)*N_TOT + coln] =
                        make_float2(acc[i][j][2]*f1, acc[i][j][3]*f1);
                }
            }
        }
    } else if (EPI == 1) {
#pragma unroll
        for (int i = 0; i < MT; i++) {
            int r0 = m0 + i*16 + g, r1 = r0 + 8;
#pragma unroll
            for (int j = 0; j < NT; j++) {
                int coln = n0 + wn0 + j*8 + 2*tig;
                float v0 = tanhf(acc[i][j][0]), v1 = tanhf(acc[i][j][1]);
                float v2 = tanhf(acc[i][j][2]), v3 = tanhf(acc[i][j][3]);
                if (OUTBF) {
                    *(uint32_t*)&Cb[(size_t)r0*N_TOT + coln] = f2bf2(v0, v1);
                    *(uint32_t*)&Cb[(size_t)r1*N_TOT + coln] = f2bf2(v2, v3);
                } else {
                    *(float2*)&Cf[(size_t)r0*N_TOT + coln] = make_float2(v0, v1);
                    *(float2*)&Cf[(size_t)r1*N_TOT + coln] = make_float2(v2, v3);
                }
            }
        }
    } else if (EPI == 2) {
#pragma unroll
        for (int i = 0; i < MT; i++) {
            int r0 = m0 + i*16 + g, r1 = r0 + 8;
            int cr0 = (r0/1152)*24 + (r0%24);
            int cr1 = (r1/1152)*24 + (r1%24);
#pragma unroll
            for (int j = 0; j < NT; j++) {
                int coln = n0 + wn0 + j*8 + 2*tig;
                float m00 = fminf(fmaxf(tanhf(acc[i][j][0]) + 1.f, -1.f), 1.f);
                float m01 = fminf(fmaxf(tanhf(acc[i][j][1]) + 1.f, -1.f), 1.f);
                float m10 = fminf(fmaxf(tanhf(acc[i][j][2]) + 1.f, -1.f), 1.f);
                float m11 = fminf(fmaxf(tanhf(acc[i][j][3]) + 1.f, -1.f), 1.f);
                float2 c0 = *(const float2*)&cap[(size_t)cr0*DD + coln];
                float2 c1 = *(const float2*)&cap[(size_t)cr1*DD + coln];
                if (OUTBF) {
                    *(uint32_t*)&Cb[(size_t)r0*N_TOT + coln] = f2bf2(c0.x*m00, c0.y*m01);
                    *(uint32_t*)&Cb[(size_t)r1*N_TOT + coln] = f2bf2(c1.x*m10, c1.y*m11);
                } else {
                    *(float2*)&Cf[(size_t)r0*N_TOT + coln] = make_float2(c0.x*m00, c0.y*m01);
                    *(float2*)&Cf[(size_t)r1*N_TOT + coln] = make_float2(c1.x*m10, c1.y*m11);
                }
            }
        }
    } else {
        __nv_bfloat16* outp; const float* bp; int ostride, oc0;
        if (n0 < 512)      { outp = Cb;  bp = bias;  ostride = 512; oc0 = n0; }
        else if (n0 < 640) { outp = Cb2; bp = bias2; ostride = 128; oc0 = n0 - 512; }
        else               { outp = Cb3; bp = bias3; ostride = 256; oc0 = n0 - 640; }
#pragma unroll
        for (int j = 0; j < NT; j++) {
            int cl = oc0 + wn0 + j*8 + 2*tig;
            float b0 = bp[cl], b1 = bp[cl+1];
#pragma unroll
            for (int i = 0; i < MT; i++) {
                acc[i][j][0] += b0; acc[i][j][1] += b1;
                acc[i][j][2] += b0; acc[i][j][3] += b1;
            }
        }
#pragma unroll
        for (int i = 0; i < MT; i++) {
            int r0 = m0 + i*16 + g, r1 = r0 + 8;
#pragma unroll
            for (int j = 0; j < NT; j++) {
                int cl = oc0 + wn0 + j*8 + 2*tig;
                *(uint32_t*)&outp[(size_t)r0*ostride + cl] =
                    f2bf2(tanhf(acc[i][j][0]), tanhf(acc[i][j][1]));
                *(uint32_t*)&outp[(size_t)r1*ostride + cl] =
                    f2bf2(tanhf(acc[i][j][2]), tanhf(acc[i][j][3]));
            }
        }
    }
}

// ---------------------------------------------------------------------------
// alv kernel: fp32 attn + softmax, then bf16 mma wctx.
// A tile: softmaxed attn 32x48 bf16 (stride 56 bf16); B: img bf16 48x(1032) in-place.
// ---------------------------------------------------------------------------
template<int PASS>
__global__ void __launch_bounds__(256) alv_kernel(
        const float* __restrict__ img, const float* __restrict__ cap,
        const int* __restrict__ lens)
{
    constexpr int ARS = 28;   // A row stride in words (56 bf16)
    constexpr int BRS = 516;  // B row stride in words (1032 bf16)

    extern __shared__ float sm[];
    float* sImg = sm;                          // RR*DD fp32 (aliased bf16 padded after cvt)
    float* sA   = sImg + RR*DD;                // RR*WW
    float* sAT  = sA + RR*WW;                  // WW*RR
    uint32_t* sAbfW = (uint32_t*)(sAT + WW*RR);// 32*ARS = 896 words
    float* sRed = (float*)(sAbfW + 32*ARS);    // 32*8
    __nv_bfloat16* sAbf = (__nv_bfloat16*)sAbfW;
    __nv_bfloat16* sImgBf = (__nv_bfloat16*)sImg;

    const int b = blockIdx.x;
    const int c = b / NN, n = b % NN;
    const int tid = threadIdx.x, lane = tid & 31, wid = tid >> 5;
    const int g = lane >> 2, tig = lane & 3;
    const int len = lens[c];

    {
        const float4* gi = (const float4*)(img + (size_t)n * RR * DD);
        float4* si = (float4*)sImg;
        for (int i = tid; i < RR*DD/4; i += 256) si[i] = gi[i];
        for (int i = tid; i < 32*ARS; i += 256) sAbfW[i] = 0;  // zero A tile (incl pad)
    }
    __syncthreads();

    // ---- phase 1: attn[r][w] = <query_w, img_r> (fp32) ----
    for (int wi = 0; wi < 3; wi++) {
        int w = wid + wi * 8;
        float4 cr4[8];
        if (PASS == 0) {
            const float* capp = cap + ((size_t)c*WW + w)*DD;
#pragma unroll
            for (int k = 0; k < 8; k++)
                cr4[k] = *(const float4*)(capp + k*128 + lane*4);
        } else {
            const __nv_bfloat16* qp = g_qmb + ((size_t)b*WW + w)*DD;
#pragma unroll
            for (int k = 0; k < 8; k++) {
                uint2 v = *(const uint2*)(qp + k*128 + lane*4);
                float2 ab = __bfloat1622float2(*(__nv_bfloat162*)&v.x);
                float2 cd = __bfloat1622float2(*(__nv_bfloat162*)&v.y);
                cr4[k] = make_float4(ab.x, ab.y, cd.x, cd.y);
            }
        }
        for (int r = 0; r < RR; r += 2) {
            float a0 = 0.f, a1 = 0.f;
#pragma unroll
            for (int k = 0; k < 8; k++) {
                float4 i0 = *(const float4*)(sImg + r*DD + k*128 + lane*4);
                float4 i1 = *(const float4*)(sImg + (r+1)*DD + k*128 + lane*4);
                a0 = fmaf(cr4[k].x, i0.x, a0); a0 = fmaf(cr4[k].y, i0.y, a0);
                a0 = fmaf(cr4[k].z, i0.z, a0); a0 = fmaf(cr4[k].w, i0.w, a0);
                a1 = fmaf(cr4[k].x, i1.x, a1); a1 = fmaf(cr4[k].y, i1.y, a1);
                a1 = fmaf(cr4[k].z, i1.z, a1); a1 = fmaf(cr4[k].w, i1.w, a1);
            }
            a0 = warp_sum(a0); a1 = warp_sum(a1);
            if (lane == 0) { sA[r*WW + w] = a0; sA[(r+1)*WW + w] = a1; }
        }
    }
    __syncthreads();

    // ---- phase 2a: leaky relu, mask, l2norm over words (fp32) ----
    if (tid < RR) {
        int r = tid;
        float vals[WW];
        float ss = 0.f;
#pragma unroll
        for (int w = 0; w < WW; w++) {
            float v = sA[r*WW + w];
            v = (v >= 0.f) ? v : 0.1f * v;
            if (w >= len) v = 0.f;
            vals[w] = v;
            ss += v * v;
        }
        float f = 1.f / (sqrtf(ss) + 1e-8f);
#pragma unroll
        for (int w = 0; w < WW; w++) sAT[w*RR + r] = vals[w] * f;
    }
    __syncthreads();

    // ---- phase 2b: softmax over regions -> bf16 A tile [w][r] ----
    if (tid < WW) {
        int w = tid;
        float smo = (PASS == 0) ? 9.f : g_smooth[(size_t)b*WW + w];
        float m = -1e30f;
        for (int r = 0; r < RR; r++) { float v = sAT[w*RR + r]*smo; if (v > m) m = v; }
        float s = 0.f;
        float e_[RR];
        for (int r = 0; r < RR; r++) {
            float e = expf(sAT[w*RR + r]*smo - m);
            e_[r] = e; s += e;
        }
        float inv = 1.f / s;
        for (int r = 0; r < RR; r++)
            sAbf[w*(2*ARS) + r] = __float2bfloat16(e_[r] * inv);
    }
    __syncthreads();

    // ---- phase 2c: convert img fp32 -> padded bf16 in place ----
    for (int it = 0; it < 9; it++) {
        float4 v[4];
#pragma unroll
        for (int q = 0; q < 4; q++)
            v[q] = ((const float4*)sImg)[it*1024 + q*256 + tid];
        __syncthreads();
#pragma unroll
        for (int q = 0; q < 4; q++) {
            int fidx = (it*1024 + q*256 + tid) * 4;
            int r = fidx >> 10, col = fidx & 1023;
            uint2 o; o.x = f2bf2(v[q].x, v[q].y); o.y = f2bf2(v[q].z, v[q].w);
            *(uint2*)(sImgBf + r*(2*BRS)/2*2 + 0) = o;  // placeholder (replaced below)
        }
        // NOTE: correct write below
        __syncthreads();
        (void)0;
        // re-do writes properly (the loop above is replaced by this one)
#pragma unroll
        for (int q = 0; q < 4; q++) {
            int fidx = (it*1024 + q*256 + tid) * 4;
            int r = fidx >> 10, col = fidx & 1023;
            uint2 o; o.x = f2bf2(v[q].x, v[q].y); o.y = f2bf2(v[q].z, v[q].w);
            *(uint2*)(sImgBf + (size_t)r*1032 + col) = o;
        }
        __syncthreads();
    }
    // zero B pad rows 36..47 (first 1024 cols)
    for (int i = tid; i < 12*256; i += 256) {
        int r = 36 + i/256, col = (i%256)*4;
        *(uint2*)(sImgBf + (size_t)r*1032 + col) = make_uint2(0,0);
    }
    __syncthreads();

    // ---- phase 3: wctx = A(32x48) @ B(48x1024) via bf16 mma ----
    {
        uint32_t smAttn = (uint32_t)__cvta_generic_to_shared(sAbf);
        uint32_t smImgB = (uint32_t)__cvta_generic_to_shared(sImgBf);
        const uint32_t aoff = (lane & 15)*(ARS*4) + (lane >> 4)*16;
        const uint32_t bRowSel = ((lane & 7) + ((lane >> 3) & 1)*8)*(BRS*4);
        const uint32_t bColSel = (lane >> 4)*8;

        float psq[2][2] = {{0.f,0.f},{0.f,0.f}};
        for (int half = 0; half < 2; half++) {
            float acc[2][8][4];
#pragma unroll
            for (int i = 0; i < 2; i++)
#pragma unroll
                for (int j = 0; j < 8; j++)
#pragma unroll
                    for (int k = 0; k < 4; k++) acc[i][j][k] = 0.f;
#pragma unroll
            for (int ks = 0; ks < 3; ks++) {
                uint32_t af0[4], af1[4];
                ldsm4(af0, smAttn + aoff + ks*32);
                ldsm4(af1, smAttn + 16*(ARS*4) + aoff + ks*32);
#pragma unroll
                for (int jp = 0; jp < 4; jp++) {
                    int ncol = half*512 + wid*64 + jp*16 + bColSel;
                    uint32_t t[4];
                    ldsm4t(t, smImgB + ks*16*(BRS*4) + bRowSel + ncol*2);
                    mmabf(acc[0][2*jp],   af0, t);
                    mmabf(acc[0][2*jp+1], af0, t+2);
                    mmabf(acc[1][2*jp],   af1, t);
                    mmabf(acc[1][2*jp+1], af1, t+2);
                }
            }
#pragma unroll
            for (int i = 0; i < 2; i++) {
                int r0 = i*16 + g, r1 = r0 + 8;
#pragma unroll
                for (int j = 0; j < 8; j++) {
                    int coln = half*512 + wid*64 + j*8 + 2*tig;
                    float v0 = acc[i][j][0], v1 = acc[i][j][1];
                    float v2 = acc[i][j][2], v3 = acc[i][j][3];
                    psq[i][0] += v0*v0 + v1*v1;
                    psq[i][1] += v2*v2 + v3*v3;
                    if (r0 < WW)
                        *(uint32_t*)&g_wc[((size_t)b*WW + r0)*DD + coln] = f2bf2(v0, v1);
                    if (r1 < WW)
                        *(uint32_t*)&g_wc[((size_t)b*WW + r1)*DD + coln] = f2bf2(v2, v3);
                }
            }
        }
#pragma unroll
        for (int i = 0; i < 2; i++)
#pragma unroll
            for (int h = 0; h < 2; h++) {
                psq[i][h] += __shfl_xor_sync(0xffffffffu, psq[i][h], 1);
                psq[i][h] += __shfl_xor_sync(0xffffffffu, psq[i][h], 2);
            }
        if (tig == 0) {
#pragma unroll
            for (int i = 0; i < 2; i++) {
                sRed[(i*16 + g    )*8 + wid] = psq[i][0];
                sRed[(i*16 + g + 8)*8 + wid] = psq[i][1];
            }
        }
        __syncthreads();
        if (tid < WW) {
            float s = 0.f;
#pragma unroll
            for (int k = 0; k < 8; k++) s += sRed[tid*8 + k];
            g_fac[(size_t)b*WW + tid] = 1.f / (sqrtf(s) + 1e-8f);
        }
    }
}

// ---------------------------------------------------------------------------
__global__ void mean_kernel(const int* __restrict__ lens)
{
    int b = blockIdx.x;
    int c = b / NN;
    int t = threadIdx.x;
    int len = lens[c];
    float inv = 1.f / (float)len;
    const __nv_bfloat16* p = g_smid + (size_t)b*WW*SS + t;
    float s = 0.f;
    for (int w = 0; w < len; w++) s += __bfloat162float(p[(size_t)w * SS]);
    g_higA[(size_t)b*SS + t] = s * inv;
}

__global__ void smooth_kernel(const float* __restrict__ w2, const float* __restrict__ b2)
{
    int wid = threadIdx.x >> 5, lane = threadIdx.x & 31;
    size_t r = (size_t)blockIdx.x * 8 + wid;
    const __nv_bfloat16* h = g_hsm + r * 128;
    float a = 0.f;
#pragma unroll
    for (int k = 0; k < 4; k++)
        a = fmaf(__bfloat162float(h[lane + 32*k]), w2[lane + 32*k], a);
    a = warp_sum(a);
    if (lane == 0) {
        float v = a + b2[0] + 9.0f;
        g_smooth[r] = v > 0.f ? v : 0.f;
    }
}

// ---------------------------------------------------------------------------
__global__ void __launch_bounds__(256) rar_kernel(
        const int* __restrict__ lens,
        const float* __restrict__ qw, const float* __restrict__ qb,
        const float* __restrict__ vw, const float* __restrict__ vb,
        const __nv_bfloat16* __restrict__ kt, int dir)
{
    extern __shared__ float sm[];
    __nv_bfloat16* sMid = (__nv_bfloat16*)sm;        // WW*SS bf16 = 3072 floats worth
    float* sHig = sm + WW*SS/2;
    float* sRed = sHig + SS;
    float* sLog = sRed + WW*8;
    float* sWgt = sLog + WW;
    float* sMisc= sWgt + WW;

    const int b = blockIdx.x;
    const int c = b / NN;
    const int tid = threadIdx.x, lane = tid & 31, wid = tid >> 5;
    const int len = lens[c];

    const float* hin = (dir == 0) ? g_higA : g_higB;
    float*       hout= (dir == 0) ? g_higB : g_higA;

    {
        const uint4* gm = (const uint4*)(g_smid + (size_t)b*WW*SS);
        uint4* s4 = (uint4*)sMid;
        for (int i = tid; i < WW*SS/8; i += 256) s4[i] = gm[i];
    }
    sHig[tid] = hin[(size_t)b*SS + tid];
    __syncthreads();

    float hv;
    {
        float acc = qb[tid];
        const float* wp = qw + tid;
#pragma unroll 4
        for (int s0 = 0; s0 < SS/4; s0++) {
            float4 h4 = *(const float4*)(sHig + s0*4);
            acc = fmaf(h4.x, wp[(size_t)(s0*4+0)*SS], acc);
            acc = fmaf(h4.y, wp[(size_t)(s0*4+1)*SS], acc);
            acc = fmaf(h4.z, wp[(size_t)(s0*4+2)*SS], acc);
            acc = fmaf(h4.w, wp[(size_t)(s0*4+3)*SS], acc);
        }
        hv = tanhf(acc) * vw[tid];
    }

    {
        const __nv_bfloat16* ktp = kt + (size_t)b*WW*SS + tid;
        float pv[WW];
#pragma unroll
        for (int w = 0; w < WW; w++)
            pv[w] = __bfloat162float(ktp[(size_t)w*SS]) * hv;
#pragma unroll
        for (int w = 0; w < WW; w++) {
            float v = warp_sum(pv[w]);
            if (lane == 0) sRed[w*8 + wid] = v;
        }
    }
    __syncthreads();
    if (tid < WW) {
        float s = 0.f;
#pragma unroll
        for (int k = 0; k < 8; k++) s += sRed[tid*8 + k];
        s += vb[0];
        if (tid >= len) s = -1e30f;
        sLog[tid] = s;
    }
    __syncthreads();
    if (tid == 0) {
        float m = -1e30f;
        for (int w = 0; w < WW; w++) m = fmaxf(m, sLog[w]);
        float s = 0.f;
        for (int w = 0; w < WW; w++) { float e = expf(sLog[w] - m); sWgt[w] = e; s += e; }
        float inv = 1.f / s;
        for (int w = 0; w < WW; w++) sWgt[w] *= inv;
    }
    __syncthreads();

    float o = 0.f;
#pragma unroll
    for (int w = 0; w < WW; w++)
        o = fmaf(sWgt[w], __bfloat162float(sMid[w*SS + tid]), o);
    float sq = warp_sum(o * o);
    if (lane == 0) sRed[wid] = sq;
    __syncthreads();
    if (tid == 0) {
        float tot = 0.f;
#pragma unroll
        for (int k = 0; k < 8; k++) tot += sRed[k];
        sMisc[0] = 1.f / (sqrtf(tot) + 1e-8f);
    }
    __syncthreads();
    hout[(size_t)b*SS + tid] = o * sMisc[0];
}

// ---------------------------------------------------------------------------
__global__ void final_kernel(const float* __restrict__ ew, const float* __restrict__ eb,
                             float* __restrict__ out)
{
    int gw = (blockIdx.x * blockDim.x + threadIdx.x) >> 5;
    int lane = threadIdx.x & 31;
    int nwarps = (gridDim.x * blockDim.x) >> 5;
    for (int b = gw; b < CC*NN; b += nwarps) {
        const float* h = g_higA + (size_t)b*SS;
        float a = 0.f;
#pragma unroll
        for (int k = 0; k < 8; k++) a = fmaf(h[lane + k*32], ew[lane + k*32], a);
        a = warp_sum(a);
        if (lane == 0) {
            float v = a + eb[0];
            int c = b / NN, n = b % NN;
            out[n*CC + c] = 1.f / (1.f + expf(-v));
        }
    }
}

// ---------------------------------------------------------------------------
extern "C" void kernel_launch(void* const* d_in, const int* in_sizes, int n_in,
                              void* d_out, int out_size)
{
    const float* img  = (const float*)d_in[0];
    const float* cap  = (const float*)d_in[1];
    const int*   lens = (const int*)  d_in[2];
    const float* alvw = (const float*)d_in[3];
    const float* alvb = (const float*)d_in[4];
    const float* qw   = (const float*)d_in[5];
    const float* qb   = (const float*)d_in[6];
    const float* kw   = (const float*)d_in[7];
    const float* kb   = (const float*)d_in[8];
    const float* vw   = (const float*)d_in[9];
    const float* vb   = (const float*)d_in[10];
    const float* smw1 = (const float*)d_in[11];
    const float* smb1 = (const float*)d_in[12];
    const float* smw2 = (const float*)d_in[13];
    const float* smb2 = (const float*)d_in[14];
    const float* mxw1 = (const float*)d_in[15];
    const float* mxb1 = (const float*)d_in[16];
    const float* mxw2 = (const float*)d_in[17];
    const float* mxb2 = (const float*)d_in[18];
    const float* ew   = (const float*)d_in[19];
    const float* eb   = (const float*)d_in[20];
    float* out = (float*)d_out;

    float *pFac;
    __nv_bfloat16 *pH, *pHsm, *pWbf, *pWc, *pKt, *pQm, *pSmid;
    cudaGetSymbolAddress((void**)&pSmid, g_smid);
    cudaGetSymbolAddress((void**)&pQm,  g_qmb);
    cudaGetSymbolAddress((void**)&pWc,  g_wc);
    cudaGetSymbolAddress((void**)&pFac, g_fac);
    cudaGetSymbolAddress((void**)&pH,   g_h);
    cudaGetSymbolAddress((void**)&pHsm, g_hsm);
    cudaGetSymbolAddress((void**)&pWbf, g_wbf);
    cudaGetSymbolAddress((void**)&pKt,  g_kt);

    const size_t ALV_SMEM = (size_t)(RR*DD + RR*WW*2 + 32*28 + 32*8 + 32) * sizeof(float);
    const size_t RAR_SMEM = (size_t)(WW*SS/2 + SS + WW*8 + WW + WW + 32) * sizeof(float);
    const size_t SM_ALVG = (size_t)(2*64*20 + 2*32*132)*4 + (64*8 + 64)*4;
    const size_t SM_MLP  = (size_t)(2*64*20 + 2*32*68)*4 + (64*8 + 64)*4;

    cudaFuncSetAttribute(alv_kernel<0>, cudaFuncAttributeMaxDynamicSharedMemorySize, (int)ALV_SMEM);
    cudaFuncSetAttribute(alv_kernel<1>, cudaFuncAttributeMaxDynamicSharedMemorySize, (int)ALV_SMEM);
    cudaFuncSetAttribute(gemm_bf16<64,256,1024,256,1,0,1>, cudaFuncAttributeMaxDynamicSharedMemorySize, (int)SM_ALVG);
    cudaFuncSetAttribute(gemm_bf16<64,128,256,896,2,3,1>,  cudaFuncAttributeMaxDynamicSharedMemorySize, (int)SM_MLP);
    cudaFuncSetAttribute(gemm_bf16<64,128,512,1024,2,2,1>, cudaFuncAttributeMaxDynamicSharedMemorySize, (int)SM_MLP);
    cudaFuncSetAttribute(gemm_bf16<64,128,256,256,2,1,1>,  cudaFuncAttributeMaxDynamicSharedMemorySize, (int)SM_MLP);

    const int B = CC * NN;
    const int MB64 = MTOT / 64;

    cvtw_kernel<<<(524288/4+255)/256, 256>>>(alvw, pWbf + OFF_ALV0, 524288/4);
    cvtw_kernel<<<(524288/4+255)/256, 256>>>(mxw2, pWbf + OFF_MX2, 524288/4);
    cvtw_kernel<<<(65536/4+255)/256, 256>>>(kw + SS*SS, pWbf + OFF_KW1, 65536/4);
    cvtw_str<<<(131072/4+255)/256, 256>>>(mxw1, pWbf + OFF_WMLP, 512, 896, 0,   131072/4);
    cvtw_str<<<(32768/4+255)/256, 256>>>(smw1, pWbf + OFF_WMLP, 128, 896, 512, 32768/4);
    cvtw_str<<<(65536/4+255)/256, 256>>>(kw,   pWbf + OFF_WMLP, 256, 896, 640, 65536/4);

    // ---- pass 0 ----
    alv_kernel<0><<<B, 256, ALV_SMEM>>>(img, cap, lens);
    gemm_bf16<64,256,1024,256,1,0,1><<<dim3(1,MB64), 256, SM_ALVG>>>(
        nullptr, pWc, pWbf + OFF_ALV0, alvb, nullptr, nullptr,
        nullptr, pSmid, nullptr, nullptr, cap, pFac);
    mean_kernel<<<B, 256>>>(lens);
    gemm_bf16<64,128,256,896,2,3,1><<<dim3(7,MB64), 256, SM_MLP>>>(
        nullptr, pSmid, pWbf + OFF_WMLP, mxb1, smb1, kb,
        nullptr, pH, pHsm, pKt, nullptr, nullptr);
    smooth_kernel<<<MTOT/8, 256>>>(smw2, smb2);
    gemm_bf16<64,128,512,1024,2,2,1><<<dim3(8,MB64), 256, SM_MLP>>>(
        nullptr, pH, pWbf + OFF_MX2, mxb2, nullptr, nullptr,
        nullptr, pQm, nullptr, nullptr, cap, nullptr);
    rar_kernel<<<B, 256, RAR_SMEM>>>(lens, qw, qb, vw, vb, pKt, 0);

    // ---- pass 1 ----
    alv_kernel<1><<<B, 256, ALV_SMEM>>>(img, cap, lens);
    gemm_bf16<64,256,1024,256,1,0,1><<<dim3(1,MB64), 256, SM_ALVG>>>(
        nullptr, pWc, pWbf + OFF_ALV1, alvb + SS, nullptr, nullptr,
        nullptr, pSmid, nullptr, nullptr, cap, pFac);
    gemm_bf16<64,128,256,256,2,1,1><<<dim3(2,MB64), 256, SM_MLP>>>(
        nullptr, pSmid, pWbf + OFF_KW1, kb + SS, nullptr, nullptr,
        nullptr, pKt, nullptr, nullptr, nullptr, nullptr);
    rar_kernel<<<B, 256, RAR_SMEM>>>(lens, qw + SS*SS, qb + SS, vw + SS, vb + 1, pKt, 1);

    final_kernel<<<9, 256>>>(ew, eb, out);
}

// round 10
// speedup vs baseline: 8.7272x; 1.4133x over previous
#include <cuda_runtime.h>
#include <cuda_bf16.h>
#include <math.h>
#include <stdint.h>

#define CC 48
#define NN 48
#define WW 24
#define RR 36
#define DD 1024
#define SS 256
#define MTOT (CC*NN*WW)   // 55296

// ---------------- scratch (device globals; no allocation allowed) ----------
__device__ __align__(16) __nv_bfloat16 g_smid[MTOT*SS];         // 28 MB
__device__ __align__(16) float g_smooth[MTOT];
__device__ __align__(16) __nv_bfloat16 g_qmb[(size_t)MTOT*DD];  // 113 MB
__device__ __align__(16) __nv_bfloat16 g_wc[(size_t)MTOT*DD];   // 113 MB
__device__ __align__(16) float g_fac[MTOT];
__device__ __align__(16) __nv_bfloat16 g_h[(size_t)MTOT*512];   // 56 MB
__device__ __align__(16) __nv_bfloat16 g_hsm[(size_t)MTOT*128]; // 14 MB
__device__ __align__(16) __nv_bfloat16 g_kt[(size_t)MTOT*SS];   // 28 MB
__device__ __align__(16) __nv_bfloat16 g_wbf[1507328];          // weights bf16
__device__ __align__(16) float g_higA[CC*NN*SS];
__device__ __align__(16) float g_higB[CC*NN*SS];

#define OFF_ALV0 0
#define OFF_ALV1 262144
#define OFF_MX2  524288
#define OFF_KW1  1048576
#define OFF_WMLP 1114112

__device__ __forceinline__ float warp_sum(float v) {
#pragma unroll
    for (int o = 16; o; o >>= 1) v += __shfl_xor_sync(0xffffffffu, v, o);
    return v;
}
__device__ __forceinline__ uint32_t f2bf2(float lo, float hi) {
    uint32_t r; asm("cvt.rn.bf16x2.f32 %0, %1, %2;" : "=r"(r) : "f"(hi), "f"(lo)); return r;
}
__device__ __forceinline__ void ldsm4(uint32_t* r, uint32_t a) {
    asm volatile("ldmatrix.sync.aligned.m8n8.x4.shared.b16 {%0,%1,%2,%3},[%4];"
        : "=r"(r[0]),"=r"(r[1]),"=r"(r[2]),"=r"(r[3]) : "r"(a));
}
__device__ __forceinline__ void ldsm4t(uint32_t* r, uint32_t a) {
    asm volatile("ldmatrix.sync.aligned.m8n8.x4.trans.shared.b16 {%0,%1,%2,%3},[%4];"
        : "=r"(r[0]),"=r"(r[1]),"=r"(r[2]),"=r"(r[3]) : "r"(a));
}
__device__ __forceinline__ void mmabf(float* d, const uint32_t* a, const uint32_t* b) {
    asm volatile("mma.sync.aligned.m16n8k16.row.col.f32.bf16.bf16.f32 "
        "{%0,%1,%2,%3},{%4,%5,%6,%7},{%8,%9},{%0,%1,%2,%3};"
        : "+f"(d[0]),"+f"(d[1]),"+f"(d[2]),"+f"(d[3])
        : "r"(a[0]),"r"(a[1]),"r"(a[2]),"r"(a[3]),"r"(b[0]),"r"(b[1]));
}

// ---------------------------------------------------------------------------
// merged weight conversion: all 6 regions in one launch
// quad segments: [0,131072) alvw  [131072,262144) mxw2  [262144,278528) kw1
//                [278528,311296) mxw1(str512,c0)  [311296,319488) smw1(str128,c512)
//                [319488,335872) kw0(str256,c640)
// ---------------------------------------------------------------------------
__global__ void cvtw_all(const float* __restrict__ alvw, const float* __restrict__ mxw2,
                         const float* __restrict__ kw,   const float* __restrict__ mxw1,
                         const float* __restrict__ smw1, __nv_bfloat16* __restrict__ wbf)
{
    int i = blockIdx.x * blockDim.x + threadIdx.x;
    const float* src; __nv_bfloat16* dst; int j; int ncols = 0, dstride = 0, dcol0 = 0;
    if (i < 131072)      { src = alvw;        dst = wbf + OFF_ALV0; j = i; }
    else if (i < 262144) { src = mxw2;        dst = wbf + OFF_MX2;  j = i - 131072; }
    else if (i < 278528) { src = kw + SS*SS;  dst = wbf + OFF_KW1;  j = i - 262144; }
    else if (i < 311296) { src = mxw1; dst = wbf + OFF_WMLP; j = i - 278528; ncols = 512; dstride = 896; dcol0 = 0; }
    else if (i < 319488) { src = smw1; dst = wbf + OFF_WMLP; j = i - 311296; ncols = 128; dstride = 896; dcol0 = 512; }
    else if (i < 335872) { src = kw;   dst = wbf + OFF_WMLP; j = i - 319488; ncols = 256; dstride = 896; dcol0 = 640; }
    else return;
    float4 v = *(const float4*)(src + (size_t)j*4);
    uint2 o; o.x = f2bf2(v.x, v.y); o.y = f2bf2(v.z, v.w);
    if (ncols == 0) {
        *(uint2*)(dst + (size_t)j*4) = o;
    } else {
        int row = (j*4) / ncols, col = (j*4) % ncols;
        *(uint2*)(dst + (size_t)row*dstride + dcol0 + col) = o;
    }
}

// ---------------------------------------------------------------------------
// bf16 m16n8k16 GEMM (unchanged from R8). grid: x = N tiles, y = M tiles.
// ---------------------------------------------------------------------------
template<int M_BLK,int N_BLK,int K_DIM,int N_TOT,int AMODE,int EPI,int OUTBF>
__global__ void __launch_bounds__(256) gemm_bf16(
    const float* __restrict__ Af, const __nv_bfloat16* __restrict__ Ab,
    const __nv_bfloat16* __restrict__ Bw,
    const float* __restrict__ bias, const float* __restrict__ bias2, const float* __restrict__ bias3,
    float* __restrict__ Cf, __nv_bfloat16* __restrict__ Cb,
    __nv_bfloat16* __restrict__ Cb2, __nv_bfloat16* __restrict__ Cb3,
    const float* __restrict__ cap, const float* __restrict__ fac)
{
    constexpr int MT   = M_BLK/16;
    constexpr int NT   = N_BLK/64;
    constexpr int SAW  = 20;
    constexpr int SBW  = N_BLK/2 + 4;
    constexpr int ABUF = M_BLK*SAW;
    constexpr int BBUF = 32*SBW;
    constexpr int APASS = M_BLK/32;
    constexpr int BROWP = 2048/N_BLK;
    constexpr int BPASS = 32/BROWP;
    constexpr int KT   = K_DIM/32;

    extern __shared__ uint32_t dsm[];
    uint32_t* As = dsm;
    uint32_t* Bs = dsm + 2*ABUF;
    float* sRed  = (float*)(dsm + 2*ABUF + 2*BBUF);
    float* sFacR = sRed + M_BLK*8;

    const int m0 = blockIdx.y * M_BLK;
    const int n0 = blockIdx.x * N_BLK;
    const int tid = threadIdx.x, lane = tid & 31, wid = tid >> 5;
    const int g = lane >> 2, tig = lane & 3;
    const int wn0 = wid * (N_BLK/8);

    const int a_row = tid >> 3, a_c = (tid & 7) * 4;
    float facr[APASS]; int caprow[APASS];
    if (AMODE == 1) {
#pragma unroll
        for (int p = 0; p < APASS; p++) {
            int r = m0 + p*32 + a_row;
            facr[p] = fac[r];
            caprow[p] = (r/1152)*24 + (r%24);
        }
    }
    const int b_row = tid / (N_BLK/8), b_c = (tid % (N_BLK/8)) * 8;
    const __nv_bfloat16* Bptr = Bw + (size_t)b_row*N_TOT + n0 + b_c;

    uint32_t areg[2*APASS]; uint4 breg[BPASS];

    auto loadA = [&](int kt) {
#pragma unroll
        for (int p = 0; p < APASS; p++) {
            int r = m0 + p*32 + a_row;
            if (AMODE == 2) {
                uint2 v = *(const uint2*)(Ab + (size_t)r*K_DIM + kt*32 + a_c);
                areg[p*2] = v.x; areg[p*2+1] = v.y;
            } else if (AMODE == 0) {
                float4 v = *(const float4*)(Af + (size_t)r*K_DIM + kt*32 + a_c);
                areg[p*2]   = f2bf2(v.x, v.y);
                areg[p*2+1] = f2bf2(v.z, v.w);
            } else {
                uint2 wv2 = *(const uint2*)(Ab + (size_t)r*K_DIM + kt*32 + a_c);
                float2 w01 = __bfloat1622float2(*(__nv_bfloat162*)&wv2.x);
                float2 w23 = __bfloat1622float2(*(__nv_bfloat162*)&wv2.y);
                float4 cv = *(const float4*)(cap + (size_t)caprow[p]*K_DIM + kt*32 + a_c);
                float f = facr[p];
                float s0 = cv.x - w01.x*f; s0 *= s0;
                float s1 = cv.y - w01.y*f; s1 *= s1;
                float s2 = cv.z - w23.x*f; s2 *= s2;
                float s3 = cv.w - w23.y*f; s3 *= s3;
                areg[p*2]   = f2bf2(s0, s1);
                areg[p*2+1] = f2bf2(s2, s3);
            }
        }
    };
    auto stsA = [&](int buf) {
#pragma unroll
        for (int p = 0; p < APASS; p++)
            *(uint2*)(As + buf*ABUF + (p*32 + a_row)*SAW + (tid&7)*2) =
                make_uint2(areg[p*2], areg[p*2+1]);
    };
    auto loadB = [&](int kt) {
#pragma unroll
        for (int p = 0; p < BPASS; p++)
            breg[p] = *(const uint4*)(Bptr + (size_t)(kt*32 + p*BROWP)*N_TOT);
    };
    auto stsB = [&](int buf) {
#pragma unroll
        for (int p = 0; p < BPASS; p++)
            *(uint4*)(Bs + buf*BBUF + (b_row + p*BROWP)*SBW + (tid % (N_BLK/8))*4) = breg[p];
    };

    loadA(0); loadB(0);
    stsA(0);  stsB(0);
    __syncthreads();

    float acc[MT][NT][4];
#pragma unroll
    for (int i = 0; i < MT; i++)
#pragma unroll
        for (int j = 0; j < NT; j++)
#pragma unroll
            for (int k = 0; k < 4; k++) acc[i][j][k] = 0.f;

    uint32_t smA = (uint32_t)__cvta_generic_to_shared(As);
    uint32_t smB = (uint32_t)__cvta_generic_to_shared(Bs);
    const uint32_t aoff = (lane & 15)*(SAW*4) + (lane >> 4)*16;
    const uint32_t boff = ((lane & 7) + ((lane >> 3) & 1)*8)*(SBW*4)
                        + (wn0 + (lane >> 4)*8)*2;

    for (int kt = 0; kt < KT; kt++) {
        int cur = kt & 1;
        if (kt + 1 < KT) { loadA(kt+1); loadB(kt+1); }
        uint32_t Ab0 = smA + cur*(ABUF*4);
        uint32_t Bb0 = smB + cur*(BBUF*4);
#pragma unroll
        for (int ks = 0; ks < 2; ks++) {
            uint32_t af[MT][4], bf[NT][2];
#pragma unroll
            for (int i = 0; i < MT; i++)
                ldsm4(af[i], Ab0 + i*16*(SAW*4) + aoff + ks*32);
#pragma unroll
            for (int jp = 0; jp < NT/2; jp++) {
                uint32_t t[4];
                ldsm4t(t, Bb0 + ks*16*(SBW*4) + boff + jp*32);
                bf[2*jp][0] = t[0]; bf[2*jp][1] = t[1];
                bf[2*jp+1][0] = t[2]; bf[2*jp+1][1] = t[3];
            }
#pragma unroll
            for (int i = 0; i < MT; i++)
#pragma unroll
                for (int j = 0; j < NT; j++)
                    mmabf(acc[i][j], af[i], bf[j]);
        }
        if (kt + 1 < KT) { stsA((kt+1)&1); stsB((kt+1)&1); }
        __syncthreads();
    }

    if (EPI != 3) {
#pragma unroll
        for (int j = 0; j < NT; j++) {
            int coln = n0 + wn0 + j*8 + 2*tig;
            float b0 = bias[coln], b1 = bias[coln+1];
#pragma unroll
            for (int i = 0; i < MT; i++) {
                acc[i][j][0] += b0; acc[i][j][1] += b1;
                acc[i][j][2] += b0; acc[i][j][3] += b1;
            }
        }
    }

    if (EPI == 0) {
        float ps[MT][2];
#pragma unroll
        for (int i = 0; i < MT; i++) {
            ps[i][0] = 0.f; ps[i][1] = 0.f;
#pragma unroll
            for (int j = 0; j < NT; j++) {
                ps[i][0] += acc[i][j][0]*acc[i][j][0] + acc[i][j][1]*acc[i][j][1];
                ps[i][1] += acc[i][j][2]*acc[i][j][2] + acc[i][j][3]*acc[i][j][3];
            }
        }
#pragma unroll
        for (int i = 0; i < MT; i++)
#pragma unroll
            for (int h = 0; h < 2; h++) {
                ps[i][h] += __shfl_xor_sync(0xffffffffu, ps[i][h], 1);
                ps[i][h] += __shfl_xor_sync(0xffffffffu, ps[i][h], 2);
            }
        if (tig == 0) {
#pragma unroll
            for (int i = 0; i < MT; i++) {
                sRed[(i*16 + g    )*8 + wid] = ps[i][0];
                sRed[(i*16 + g + 8)*8 + wid] = ps[i][1];
            }
        }
        __syncthreads();
        if (tid < M_BLK) {
            float s = 0.f;
#pragma unroll
            for (int k = 0; k < 8; k++) s += sRed[tid*8 + k];
            sFacR[tid] = 1.f / (sqrtf(s) + 1e-8f);
        }
        __syncthreads();
#pragma unroll
        for (int i = 0; i < MT; i++) {
            float f0 = sFacR[i*16 + g], f1 = sFacR[i*16 + g + 8];
#pragma unroll
            for (int j = 0; j < NT; j++) {
                int coln = wn0 + j*8 + 2*tig;
                if (OUTBF) {
                    *(uint32_t*)&Cb[(size_t)(m0 + i*16 + g    )*N_TOT + coln] =
                        f2bf2(acc[i][j][0]*f0, acc[i][j][1]*f0);
                    *(uint32_t*)&Cb[(size_t)(m0 + i*16 + g + 8)*N_TOT + coln] =
                        f2bf2(acc[i][j][2]*f1, acc[i][j][3]*f1);
                } else {
                    *(float2*)&Cf[(size_t)(m0 + i*16 + g    )*N_TOT + coln] =
                        make_float2(acc[i][j][0]*f0, acc[i][j][1]*f0);
                    *(float2*)&Cf[(size_t)(m0 + i*16 + g + 8)*N_TOT + coln] =
                        make_float2(acc[i][j][2]*f1, acc[i][j][3]*f1);
                }
            }
        }
    } else if (EPI == 1) {
#pragma unroll
        for (int i = 0; i < MT; i++) {
            int r0 = m0 + i*16 + g, r1 = r0 + 8;
#pragma unroll
            for (int j = 0; j < NT; j++) {
                int coln = n0 + wn0 + j*8 + 2*tig;
                float v0 = tanhf(acc[i][j][0]), v1 = tanhf(acc[i][j][1]);
                float v2 = tanhf(acc[i][j][2]), v3 = tanhf(acc[i][j][3]);
                if (OUTBF) {
                    *(uint32_t*)&Cb[(size_t)r0*N_TOT + coln] = f2bf2(v0, v1);
                    *(uint32_t*)&Cb[(size_t)r1*N_TOT + coln] = f2bf2(v2, v3);
                } else {
                    *(float2*)&Cf[(size_t)r0*N_TOT + coln] = make_float2(v0, v1);
                    *(float2*)&Cf[(size_t)r1*N_TOT + coln] = make_float2(v2, v3);
                }
            }
        }
    } else if (EPI == 2) {
#pragma unroll
        for (int i = 0; i < MT; i++) {
            int r0 = m0 + i*16 + g, r1 = r0 + 8;
            int cr0 = (r0/1152)*24 + (r0%24);
            int cr1 = (r1/1152)*24 + (r1%24);
#pragma unroll
            for (int j = 0; j < NT; j++) {
                int coln = n0 + wn0 + j*8 + 2*tig;
                float m00 = fminf(fmaxf(tanhf(acc[i][j][0]) + 1.f, -1.f), 1.f);
                float m01 = fminf(fmaxf(tanhf(acc[i][j][1]) + 1.f, -1.f), 1.f);
                float m10 = fminf(fmaxf(tanhf(acc[i][j][2]) + 1.f, -1.f), 1.f);
                float m11 = fminf(fmaxf(tanhf(acc[i][j][3]) + 1.f, -1.f), 1.f);
                float2 c0 = *(const float2*)&cap[(size_t)cr0*DD + coln];
                float2 c1 = *(const float2*)&cap[(size_t)cr1*DD + coln];
                if (OUTBF) {
                    *(uint32_t*)&Cb[(size_t)r0*N_TOT + coln] = f2bf2(c0.x*m00, c0.y*m01);
                    *(uint32_t*)&Cb[(size_t)r1*N_TOT + coln] = f2bf2(c1.x*m10, c1.y*m11);
                } else {
                    *(float2*)&Cf[(size_t)r0*N_TOT + coln] = make_float2(c0.x*m00, c0.y*m01);
                    *(float2*)&Cf[(size_t)r1*N_TOT + coln] = make_float2(c1.x*m10, c1.y*m11);
                }
            }
        }
    } else {
        __nv_bfloat16* outp; const float* bp; int ostride, oc0;
        if (n0 < 512)      { outp = Cb;  bp = bias;  ostride = 512; oc0 = n0; }
        else if (n0 < 640) { outp = Cb2; bp = bias2; ostride = 128; oc0 = n0 - 512; }
        else               { outp = Cb3; bp = bias3; ostride = 256; oc0 = n0 - 640; }
#pragma unroll
        for (int j = 0; j < NT; j++) {
            int cl = oc0 + wn0 + j*8 + 2*tig;
            float b0 = bp[cl], b1 = bp[cl+1];
#pragma unroll
            for (int i = 0; i < MT; i++) {
                acc[i][j][0] += b0; acc[i][j][1] += b1;
                acc[i][j][2] += b0; acc[i][j][3] += b1;
            }
        }
#pragma unroll
        for (int i = 0; i < MT; i++) {
            int r0 = m0 + i*16 + g, r1 = r0 + 8;
#pragma unroll
            for (int j = 0; j < NT; j++) {
                int cl = oc0 + wn0 + j*8 + 2*tig;
                *(uint32_t*)&outp[(size_t)r0*ostride + cl] =
                    f2bf2(tanhf(acc[i][j][0]), tanhf(acc[i][j][1]));
                *(uint32_t*)&outp[(size_t)r1*ostride + cl] =
                    f2bf2(tanhf(acc[i][j][2]), tanhf(acc[i][j][3]));
            }
        }
    }
}

// ---------------------------------------------------------------------------
// alv kernel v3: fully tensorized. img + query loaded as bf16 padded tiles.
// attn = img(48x1024) @ q^T(32x1024) via mma (6 warps); softmax fp32;
// wctx = attnW(32x48) @ img(48x1024) via mma (8 warps).
// ---------------------------------------------------------------------------
template<int PASS>
__global__ void __launch_bounds__(256) alv_kernel(
        const float* __restrict__ img, const float* __restrict__ cap,
        const int* __restrict__ lens)
{
    constexpr int ARS = 28;    // wctx A-tile row stride (words)
    constexpr int IRS = 516;   // img/query row stride in words (1032 bf16, 2064 B)

    extern __shared__ float sm[];
    __nv_bfloat16* sImgBf = (__nv_bfloat16*)sm;            // 48 x 1032
    __nv_bfloat16* sQBf   = sImgBf + 48*1032;              // 32 x 1032
    float* sA   = (float*)(sQBf + 32*1032);                // RR*WW raw attn
    float* sAT  = sA + RR*WW;                              // WW*RR
    uint32_t* sAbfW = (uint32_t*)(sAT + WW*RR);            // 32*ARS
    float* sRed = (float*)(sAbfW + 32*ARS);                // 32*8
    __nv_bfloat16* sAbf = (__nv_bfloat16*)sAbfW;

    const int b = blockIdx.x;
    const int c = b / NN, n = b % NN;
    const int tid = threadIdx.x, lane = tid & 31, wid = tid >> 5;
    const int g = lane >> 2, tig = lane & 3;
    const int len = lens[c];

    // ---- load img fp32 -> bf16 smem; query -> bf16 smem; zero pads ----
    {
        const float4* gi = (const float4*)(img + (size_t)n * RR * DD);
        for (int i = tid; i < RR*DD/4; i += 256) {
            float4 v = gi[i];
            int r = (i*4) >> 10, col = (i*4) & 1023;
            uint2 o; o.x = f2bf2(v.x, v.y); o.y = f2bf2(v.z, v.w);
            *(uint2*)(sImgBf + (size_t)r*1032 + col) = o;
        }
        for (int i = tid; i < 12*256; i += 256) {          // img pad rows 36-47
            int r = 36 + i/256, col = (i%256)*4;
            *(uint2*)(sImgBf + (size_t)r*1032 + col) = make_uint2(0,0);
        }
        if (PASS == 0) {
            const float4* gq = (const float4*)(cap + (size_t)c * WW * DD);
            for (int i = tid; i < WW*DD/4; i += 256) {
                float4 v = gq[i];
                int r = (i*4) >> 10, col = (i*4) & 1023;
                uint2 o; o.x = f2bf2(v.x, v.y); o.y = f2bf2(v.z, v.w);
                *(uint2*)(sQBf + (size_t)r*1032 + col) = o;
            }
        } else {
            const uint2* gq = (const uint2*)(g_qmb + (size_t)b * WW * DD);
            for (int i = tid; i < WW*DD/4; i += 256) {
                int r = (i*4) >> 10, col = (i*4) & 1023;
                *(uint2*)(sQBf + (size_t)r*1032 + col) = gq[i];
            }
        }
        for (int i = tid; i < 8*256; i += 256) {           // query pad rows 24-31
            int r = 24 + i/256, col = (i%256)*4;
            *(uint2*)(sQBf + (size_t)r*1032 + col) = make_uint2(0,0);
        }
        for (int i = tid; i < 32*ARS; i += 256) sAbfW[i] = 0;  // zero wctx A tile
    }
    __syncthreads();

    // ---- phase 1: attn via bf16 mma (warps 0-5: mi in 0..2, ni in 0..1) ----
    if (wid < 6) {
        int mi = wid >> 1, ni = wid & 1;
        uint32_t smI = (uint32_t)__cvta_generic_to_shared(sImgBf);
        uint32_t smQ = (uint32_t)__cvta_generic_to_shared(sQBf);
        uint32_t aBase = smI + (mi*16 + (lane & 15))*(IRS*4) + (lane >> 4)*16;
        uint32_t bBase = smQ + (ni*16 + (lane & 15))*(IRS*4) + (lane >> 4)*16;
        float acc0[4] = {0,0,0,0}, acc1[4] = {0,0,0,0};
#pragma unroll 4
        for (int kk = 0; kk < 64; kk++) {
            uint32_t a[4], t[4];
            ldsm4(a, aBase + kk*32);
            ldsm4(t, bBase + kk*32);
            uint32_t b0[2] = {t[0], t[2]};   // n rows 0-7 of this tile
            uint32_t b1[2] = {t[1], t[3]};   // n rows 8-15
            mmabf(acc0, a, b0);
            mmabf(acc1, a, b1);
        }
        int r0 = mi*16 + g, r1 = r0 + 8;
        int w0 = ni*16 + 2*tig;
        if (r0 < RR) {
            if (w0 < WW)     sA[r0*WW + w0]     = acc0[0];
            if (w0+1 < WW)   sA[r0*WW + w0+1]   = acc0[1];
            if (w0+8 < WW)   sA[r0*WW + w0+8]   = acc1[0];
            if (w0+9 < WW)   sA[r0*WW + w0+9]   = acc1[1];
        }
        if (r1 < RR) {
            if (w0 < WW)     sA[r1*WW + w0]     = acc0[2];
            if (w0+1 < WW)   sA[r1*WW + w0+1]   = acc0[3];
            if (w0+8 < WW)   sA[r1*WW + w0+8]   = acc1[2];
            if (w0+9 < WW)   sA[r1*WW + w0+9]   = acc1[3];
        }
    }
    __syncthreads();

    // ---- phase 2a: leaky relu, mask, l2norm over words (fp32) ----
    if (tid < RR) {
        int r = tid;
        float vals[WW];
        float ss = 0.f;
#pragma unroll
        for (int w = 0; w < WW; w++) {
            float v = sA[r*WW + w];
            v = (v >= 0.f) ? v : 0.1f * v;
            if (w >= len) v = 0.f;
            vals[w] = v;
            ss += v * v;
        }
        float f = 1.f / (sqrtf(ss) + 1e-8f);
#pragma unroll
        for (int w = 0; w < WW; w++) sAT[w*RR + r] = vals[w] * f;
    }
    __syncthreads();

    // ---- phase 2b: softmax over regions -> bf16 A tile [w][r] ----
    if (tid < WW) {
        int w = tid;
        float smo = (PASS == 0) ? 9.f : g_smooth[(size_t)b*WW + w];
        float m = -1e30f;
        for (int r = 0; r < RR; r++) { float v = sAT[w*RR + r]*smo; if (v > m) m = v; }
        float s = 0.f;
        float e_[RR];
        for (int r = 0; r < RR; r++) {
            float e = expf(sAT[w*RR + r]*smo - m);
            e_[r] = e; s += e;
        }
        float inv = 1.f / s;
        for (int r = 0; r < RR; r++)
            sAbf[w*(2*ARS) + r] = __float2bfloat16(e_[r] * inv);
    }
    __syncthreads();

    // ---- phase 3: wctx = A(32x48) @ B(48x1024) via bf16 mma (8 warps) ----
    {
        uint32_t smAttn = (uint32_t)__cvta_generic_to_shared(sAbf);
        uint32_t smImgB = (uint32_t)__cvta_generic_to_shared(sImgBf);
        const uint32_t aoff = (lane & 15)*(ARS*4) + (lane >> 4)*16;
        const uint32_t bRowSel = ((lane & 7) + ((lane >> 3) & 1)*8)*(IRS*4);
        const uint32_t bColSel = (lane >> 4)*8;

        float psq[2][2] = {{0.f,0.f},{0.f,0.f}};
        for (int half = 0; half < 2; half++) {
            float acc[2][8][4];
#pragma unroll
            for (int i = 0; i < 2; i++)
#pragma unroll
                for (int j = 0; j < 8; j++)
#pragma unroll
                    for (int k = 0; k < 4; k++) acc[i][j][k] = 0.f;
#pragma unroll
            for (int ks = 0; ks < 3; ks++) {
                uint32_t af0[4], af1[4];
                ldsm4(af0, smAttn + aoff + ks*32);
                ldsm4(af1, smAttn + 16*(ARS*4) + aoff + ks*32);
#pragma unroll
                for (int jp = 0; jp < 4; jp++) {
                    int ncol = half*512 + wid*64 + jp*16 + bColSel;
                    uint32_t t[4];
                    ldsm4t(t, smImgB + ks*16*(IRS*4) + bRowSel + ncol*2);
                    mmabf(acc[0][2*jp],   af0, t);
                    mmabf(acc[0][2*jp+1], af0, t+2);
                    mmabf(acc[1][2*jp],   af1, t);
                    mmabf(acc[1][2*jp+1], af1, t+2);
                }
            }
#pragma unroll
            for (int i = 0; i < 2; i++) {
                int r0 = i*16 + g, r1 = r0 + 8;
#pragma unroll
                for (int j = 0; j < 8; j++) {
                    int coln = half*512 + wid*64 + j*8 + 2*tig;
                    float v0 = acc[i][j][0], v1 = acc[i][j][1];
                    float v2 = acc[i][j][2], v3 = acc[i][j][3];
                    psq[i][0] += v0*v0 + v1*v1;
                    psq[i][1] += v2*v2 + v3*v3;
                    if (r0 < WW)
                        *(uint32_t*)&g_wc[((size_t)b*WW + r0)*DD + coln] = f2bf2(v0, v1);
                    if (r1 < WW)
                        *(uint32_t*)&g_wc[((size_t)b*WW + r1)*DD + coln] = f2bf2(v2, v3);
                }
            }
        }
#pragma unroll
        for (int i = 0; i < 2; i++)
#pragma unroll
            for (int h = 0; h < 2; h++) {
                psq[i][h] += __shfl_xor_sync(0xffffffffu, psq[i][h], 1);
                psq[i][h] += __shfl_xor_sync(0xffffffffu, psq[i][h], 2);
            }
        if (tig == 0) {
#pragma unroll
            for (int i = 0; i < 2; i++) {
                sRed[(i*16 + g    )*8 + wid] = psq[i][0];
                sRed[(i*16 + g + 8)*8 + wid] = psq[i][1];
            }
        }
        __syncthreads();
        if (tid < WW) {
            float s = 0.f;
#pragma unroll
            for (int k = 0; k < 8; k++) s += sRed[tid*8 + k];
            g_fac[(size_t)b*WW + tid] = 1.f / (sqrtf(s) + 1e-8f);
        }
    }
}

// ---------------------------------------------------------------------------
__global__ void mean_kernel(const int* __restrict__ lens)
{
    int b = blockIdx.x;
    int c = b / NN;
    int t = threadIdx.x;
    int len = lens[c];
    float inv = 1.f / (float)len;
    const __nv_bfloat16* p = g_smid + (size_t)b*WW*SS + t;
    float s = 0.f;
    for (int w = 0; w < len; w++) s += __bfloat162float(p[(size_t)w * SS]);
    g_higA[(size_t)b*SS + t] = s * inv;
}

__global__ void smooth_kernel(const float* __restrict__ w2, const float* __restrict__ b2)
{
    int wid = threadIdx.x >> 5, lane = threadIdx.x & 31;
    size_t r = (size_t)blockIdx.x * 8 + wid;
    const __nv_bfloat16* h = g_hsm + r * 128;
    float a = 0.f;
#pragma unroll
    for (int k = 0; k < 4; k++)
        a = fmaf(__bfloat162float(h[lane + 32*k]), w2[lane + 32*k], a);
    a = warp_sum(a);
    if (lane == 0) {
        float v = a + b2[0] + 9.0f;
        g_smooth[r] = v > 0.f ? v : 0.f;
    }
}

// ---------------------------------------------------------------------------
__global__ void __launch_bounds__(256) rar_kernel(
        const int* __restrict__ lens,
        const float* __restrict__ qw, const float* __restrict__ qb,
        const float* __restrict__ vw, const float* __restrict__ vb,
        const __nv_bfloat16* __restrict__ kt, int dir)
{
    extern __shared__ float sm[];
    __nv_bfloat16* sMid = (__nv_bfloat16*)sm;
    float* sHig = sm + WW*SS/2;
    float* sRed = sHig + SS;
    float* sLog = sRed + WW*8;
    float* sWgt = sLog + WW;
    float* sMisc= sWgt + WW;

    const int b = blockIdx.x;
    const int c = b / NN;
    const int tid = threadIdx.x, lane = tid & 31, wid = tid >> 5;
    const int len = lens[c];

    const float* hin = (dir == 0) ? g_higA : g_higB;
    float*       hout= (dir == 0) ? g_higB : g_higA;

    {
        const uint4* gm = (const uint4*)(g_smid + (size_t)b*WW*SS);
        uint4* s4 = (uint4*)sMid;
        for (int i = tid; i < WW*SS/8; i += 256) s4[i] = gm[i];
    }
    sHig[tid] = hin[(size_t)b*SS + tid];
    __syncthreads();

    float hv;
    {
        float acc = qb[tid];
        const float* wp = qw + tid;
#pragma unroll 4
        for (int s0 = 0; s0 < SS/4; s0++) {
            float4 h4 = *(const float4*)(sHig + s0*4);
            acc = fmaf(h4.x, wp[(size_t)(s0*4+0)*SS], acc);
            acc = fmaf(h4.y, wp[(size_t)(s0*4+1)*SS], acc);
            acc = fmaf(h4.z, wp[(size_t)(s0*4+2)*SS], acc);
            acc = fmaf(h4.w, wp[(size_t)(s0*4+3)*SS], acc);
        }
        hv = tanhf(acc) * vw[tid];
    }

    {
        const __nv_bfloat16* ktp = kt + (size_t)b*WW*SS + tid;
        float pv[WW];
#pragma unroll
        for (int w = 0; w < WW; w++)
            pv[w] = __bfloat162float(ktp[(size_t)w*SS]) * hv;
#pragma unroll
        for (int w = 0; w < WW; w++) {
            float v = warp_sum(pv[w]);
            if (lane == 0) sRed[w*8 + wid] = v;
        }
    }
    __syncthreads();
    if (tid < WW) {
        float s = 0.f;
#pragma unroll
        for (int k = 0; k < 8; k++) s += sRed[tid*8 + k];
        s += vb[0];
        if (tid >= len) s = -1e30f;
        sLog[tid] = s;
    }
    __syncthreads();
    if (tid == 0) {
        float m = -1e30f;
        for (int w = 0; w < WW; w++) m = fmaxf(m, sLog[w]);
        float s = 0.f;
        for (int w = 0; w < WW; w++) { float e = expf(sLog[w] - m); sWgt[w] = e; s += e; }
        float inv = 1.f / s;
        for (int w = 0; w < WW; w++) sWgt[w] *= inv;
    }
    __syncthreads();

    float o = 0.f;
#pragma unroll
    for (int w = 0; w < WW; w++)
        o = fmaf(sWgt[w], __bfloat162float(sMid[w*SS + tid]), o);
    float sq = warp_sum(o * o);
    if (lane == 0) sRed[wid] = sq;
    __syncthreads();
    if (tid == 0) {
        float tot = 0.f;
#pragma unroll
        for (int k = 0; k < 8; k++) tot += sRed[k];
        sMisc[0] = 1.f / (sqrtf(tot) + 1e-8f);
    }
    __syncthreads();
    hout[(size_t)b*SS + tid] = o * sMisc[0];
}

// ---------------------------------------------------------------------------
__global__ void final_kernel(const float* __restrict__ ew, const float* __restrict__ eb,
                             float* __restrict__ out)
{
    int gw = (blockIdx.x * blockDim.x + threadIdx.x) >> 5;
    int lane = threadIdx.x & 31;
    int nwarps = (gridDim.x * blockDim.x) >> 5;
    for (int b = gw; b < CC*NN; b += nwarps) {
        const float* h = g_higA + (size_t)b*SS;
        float a = 0.f;
#pragma unroll
        for (int k = 0; k < 8; k++) a = fmaf(h[lane + k*32], ew[lane + k*32], a);
        a = warp_sum(a);
        if (lane == 0) {
            float v = a + eb[0];
            int c = b / NN, n = b % NN;
            out[n*CC + c] = 1.f / (1.f + expf(-v));
        }
    }
}

// ---------------------------------------------------------------------------
extern "C" void kernel_launch(void* const* d_in, const int* in_sizes, int n_in,
                              void* d_out, int out_size)
{
    const float* img  = (const float*)d_in[0];
    const float* cap  = (const float*)d_in[1];
    const int*   lens = (const int*)  d_in[2];
    const float* alvw = (const float*)d_in[3];
    const float* alvb = (const float*)d_in[4];
    const float* qw   = (const float*)d_in[5];
    const float* qb   = (const float*)d_in[6];
    const float* kw   = (const float*)d_in[7];
    const float* kb   = (const float*)d_in[8];
    const float* vw   = (const float*)d_in[9];
    const float* vb   = (const float*)d_in[10];
    const float* smw1 = (const float*)d_in[11];
    const float* smb1 = (const float*)d_in[12];
    const float* smw2 = (const float*)d_in[13];
    const float* smb2 = (const float*)d_in[14];
    const float* mxw1 = (const float*)d_in[15];
    const float* mxb1 = (const float*)d_in[16];
    const float* mxw2 = (const float*)d_in[17];
    const float* mxb2 = (const float*)d_in[18];
    const float* ew   = (const float*)d_in[19];
    const float* eb   = (const float*)d_in[20];
    float* out = (float*)d_out;

    float *pFac;
    __nv_bfloat16 *pH, *pHsm, *pWbf, *pWc, *pKt, *pQm, *pSmid;
    cudaGetSymbolAddress((void**)&pSmid, g_smid);
    cudaGetSymbolAddress((void**)&pQm,  g_qmb);
    cudaGetSymbolAddress((void**)&pWc,  g_wc);
    cudaGetSymbolAddress((void**)&pFac, g_fac);
    cudaGetSymbolAddress((void**)&pH,   g_h);
    cudaGetSymbolAddress((void**)&pHsm, g_hsm);
    cudaGetSymbolAddress((void**)&pWbf, g_wbf);
    cudaGetSymbolAddress((void**)&pKt,  g_kt);

    const size_t ALV_SMEM = (size_t)(48*1032 + 32*1032) * 2
                          + (size_t)(RR*WW*2 + 32*8) * 4 + 32*28*4;   // 176,640 B
    const size_t RAR_SMEM = (size_t)(WW*SS/2 + SS + WW*8 + WW + WW + 32) * sizeof(float);
    const size_t SM_ALVG = (size_t)(2*64*20 + 2*32*132)*4 + (64*8 + 64)*4;
    const size_t SM_MLP  = (size_t)(2*64*20 + 2*32*68)*4 + (64*8 + 64)*4;

    cudaFuncSetAttribute(alv_kernel<0>, cudaFuncAttributeMaxDynamicSharedMemorySize, (int)ALV_SMEM);
    cudaFuncSetAttribute(alv_kernel<1>, cudaFuncAttributeMaxDynamicSharedMemorySize, (int)ALV_SMEM);
    cudaFuncSetAttribute(gemm_bf16<64,256,1024,256,1,0,1>, cudaFuncAttributeMaxDynamicSharedMemorySize, (int)SM_ALVG);
    cudaFuncSetAttribute(gemm_bf16<64,128,256,896,2,3,1>,  cudaFuncAttributeMaxDynamicSharedMemorySize, (int)SM_MLP);
    cudaFuncSetAttribute(gemm_bf16<64,128,512,1024,2,2,1>, cudaFuncAttributeMaxDynamicSharedMemorySize, (int)SM_MLP);
    cudaFuncSetAttribute(gemm_bf16<64,128,256,256,2,1,1>,  cudaFuncAttributeMaxDynamicSharedMemorySize, (int)SM_MLP);

    const int B = CC * NN;
    const int MB64 = MTOT / 64;

    // single merged weight-convert launch (335872 quads)
    cvtw_all<<<(335872 + 255)/256, 256>>>(alvw, mxw2, kw, mxw1, smw1, pWbf);

    // ---- pass 0 ----
    alv_kernel<0><<<B, 256, ALV_SMEM>>>(img, cap, lens);
    gemm_bf16<64,256,1024,256,1,0,1><<<dim3(1,MB64), 256, SM_ALVG>>>(
        nullptr, pWc, pWbf + OFF_ALV0, alvb, nullptr, nullptr,
        nullptr, pSmid, nullptr, nullptr, cap, pFac);
    mean_kernel<<<B, 256>>>(lens);
    gemm_bf16<64,128,256,896,2,3,1><<<dim3(7,MB64), 256, SM_MLP>>>(
        nullptr, pSmid, pWbf + OFF_WMLP, mxb1, smb1, kb,
        nullptr, pH, pHsm, pKt, nullptr, nullptr);
    smooth_kernel<<<MTOT/8, 256>>>(smw2, smb2);
    gemm_bf16<64,128,512,1024,2,2,1><<<dim3(8,MB64), 256, SM_MLP>>>(
        nullptr, pH, pWbf + OFF_MX2, mxb2, nullptr, nullptr,
        nullptr, pQm, nullptr, nullptr, cap, nullptr);
    rar_kernel<<<B, 256, RAR_SMEM>>>(lens, qw, qb, vw, vb, pKt, 0);

    // ---- pass 1 ----
    alv_kernel<1><<<B, 256, ALV_SMEM>>>(img, cap, lens);
    gemm_bf16<64,256,1024,256,1,0,1><<<dim3(1,MB64), 256, SM_ALVG>>>(
        nullptr, pWc, pWbf + OFF_ALV1, alvb + SS, nullptr, nullptr,
        nullptr, pSmid, nullptr, nullptr, cap, pFac);
    gemm_bf16<64,128,256,256,2,1,1><<<dim3(2,MB64), 256, SM_MLP>>>(
        nullptr, pSmid, pWbf + OFF_KW1, kb + SS, nullptr, nullptr,
        nullptr, pKt, nullptr, nullptr, nullptr, nullptr);
    rar_kernel<<<B, 256, RAR_SMEM>>>(lens, qw + SS*SS, qb + SS, vw + SS, vb + 1, pKt, 1);

    final_kernel<<<9, 256>>>(ew, eb, out);
}

// round 11
// speedup vs baseline: 9.2941x; 1.0650x over previous
#include <cuda_runtime.h>
#include <cuda_bf16.h>
#include <math.h>
#include <stdint.h>

#define CC 48
#define NN 48
#define WW 24
#define RR 36
#define DD 1024
#define SS 256
#define MTOT (CC*NN*WW)   // 55296

// ---------------- scratch (device globals; no allocation allowed) ----------
__device__ __align__(16) __nv_bfloat16 g_smid[MTOT*SS];         // 28 MB
__device__ __align__(16) float g_smooth[MTOT];
__device__ __align__(16) __nv_bfloat16 g_qmb[(size_t)MTOT*DD];  // 113 MB
__device__ __align__(16) __nv_bfloat16 g_wc[(size_t)MTOT*DD];   // 113 MB
__device__ __align__(16) float g_fac[MTOT];
__device__ __align__(16) __nv_bfloat16 g_h[(size_t)MTOT*512];   // 56 MB
__device__ __align__(16) __nv_bfloat16 g_kt[(size_t)MTOT*SS];   // 28 MB
__device__ __align__(16) __nv_bfloat16 g_wbf[1507328];          // weights bf16
__device__ __align__(16) float g_higA[CC*NN*SS];
__device__ __align__(16) float g_higB[CC*NN*SS];

#define OFF_ALV0 0
#define OFF_ALV1 262144
#define OFF_MX2  524288
#define OFF_KW1  1048576
#define OFF_WMLP 1114112

__device__ __forceinline__ float warp_sum(float v) {
#pragma unroll
    for (int o = 16; o; o >>= 1) v += __shfl_xor_sync(0xffffffffu, v, o);
    return v;
}
__device__ __forceinline__ uint32_t f2bf2(float lo, float hi) {
    uint32_t r; asm("cvt.rn.bf16x2.f32 %0, %1, %2;" : "=r"(r) : "f"(hi), "f"(lo)); return r;
}
__device__ __forceinline__ void ldsm4(uint32_t* r, uint32_t a) {
    asm volatile("ldmatrix.sync.aligned.m8n8.x4.shared.b16 {%0,%1,%2,%3},[%4];"
        : "=r"(r[0]),"=r"(r[1]),"=r"(r[2]),"=r"(r[3]) : "r"(a));
}
__device__ __forceinline__ void ldsm4t(uint32_t* r, uint32_t a) {
    asm volatile("ldmatrix.sync.aligned.m8n8.x4.trans.shared.b16 {%0,%1,%2,%3},[%4];"
        : "=r"(r[0]),"=r"(r[1]),"=r"(r[2]),"=r"(r[3]) : "r"(a));
}
__device__ __forceinline__ void mmabf(float* d, const uint32_t* a, const uint32_t* b) {
    asm volatile("mma.sync.aligned.m16n8k16.row.col.f32.bf16.bf16.f32 "
        "{%0,%1,%2,%3},{%4,%5,%6,%7},{%8,%9},{%0,%1,%2,%3};"
        : "+f"(d[0]),"+f"(d[1]),"+f"(d[2]),"+f"(d[3])
        : "r"(a[0]),"r"(a[1]),"r"(a[2]),"r"(a[3]),"r"(b[0]),"r"(b[1]));
}

// ---------------------------------------------------------------------------
// merged weight conversion (6 regions, one launch)
// ---------------------------------------------------------------------------
__global__ void cvtw_all(const float* __restrict__ alvw, const float* __restrict__ mxw2,
                         const float* __restrict__ kw,   const float* __restrict__ mxw1,
                         const float* __restrict__ smw1, __nv_bfloat16* __restrict__ wbf)
{
    int i = blockIdx.x * blockDim.x + threadIdx.x;
    const float* src; __nv_bfloat16* dst; int j; int ncols = 0, dstride = 0, dcol0 = 0;
    if (i < 131072)      { src = alvw;        dst = wbf + OFF_ALV0; j = i; }
    else if (i < 262144) { src = mxw2;        dst = wbf + OFF_MX2;  j = i - 131072; }
    else if (i < 278528) { src = kw + SS*SS;  dst = wbf + OFF_KW1;  j = i - 262144; }
    else if (i < 311296) { src = mxw1; dst = wbf + OFF_WMLP; j = i - 278528; ncols = 512; dstride = 896; dcol0 = 0; }
    else if (i < 319488) { src = smw1; dst = wbf + OFF_WMLP; j = i - 311296; ncols = 128; dstride = 896; dcol0 = 512; }
    else if (i < 335872) { src = kw;   dst = wbf + OFF_WMLP; j = i - 319488; ncols = 256; dstride = 896; dcol0 = 640; }
    else return;
    float4 v = *(const float4*)(src + (size_t)j*4);
    uint2 o; o.x = f2bf2(v.x, v.y); o.y = f2bf2(v.z, v.w);
    if (ncols == 0) {
        *(uint2*)(dst + (size_t)j*4) = o;
    } else {
        int row = (j*4) / ncols, col = (j*4) % ncols;
        *(uint2*)(dst + (size_t)row*dstride + dcol0 + col) = o;
    }
}

// ---------------------------------------------------------------------------
// bf16 m16n8k16 GEMM. grid: x = N tiles, y = M tiles.
// AMODE 0: A fp32->cvt. 1: A=(cap-wc*fac)^2. 2: A bf16.
// EPI 0: +bias, l2norm full 256 row -> OUTBF? bf16 : fp32.
// EPI 1: +bias, tanh. EPI 2: +bias, tanh, clip(+1), *cap.
// EPI 3: fused MLP: [0,512)->Cb tanh bf16; [512,640) -> SMOOTH fused
//        (bias2=smb1, fac=smw2, cap=smb2, Cf=g_smooth); [640,896)->Cb3 tanh bf16.
// ---------------------------------------------------------------------------
template<int M_BLK,int N_BLK,int K_DIM,int N_TOT,int AMODE,int EPI,int OUTBF>
__global__ void __launch_bounds__(256) gemm_bf16(
    const float* __restrict__ Af, const __nv_bfloat16* __restrict__ Ab,
    const __nv_bfloat16* __restrict__ Bw,
    const float* __restrict__ bias, const float* __restrict__ bias2, const float* __restrict__ bias3,
    float* __restrict__ Cf, __nv_bfloat16* __restrict__ Cb,
    __nv_bfloat16* __restrict__ Cb2, __nv_bfloat16* __restrict__ Cb3,
    const float* __restrict__ cap, const float* __restrict__ fac)
{
    constexpr int MT   = M_BLK/16;
    constexpr int NT   = N_BLK/64;
    constexpr int SAW  = 20;
    constexpr int SBW  = N_BLK/2 + 4;
    constexpr int ABUF = M_BLK*SAW;
    constexpr int BBUF = 32*SBW;
    constexpr int APASS = M_BLK/32;
    constexpr int BROWP = 2048/N_BLK;
    constexpr int BPASS = 32/BROWP;
    constexpr int KT   = K_DIM/32;

    extern __shared__ uint32_t dsm[];
    uint32_t* As = dsm;
    uint32_t* Bs = dsm + 2*ABUF;
    float* sRed  = (float*)(dsm + 2*ABUF + 2*BBUF);
    float* sFacR = sRed + M_BLK*8;

    const int m0 = blockIdx.y * M_BLK;
    const int n0 = blockIdx.x * N_BLK;
    const int tid = threadIdx.x, lane = tid & 31, wid = tid >> 5;
    const int g = lane >> 2, tig = lane & 3;
    const int wn0 = wid * (N_BLK/8);

    const int a_row = tid >> 3, a_c = (tid & 7) * 4;
    float facr[APASS]; int caprow[APASS];
    if (AMODE == 1) {
#pragma unroll
        for (int p = 0; p < APASS; p++) {
            int r = m0 + p*32 + a_row;
            facr[p] = fac[r];
            caprow[p] = (r/1152)*24 + (r%24);
        }
    }
    const int b_row = tid / (N_BLK/8), b_c = (tid % (N_BLK/8)) * 8;
    const __nv_bfloat16* Bptr = Bw + (size_t)b_row*N_TOT + n0 + b_c;

    uint32_t areg[2*APASS]; uint4 breg[BPASS];

    auto loadA = [&](int kt) {
#pragma unroll
        for (int p = 0; p < APASS; p++) {
            int r = m0 + p*32 + a_row;
            if (AMODE == 2) {
                uint2 v = *(const uint2*)(Ab + (size_t)r*K_DIM + kt*32 + a_c);
                areg[p*2] = v.x; areg[p*2+1] = v.y;
            } else if (AMODE == 0) {
                float4 v = *(const float4*)(Af + (size_t)r*K_DIM + kt*32 + a_c);
                areg[p*2]   = f2bf2(v.x, v.y);
                areg[p*2+1] = f2bf2(v.z, v.w);
            } else {
                uint2 wv2 = *(const uint2*)(Ab + (size_t)r*K_DIM + kt*32 + a_c);
                float2 w01 = __bfloat1622float2(*(__nv_bfloat162*)&wv2.x);
                float2 w23 = __bfloat1622float2(*(__nv_bfloat162*)&wv2.y);
                float4 cv = *(const float4*)(cap + (size_t)caprow[p]*K_DIM + kt*32 + a_c);
                float f = facr[p];
                float s0 = cv.x - w01.x*f; s0 *= s0;
                float s1 = cv.y - w01.y*f; s1 *= s1;
                float s2 = cv.z - w23.x*f; s2 *= s2;
                float s3 = cv.w - w23.y*f; s3 *= s3;
                areg[p*2]   = f2bf2(s0, s1);
                areg[p*2+1] = f2bf2(s2, s3);
            }
        }
    };
    auto stsA = [&](int buf) {
#pragma unroll
        for (int p = 0; p < APASS; p++)
            *(uint2*)(As + buf*ABUF + (p*32 + a_row)*SAW + (tid&7)*2) =
                make_uint2(areg[p*2], areg[p*2+1]);
    };
    auto loadB = [&](int kt) {
#pragma unroll
        for (int p = 0; p < BPASS; p++)
            breg[p] = *(const uint4*)(Bptr + (size_t)(kt*32 + p*BROWP)*N_TOT);
    };
    auto stsB = [&](int buf) {
#pragma unroll
        for (int p = 0; p < BPASS; p++)
            *(uint4*)(Bs + buf*BBUF + (b_row + p*BROWP)*SBW + (tid % (N_BLK/8))*4) = breg[p];
    };

    loadA(0); loadB(0);
    stsA(0);  stsB(0);
    __syncthreads();

    float acc[MT][NT][4];
#pragma unroll
    for (int i = 0; i < MT; i++)
#pragma unroll
        for (int j = 0; j < NT; j++)
#pragma unroll
            for (int k = 0; k < 4; k++) acc[i][j][k] = 0.f;

    uint32_t smA = (uint32_t)__cvta_generic_to_shared(As);
    uint32_t smB = (uint32_t)__cvta_generic_to_shared(Bs);
    const uint32_t aoff = (lane & 15)*(SAW*4) + (lane >> 4)*16;
    const uint32_t boff = ((lane & 7) + ((lane >> 3) & 1)*8)*(SBW*4)
                        + (wn0 + (lane >> 4)*8)*2;

    for (int kt = 0; kt < KT; kt++) {
        int cur = kt & 1;
        if (kt + 1 < KT) { loadA(kt+1); loadB(kt+1); }
        uint32_t Ab0 = smA + cur*(ABUF*4);
        uint32_t Bb0 = smB + cur*(BBUF*4);
#pragma unroll
        for (int ks = 0; ks < 2; ks++) {
            uint32_t af[MT][4], bf[NT][2];
#pragma unroll
            for (int i = 0; i < MT; i++)
                ldsm4(af[i], Ab0 + i*16*(SAW*4) + aoff + ks*32);
#pragma unroll
            for (int jp = 0; jp < NT/2; jp++) {
                uint32_t t[4];
                ldsm4t(t, Bb0 + ks*16*(SBW*4) + boff + jp*32);
                bf[2*jp][0] = t[0]; bf[2*jp][1] = t[1];
                bf[2*jp+1][0] = t[2]; bf[2*jp+1][1] = t[3];
            }
#pragma unroll
            for (int i = 0; i < MT; i++)
#pragma unroll
                for (int j = 0; j < NT; j++)
                    mmabf(acc[i][j], af[i], bf[j]);
        }
        if (kt + 1 < KT) { stsA((kt+1)&1); stsB((kt+1)&1); }
        __syncthreads();
    }

    if (EPI != 3) {
#pragma unroll
        for (int j = 0; j < NT; j++) {
            int coln = n0 + wn0 + j*8 + 2*tig;
            float b0 = bias[coln], b1 = bias[coln+1];
#pragma unroll
            for (int i = 0; i < MT; i++) {
                acc[i][j][0] += b0; acc[i][j][1] += b1;
                acc[i][j][2] += b0; acc[i][j][3] += b1;
            }
        }
    }

    if (EPI == 0) {
        float ps[MT][2];
#pragma unroll
        for (int i = 0; i < MT; i++) {
            ps[i][0] = 0.f; ps[i][1] = 0.f;
#pragma unroll
            for (int j = 0; j < NT; j++) {
                ps[i][0] += acc[i][j][0]*acc[i][j][0] + acc[i][j][1]*acc[i][j][1];
                ps[i][1] += acc[i][j][2]*acc[i][j][2] + acc[i][j][3]*acc[i][j][3];
            }
        }
#pragma unroll
        for (int i = 0; i < MT; i++)
#pragma unroll
            for (int h = 0; h < 2; h++) {
                ps[i][h] += __shfl_xor_sync(0xffffffffu, ps[i][h], 1);
                ps[i][h] += __shfl_xor_sync(0xffffffffu, ps[i][h], 2);
            }
        if (tig == 0) {
#pragma unroll
            for (int i = 0; i < MT; i++) {
                sRed[(i*16 + g    )*8 + wid] = ps[i][0];
                sRed[(i*16 + g + 8)*8 + wid] = ps[i][1];
            }
        }
        __syncthreads();
        if (tid < M_BLK) {
            float s = 0.f;
#pragma unroll
            for (int k = 0; k < 8; k++) s += sRed[tid*8 + k];
            sFacR[tid] = 1.f / (sqrtf(s) + 1e-8f);
        }
        __syncthreads();
#pragma unroll
        for (int i = 0; i < MT; i++) {
            float f0 = sFacR[i*16 + g], f1 = sFacR[i*16 + g + 8];
#pragma unroll
            for (int j = 0; j < NT; j++) {
                int coln = wn0 + j*8 + 2*tig;
                if (OUTBF) {
                    *(uint32_t*)&Cb[(size_t)(m0 + i*16 + g    )*N_TOT + coln] =
                        f2bf2(acc[i][j][0]*f0, acc[i][j][1]*f0);
                    *(uint32_t*)&Cb[(size_t)(m0 + i*16 + g + 8)*N_TOT + coln] =
                        f2bf2(acc[i][j][2]*f1, acc[i][j][3]*f1);
                } else {
                    *(float2*)&Cf[(size_t)(m0 + i*16 + g    )*N_TOT + coln] =
                        make_float2(acc[i][j][0]*f0, acc[i][j][1]*f0);
                    *(float2*)&Cf[(size_t)(m0 + i*16 + g + 8)*N_TOT + coln] =
                        make_float2(acc[i][j][2]*f1, acc[i][j][3]*f1);
                }
            }
        }
    } else if (EPI == 1) {
#pragma unroll
        for (int i = 0; i < MT; i++) {
            int r0 = m0 + i*16 + g, r1 = r0 + 8;
#pragma unroll
            for (int j = 0; j < NT; j++) {
                int coln = n0 + wn0 + j*8 + 2*tig;
                float v0 = tanhf(acc[i][j][0]), v1 = tanhf(acc[i][j][1]);
                float v2 = tanhf(acc[i][j][2]), v3 = tanhf(acc[i][j][3]);
                if (OUTBF) {
                    *(uint32_t*)&Cb[(size_t)r0*N_TOT + coln] = f2bf2(v0, v1);
                    *(uint32_t*)&Cb[(size_t)r1*N_TOT + coln] = f2bf2(v2, v3);
                } else {
                    *(float2*)&Cf[(size_t)r0*N_TOT + coln] = make_float2(v0, v1);
                    *(float2*)&Cf[(size_t)r1*N_TOT + coln] = make_float2(v2, v3);
                }
            }
        }
    } else if (EPI == 2) {
#pragma unroll
        for (int i = 0; i < MT; i++) {
            int r0 = m0 + i*16 + g, r1 = r0 + 8;
            int cr0 = (r0/1152)*24 + (r0%24);
            int cr1 = (r1/1152)*24 + (r1%24);
#pragma unroll
            for (int j = 0; j < NT; j++) {
                int coln = n0 + wn0 + j*8 + 2*tig;
                float m00 = fminf(fmaxf(tanhf(acc[i][j][0]) + 1.f, -1.f), 1.f);
                float m01 = fminf(fmaxf(tanhf(acc[i][j][1]) + 1.f, -1.f), 1.f);
                float m10 = fminf(fmaxf(tanhf(acc[i][j][2]) + 1.f, -1.f), 1.f);
                float m11 = fminf(fmaxf(tanhf(acc[i][j][3]) + 1.f, -1.f), 1.f);
                float2 c0 = *(const float2*)&cap[(size_t)cr0*DD + coln];
                float2 c1 = *(const float2*)&cap[(size_t)cr1*DD + coln];
                if (OUTBF) {
                    *(uint32_t*)&Cb[(size_t)r0*N_TOT + coln] = f2bf2(c0.x*m00, c0.y*m01);
                    *(uint32_t*)&Cb[(size_t)r1*N_TOT + coln] = f2bf2(c1.x*m10, c1.y*m11);
                } else {
                    *(float2*)&Cf[(size_t)r0*N_TOT + coln] = make_float2(c0.x*m00, c0.y*m01);
                    *(float2*)&Cf[(size_t)r1*N_TOT + coln] = make_float2(c1.x*m10, c1.y*m11);
                }
            }
        }
    } else {  // EPI 3
        if (n0 >= 512 && n0 < 640) {
            // smooth segment: x = tanh(acc + smb1); smooth = relu(x . smw2 + smb2 + 9)
            float pr[MT][2];
#pragma unroll
            for (int i = 0; i < MT; i++) { pr[i][0] = 0.f; pr[i][1] = 0.f; }
#pragma unroll
            for (int j = 0; j < NT; j++) {
                int cl = (n0 - 512) + wn0 + j*8 + 2*tig;
                float b0 = bias2[cl], b1 = bias2[cl+1];
                float w0 = fac[cl],  w1 = fac[cl+1];
#pragma unroll
                for (int i = 0; i < MT; i++) {
                    pr[i][0] += tanhf(acc[i][j][0] + b0)*w0 + tanhf(acc[i][j][1] + b1)*w1;
                    pr[i][1] += tanhf(acc[i][j][2] + b0)*w0 + tanhf(acc[i][j][3] + b1)*w1;
                }
            }
#pragma unroll
            for (int i = 0; i < MT; i++)
#pragma unroll
                for (int h = 0; h < 2; h++) {
                    pr[i][h] += __shfl_xor_sync(0xffffffffu, pr[i][h], 1);
                    pr[i][h] += __shfl_xor_sync(0xffffffffu, pr[i][h], 2);
                }
            if (tig == 0) {
#pragma unroll
                for (int i = 0; i < MT; i++) {
                    sRed[(i*16 + g    )*8 + wid] = pr[i][0];
                    sRed[(i*16 + g + 8)*8 + wid] = pr[i][1];
                }
            }
            __syncthreads();
            if (tid < M_BLK) {
                float s = 0.f;
#pragma unroll
                for (int k = 0; k < 8; k++) s += sRed[tid*8 + k];
                float v = s + cap[0] + 9.0f;
                Cf[m0 + tid] = v > 0.f ? v : 0.f;
            }
        } else {
            __nv_bfloat16* outp; const float* bp; int ostride, oc0;
            if (n0 < 512) { outp = Cb;  bp = bias;  ostride = 512; oc0 = n0; }
            else          { outp = Cb3; bp = bias3; ostride = 256; oc0 = n0 - 640; }
#pragma unroll
            for (int j = 0; j < NT; j++) {
                int cl = oc0 + wn0 + j*8 + 2*tig;
                float b0 = bp[cl], b1 = bp[cl+1];
#pragma unroll
                for (int i = 0; i < MT; i++) {
                    acc[i][j][0] += b0; acc[i][j][1] += b1;
                    acc[i][j][2] += b0; acc[i][j][3] += b1;
                }
            }
#pragma unroll
            for (int i = 0; i < MT; i++) {
                int r0 = m0 + i*16 + g, r1 = r0 + 8;
#pragma unroll
                for (int j = 0; j < NT; j++) {
                    int cl = oc0 + wn0 + j*8 + 2*tig;
                    *(uint32_t*)&outp[(size_t)r0*ostride + cl] =
                        f2bf2(tanhf(acc[i][j][0]), tanhf(acc[i][j][1]));
                    *(uint32_t*)&outp[(size_t)r1*ostride + cl] =
                        f2bf2(tanhf(acc[i][j][2]), tanhf(acc[i][j][3]));
                }
            }
        }
    }
}

// ---------------------------------------------------------------------------
// alv kernel v3: fully tensorized (unchanged from R9).
// ---------------------------------------------------------------------------
template<int PASS>
__global__ void __launch_bounds__(256) alv_kernel(
        const float* __restrict__ img, const float* __restrict__ cap,
        const int* __restrict__ lens)
{
    constexpr int ARS = 28;
    constexpr int IRS = 516;

    extern __shared__ float sm[];
    __nv_bfloat16* sImgBf = (__nv_bfloat16*)sm;            // 48 x 1032
    __nv_bfloat16* sQBf   = sImgBf + 48*1032;              // 32 x 1032
    float* sA   = (float*)(sQBf + 32*1032);                // RR*WW
    float* sAT  = sA + RR*WW;                              // WW*RR
    uint32_t* sAbfW = (uint32_t*)(sAT + WW*RR);            // 32*ARS
    float* sRed = (float*)(sAbfW + 32*ARS);                // 32*8
    __nv_bfloat16* sAbf = (__nv_bfloat16*)sAbfW;

    const int b = blockIdx.x;
    const int c = b / NN, n = b % NN;
    const int tid = threadIdx.x, lane = tid & 31, wid = tid >> 5;
    const int g = lane >> 2, tig = lane & 3;
    const int len = lens[c];

    {
        const float4* gi = (const float4*)(img + (size_t)n * RR * DD);
        for (int i = tid; i < RR*DD/4; i += 256) {
            float4 v = gi[i];
            int r = (i*4) >> 10, col = (i*4) & 1023;
            uint2 o; o.x = f2bf2(v.x, v.y); o.y = f2bf2(v.z, v.w);
            *(uint2*)(sImgBf + (size_t)r*1032 + col) = o;
        }
        for (int i = tid; i < 12*256; i += 256) {
            int r = 36 + i/256, col = (i%256)*4;
            *(uint2*)(sImgBf + (size_t)r*1032 + col) = make_uint2(0,0);
        }
        if (PASS == 0) {
            const float4* gq = (const float4*)(cap + (size_t)c * WW * DD);
            for (int i = tid; i < WW*DD/4; i += 256) {
                float4 v = gq[i];
                int r = (i*4) >> 10, col = (i*4) & 1023;
                uint2 o; o.x = f2bf2(v.x, v.y); o.y = f2bf2(v.z, v.w);
                *(uint2*)(sQBf + (size_t)r*1032 + col) = o;
            }
        } else {
            const uint2* gq = (const uint2*)(g_qmb + (size_t)b * WW * DD);
            for (int i = tid; i < WW*DD/4; i += 256) {
                int r = (i*4) >> 10, col = (i*4) & 1023;
                *(uint2*)(sQBf + (size_t)r*1032 + col) = gq[i];
            }
        }
        for (int i = tid; i < 8*256; i += 256) {
            int r = 24 + i/256, col = (i%256)*4;
            *(uint2*)(sQBf + (size_t)r*1032 + col) = make_uint2(0,0);
        }
        for (int i = tid; i < 32*ARS; i += 256) sAbfW[i] = 0;
    }
    __syncthreads();

    if (wid < 6) {
        int mi = wid >> 1, ni = wid & 1;
        uint32_t smI = (uint32_t)__cvta_generic_to_shared(sImgBf);
        uint32_t smQ = (uint32_t)__cvta_generic_to_shared(sQBf);
        uint32_t aBase = smI + (mi*16 + (lane & 15))*(IRS*4) + (lane >> 4)*16;
        uint32_t bBase = smQ + (ni*16 + (lane & 15))*(IRS*4) + (lane >> 4)*16;
        float acc0[4] = {0,0,0,0}, acc1[4] = {0,0,0,0};
#pragma unroll 4
        for (int kk = 0; kk < 64; kk++) {
            uint32_t a[4], t[4];
            ldsm4(a, aBase + kk*32);
            ldsm4(t, bBase + kk*32);
            uint32_t b0[2] = {t[0], t[2]};
            uint32_t b1[2] = {t[1], t[3]};
            mmabf(acc0, a, b0);
            mmabf(acc1, a, b1);
        }
        int r0 = mi*16 + g, r1 = r0 + 8;
        int w0 = ni*16 + 2*tig;
        if (r0 < RR) {
            if (w0 < WW)     sA[r0*WW + w0]     = acc0[0];
            if (w0+1 < WW)   sA[r0*WW + w0+1]   = acc0[1];
            if (w0+8 < WW)   sA[r0*WW + w0+8]   = acc1[0];
            if (w0+9 < WW)   sA[r0*WW + w0+9]   = acc1[1];
        }
        if (r1 < RR) {
            if (w0 < WW)     sA[r1*WW + w0]     = acc0[2];
            if (w0+1 < WW)   sA[r1*WW + w0+1]   = acc0[3];
            if (w0+8 < WW)   sA[r1*WW + w0+8]   = acc1[2];
            if (w0+9 < WW)   sA[r1*WW + w0+9]   = acc1[3];
        }
    }
    __syncthreads();

    if (tid < RR) {
        int r = tid;
        float vals[WW];
        float ss = 0.f;
#pragma unroll
        for (int w = 0; w < WW; w++) {
            float v = sA[r*WW + w];
            v = (v >= 0.f) ? v : 0.1f * v;
            if (w >= len) v = 0.f;
            vals[w] = v;
            ss += v * v;
        }
        float f = 1.f / (sqrtf(ss) + 1e-8f);
#pragma unroll
        for (int w = 0; w < WW; w++) sAT[w*RR + r] = vals[w] * f;
    }
    __syncthreads();

    if (tid < WW) {
        int w = tid;
        float smo = (PASS == 0) ? 9.f : g_smooth[(size_t)b*WW + w];
        float m = -1e30f;
        for (int r = 0; r < RR; r++) { float v = sAT[w*RR + r]*smo; if (v > m) m = v; }
        float s = 0.f;
        float e_[RR];
        for (int r = 0; r < RR; r++) {
            float e = expf(sAT[w*RR + r]*smo - m);
            e_[r] = e; s += e;
        }
        float inv = 1.f / s;
        for (int r = 0; r < RR; r++)
            sAbf[w*(2*ARS) + r] = __float2bfloat16(e_[r] * inv);
    }
    __syncthreads();

    {
        uint32_t smAttn = (uint32_t)__cvta_generic_to_shared(sAbf);
        uint32_t smImgB = (uint32_t)__cvta_generic_to_shared(sImgBf);
        const uint32_t aoff = (lane & 15)*(ARS*4) + (lane >> 4)*16;
        const uint32_t bRowSel = ((lane & 7) + ((lane >> 3) & 1)*8)*(IRS*4);
        const uint32_t bColSel = (lane >> 4)*8;

        float psq[2][2] = {{0.f,0.f},{0.f,0.f}};
        for (int half = 0; half < 2; half++) {
            float acc[2][8][4];
#pragma unroll
            for (int i = 0; i < 2; i++)
#pragma unroll
                for (int j = 0; j < 8; j++)
#pragma unroll
                    for (int k = 0; k < 4; k++) acc[i][j][k] = 0.f;
#pragma unroll
            for (int ks = 0; ks < 3; ks++) {
                uint32_t af0[4], af1[4];
                ldsm4(af0, smAttn + aoff + ks*32);
                ldsm4(af1, smAttn + 16*(ARS*4) + aoff + ks*32);
#pragma unroll
                for (int jp = 0; jp < 4; jp++) {
                    int ncol = half*512 + wid*64 + jp*16 + bColSel;
                    uint32_t t[4];
                    ldsm4t(t, smImgB + ks*16*(IRS*4) + bRowSel + ncol*2);
                    mmabf(acc[0][2*jp],   af0, t);
                    mmabf(acc[0][2*jp+1], af0, t+2);
                    mmabf(acc[1][2*jp],   af1, t);
                    mmabf(acc[1][2*jp+1], af1, t+2);
                }
            }
#pragma unroll
            for (int i = 0; i < 2; i++) {
                int r0 = i*16 + g, r1 = r0 + 8;
#pragma unroll
                for (int j = 0; j < 8; j++) {
                    int coln = half*512 + wid*64 + j*8 + 2*tig;
                    float v0 = acc[i][j][0], v1 = acc[i][j][1];
                    float v2 = acc[i][j][2], v3 = acc[i][j][3];
                    psq[i][0] += v0*v0 + v1*v1;
                    psq[i][1] += v2*v2 + v3*v3;
                    if (r0 < WW)
                        *(uint32_t*)&g_wc[((size_t)b*WW + r0)*DD + coln] = f2bf2(v0, v1);
                    if (r1 < WW)
                        *(uint32_t*)&g_wc[((size_t)b*WW + r1)*DD + coln] = f2bf2(v2, v3);
                }
            }
        }
#pragma unroll
        for (int i = 0; i < 2; i++)
#pragma unroll
            for (int h = 0; h < 2; h++) {
                psq[i][h] += __shfl_xor_sync(0xffffffffu, psq[i][h], 1);
                psq[i][h] += __shfl_xor_sync(0xffffffffu, psq[i][h], 2);
            }
        if (tig == 0) {
#pragma unroll
            for (int i = 0; i < 2; i++) {
                sRed[(i*16 + g    )*8 + wid] = psq[i][0];
                sRed[(i*16 + g + 8)*8 + wid] = psq[i][1];
            }
        }
        __syncthreads();
        if (tid < WW) {
            float s = 0.f;
#pragma unroll
            for (int k = 0; k < 8; k++) s += sRed[tid*8 + k];
            g_fac[(size_t)b*WW + tid] = 1.f / (sqrtf(s) + 1e-8f);
        }
    }
}

// ---------------------------------------------------------------------------
// rar: dir==0 computes hig = masked mean of sim_mid in-kernel (mean fused).
// ---------------------------------------------------------------------------
__global__ void __launch_bounds__(256) rar_kernel(
        const int* __restrict__ lens,
        const float* __restrict__ qw, const float* __restrict__ qb,
        const float* __restrict__ vw, const float* __restrict__ vb,
        const __nv_bfloat16* __restrict__ kt, int dir)
{
    extern __shared__ float sm[];
    __nv_bfloat16* sMid = (__nv_bfloat16*)sm;
    float* sHig = sm + WW*SS/2;
    float* sRed = sHig + SS;
    float* sLog = sRed + WW*8;
    float* sWgt = sLog + WW;
    float* sMisc= sWgt + WW;

    const int b = blockIdx.x;
    const int c = b / NN;
    const int tid = threadIdx.x, lane = tid & 31, wid = tid >> 5;
    const int len = lens[c];

    float*       hout= (dir == 0) ? g_higB : g_higA;

    {
        const uint4* gm = (const uint4*)(g_smid + (size_t)b*WW*SS);
        uint4* s4 = (uint4*)sMid;
        for (int i = tid; i < WW*SS/8; i += 256) s4[i] = gm[i];
    }
    __syncthreads();

    if (dir == 0) {
        // hig = masked mean over words (fused mean_kernel)
        float s = 0.f;
        for (int w = 0; w < len; w++) s += __bfloat162float(sMid[w*SS + tid]);
        sHig[tid] = s / (float)len;
    } else {
        sHig[tid] = g_higB[(size_t)b*SS + tid];
    }
    __syncthreads();

    float hv;
    {
        float acc = qb[tid];
        const float* wp = qw + tid;
#pragma unroll 4
        for (int s0 = 0; s0 < SS/4; s0++) {
            float4 h4 = *(const float4*)(sHig + s0*4);
            acc = fmaf(h4.x, wp[(size_t)(s0*4+0)*SS], acc);
            acc = fmaf(h4.y, wp[(size_t)(s0*4+1)*SS], acc);
            acc = fmaf(h4.z, wp[(size_t)(s0*4+2)*SS], acc);
            acc = fmaf(h4.w, wp[(size_t)(s0*4+3)*SS], acc);
        }
        hv = tanhf(acc) * vw[tid];
    }

    {
        const __nv_bfloat16* ktp = kt + (size_t)b*WW*SS + tid;
        float pv[WW];
#pragma unroll
        for (int w = 0; w < WW; w++)
            pv[w] = __bfloat162float(ktp[(size_t)w*SS]) * hv;
#pragma unroll
        for (int w = 0; w < WW; w++) {
            float v = warp_sum(pv[w]);
            if (lane == 0) sRed[w*8 + wid] = v;
        }
    }
    __syncthreads();
    if (tid < WW) {
        float s = 0.f;
#pragma unroll
        for (int k = 0; k < 8; k++) s += sRed[tid*8 + k];
        s += vb[0];
        if (tid >= len) s = -1e30f;
        sLog[tid] = s;
    }
    __syncthreads();
    if (tid == 0) {
        float m = -1e30f;
        for (int w = 0; w < WW; w++) m = fmaxf(m, sLog[w]);
        float s = 0.f;
        for (int w = 0; w < WW; w++) { float e = expf(sLog[w] - m); sWgt[w] = e; s += e; }
        float inv = 1.f / s;
        for (int w = 0; w < WW; w++) sWgt[w] *= inv;
    }
    __syncthreads();

    float o = 0.f;
#pragma unroll
    for (int w = 0; w < WW; w++)
        o = fmaf(sWgt[w], __bfloat162float(sMid[w*SS + tid]), o);
    float sq = warp_sum(o * o);
    if (lane == 0) sRed[wid] = sq;
    __syncthreads();
    if (tid == 0) {
        float tot = 0.f;
#pragma unroll
        for (int k = 0; k < 8; k++) tot += sRed[k];
        sMisc[0] = 1.f / (sqrtf(tot) + 1e-8f);
    }
    __syncthreads();
    hout[(size_t)b*SS + tid] = o * sMisc[0];
}

// ---------------------------------------------------------------------------
__global__ void final_kernel(const float* __restrict__ ew, const float* __restrict__ eb,
                             float* __restrict__ out)
{
    int gw = (blockIdx.x * blockDim.x + threadIdx.x) >> 5;
    int lane = threadIdx.x & 31;
    int nwarps = (gridDim.x * blockDim.x) >> 5;
    for (int b = gw; b < CC*NN; b += nwarps) {
        const float* h = g_higA + (size_t)b*SS;
        float a = 0.f;
#pragma unroll
        for (int k = 0; k < 8; k++) a = fmaf(h[lane + k*32], ew[lane + k*32], a);
        a = warp_sum(a);
        if (lane == 0) {
            float v = a + eb[0];
            int c = b / NN, n = b % NN;
            out[n*CC + c] = 1.f / (1.f + expf(-v));
        }
    }
}

// ---------------------------------------------------------------------------
extern "C" void kernel_launch(void* const* d_in, const int* in_sizes, int n_in,
                              void* d_out, int out_size)
{
    const float* img  = (const float*)d_in[0];
    const float* cap  = (const float*)d_in[1];
    const int*   lens = (const int*)  d_in[2];
    const float* alvw = (const float*)d_in[3];
    const float* alvb = (const float*)d_in[4];
    const float* qw   = (const float*)d_in[5];
    const float* qb   = (const float*)d_in[6];
    const float* kw   = (const float*)d_in[7];
    const float* kb   = (const float*)d_in[8];
    const float* vw   = (const float*)d_in[9];
    const float* vb   = (const float*)d_in[10];
    const float* smw1 = (const float*)d_in[11];
    const float* smb1 = (const float*)d_in[12];
    const float* smw2 = (const float*)d_in[13];
    const float* smb2 = (const float*)d_in[14];
    const float* mxw1 = (const float*)d_in[15];
    const float* mxb1 = (const float*)d_in[16];
    const float* mxw2 = (const float*)d_in[17];
    const float* mxb2 = (const float*)d_in[18];
    const float* ew   = (const float*)d_in[19];
    const float* eb   = (const float*)d_in[20];
    float* out = (float*)d_out;

    float *pFac, *pSmooth;
    __nv_bfloat16 *pH, *pWbf, *pWc, *pKt, *pQm, *pSmid;
    cudaGetSymbolAddress((void**)&pSmid, g_smid);
    cudaGetSymbolAddress((void**)&pQm,  g_qmb);
    cudaGetSymbolAddress((void**)&pWc,  g_wc);
    cudaGetSymbolAddress((void**)&pFac, g_fac);
    cudaGetSymbolAddress((void**)&pH,   g_h);
    cudaGetSymbolAddress((void**)&pWbf, g_wbf);
    cudaGetSymbolAddress((void**)&pKt,  g_kt);
    cudaGetSymbolAddress((void**)&pSmooth, g_smooth);

    const size_t ALV_SMEM = (size_t)(48*1032 + 32*1032) * 2
                          + (size_t)(RR*WW*2 + 32*8) * 4 + 32*28*4;
    const size_t RAR_SMEM = (size_t)(WW*SS/2 + SS + WW*8 + WW + WW + 32) * sizeof(float);
    const size_t SM_N256 = (size_t)(2*64*20 + 2*32*132)*4 + (64*8 + 64)*4;  // 46336
    const size_t SM_N128 = (size_t)(2*64*20 + 2*32*68)*4 + (64*8 + 64)*4;   // 29952

    cudaFuncSetAttribute(alv_kernel<0>, cudaFuncAttributeMaxDynamicSharedMemorySize, (int)ALV_SMEM);
    cudaFuncSetAttribute(alv_kernel<1>, cudaFuncAttributeMaxDynamicSharedMemorySize, (int)ALV_SMEM);
    cudaFuncSetAttribute(gemm_bf16<64,256,1024,256,1,0,1>, cudaFuncAttributeMaxDynamicSharedMemorySize, (int)SM_N256);
    cudaFuncSetAttribute(gemm_bf16<64,128,256,896,2,3,1>,  cudaFuncAttributeMaxDynamicSharedMemorySize, (int)SM_N128);
    cudaFuncSetAttribute(gemm_bf16<64,256,512,1024,2,2,1>, cudaFuncAttributeMaxDynamicSharedMemorySize, (int)SM_N256);
    cudaFuncSetAttribute(gemm_bf16<64,256,256,256,2,1,1>,  cudaFuncAttributeMaxDynamicSharedMemorySize, (int)SM_N256);

    const int B = CC * NN;
    const int MB64 = MTOT / 64;

    cvtw_all<<<(335872 + 255)/256, 256>>>(alvw, mxw2, kw, mxw1, smw1, pWbf);

    // ---- pass 0 ----
    alv_kernel<0><<<B, 256, ALV_SMEM>>>(img, cap, lens);
    gemm_bf16<64,256,1024,256,1,0,1><<<dim3(1,MB64), 256, SM_N256>>>(
        nullptr, pWc, pWbf + OFF_ALV0, alvb, nullptr, nullptr,
        nullptr, pSmid, nullptr, nullptr, cap, pFac);
    // fused MLP: h (tanh), smooth (fully fused), kt
    gemm_bf16<64,128,256,896,2,3,1><<<dim3(7,MB64), 256, SM_N128>>>(
        nullptr, pSmid, pWbf + OFF_WMLP, mxb1, smb1, kb,
        pSmooth, pH, nullptr, pKt, smb2, smw2);
    gemm_bf16<64,256,512,1024,2,2,1><<<dim3(4,MB64), 256, SM_N256>>>(
        nullptr, pH, pWbf + OFF_MX2, mxb2, nullptr, nullptr,
        nullptr, pQm, nullptr, nullptr, cap, nullptr);
    rar_kernel<<<B, 256, RAR_SMEM>>>(lens, qw, qb, vw, vb, pKt, 0);

    // ---- pass 1 ----
    alv_kernel<1><<<B, 256, ALV_SMEM>>>(img, cap, lens);
    gemm_bf16<64,256,1024,256,1,0,1><<<dim3(1,MB64), 256, SM_N256>>>(
        nullptr, pWc, pWbf + OFF_ALV1, alvb + SS, nullptr, nullptr,
        nullptr, pSmid, nullptr, nullptr, cap, pFac);
    gemm_bf16<64,256,256,256,2,1,1><<<dim3(1,MB64), 256, SM_N256>>>(
        nullptr, pSmid, pWbf + OFF_KW1, kb + SS, nullptr, nullptr,
        nullptr, pKt, nullptr, nullptr, nullptr, nullptr);
    rar_kernel<<<B, 256, RAR_SMEM>>>(lens, qw + SS*SS, qb + SS, vw + SS, vb + 1, pKt, 1);

    final_kernel<<<9, 256>>>(ew, eb, out);
}